// round 4
// baseline (speedup 1.0000x reference)
#include <cuda_runtime.h>
#include <cuda_bf16.h>
#include <math.h>
#include <stdint.h>

#ifndef M_PI
#define M_PI 3.14159265358979323846
#endif

// Problem constants
#define B_SZ   8
#define T_SZ   1024
#define DIMX   1024
#define DI     2048
#define NFFT   2048
#define ROWS   (B_SZ * T_SZ)   // 8192

// ----- device scratch (no runtime allocation allowed) -----
__device__ float  g_gate [(size_t)ROWS * DI];
__device__ float  g_pre  [(size_t)ROWS * DI];
__device__ float  g_hseq [(size_t)ROWS * DI];
__device__ float2 g_W  [NFFT];
__device__ float2 g_FCh[NFFT];
__device__ float2 g_FCx[NFFT];

// bf16 split operands
__device__ __nv_bfloat16 g_xhi [(size_t)ROWS * DIMX];
__device__ __nv_bfloat16 g_xlo [(size_t)ROWS * DIMX];
__device__ __nv_bfloat16 g_xphi[(size_t)ROWS * DI];
__device__ __nv_bfloat16 g_xplo[(size_t)ROWS * DI];
__device__ __nv_bfloat16 g_clhi[(size_t)ROWS * DI];
__device__ __nv_bfloat16 g_cllo[(size_t)ROWS * DI];
__device__ __nv_bfloat16 g_iwhi[(size_t)DI * DIMX];
__device__ __nv_bfloat16 g_iwlo[(size_t)DI * DIMX];
__device__ __nv_bfloat16 g_wghi[(size_t)DI * DI];
__device__ __nv_bfloat16 g_wglo[(size_t)DI * DI];
__device__ __nv_bfloat16 g_owhi[(size_t)DIMX * DI];
__device__ __nv_bfloat16 g_owlo[(size_t)DIMX * DI];

__device__ __forceinline__ float2 cmulf(float2 a, float2 b){
    return make_float2(fmaf(a.x, b.x, -a.y * b.y), fmaf(a.x, b.y, a.y * b.x));
}
__device__ __forceinline__ float2 cadd(float2 a, float2 b){ return make_float2(a.x+b.x, a.y+b.y); }
__device__ __forceinline__ float2 csub(float2 a, float2 b){ return make_float2(a.x-b.x, a.y-b.y); }

// fast tanh via MUFU.EX2 (rel err ~1e-7)
__device__ __forceinline__ float tanh_fast(float x){
    float ax = fabsf(x);
    float e  = __expf(-2.0f * ax);
    float r  = __fdividef(1.0f - e, 1.0f + e);
    return copysignf(r, x);
}

// bank swizzle for FFT smem buffers (float2 index space)
__device__ __forceinline__ int sidx(int i){ return i ^ ((i >> 4) & 15); }

// ============================================================================
// PTX helpers (plain sm_103 — NO tcgen05)
// ============================================================================
__device__ __forceinline__ uint32_t smem_u32(const void* p){
    uint32_t a;
    asm("{ .reg .u64 t; cvta.to.shared.u64 t, %1; cvt.u32.u64 %0, t; }" : "=r"(a) : "l"(p));
    return a;
}
__device__ __forceinline__ void cpasync16(uint32_t dst, const void* src){
    asm volatile("cp.async.cg.shared.global [%0], [%1], 16;" :: "r"(dst), "l"(src));
}
#define CP_COMMIT()  asm volatile("cp.async.commit_group;" ::: "memory")
#define CP_WAIT(n)   asm volatile("cp.async.wait_group %0;" :: "n"(n) : "memory")

__device__ __forceinline__ void ldsm_x4(uint32_t* r, uint32_t addr){
    asm volatile("ldmatrix.sync.aligned.m8n8.x4.shared.b16 {%0,%1,%2,%3}, [%4];"
        : "=r"(r[0]), "=r"(r[1]), "=r"(r[2]), "=r"(r[3]) : "r"(addr));
}
__device__ __forceinline__ void mma16816(float* c, const uint32_t* a,
                                         uint32_t b0, uint32_t b1){
    asm volatile("mma.sync.aligned.m16n8k16.row.col.f32.bf16.bf16.f32 "
        "{%0,%1,%2,%3}, {%4,%5,%6,%7}, {%8,%9}, {%0,%1,%2,%3};"
        : "+f"(c[0]), "+f"(c[1]), "+f"(c[2]), "+f"(c[3])
        : "r"(a[0]), "r"(a[1]), "r"(a[2]), "r"(a[3]), "r"(b0), "r"(b1));
}

#define SWZ128(o) ((o) ^ (((o) >> 3) & 0x70))

// ============================================================================
// Radix-8 DFT core (natural frequency order). DIR=0 fwd (e^-i), DIR=1 inv.
// ============================================================================
template<int DIR>
__device__ __forceinline__ void dft8(const float2* a, float2* X)
{
    const float RS = 0.70710678118654752f;
    // even DFT4 on a0,a2,a4,a6
    float2 s0 = cadd(a[0], a[4]), s1 = csub(a[0], a[4]);
    float2 s2 = cadd(a[2], a[6]), s3 = csub(a[2], a[6]);
    float2 s3i = DIR ? make_float2(-s3.y, s3.x) : make_float2(s3.y, -s3.x);
    float2 E0 = cadd(s0, s2), E2 = csub(s0, s2);
    float2 E1 = cadd(s1, s3i), E3 = csub(s1, s3i);
    // odd DFT4 on a1,a3,a5,a7
    float2 u0 = cadd(a[1], a[5]), u1 = csub(a[1], a[5]);
    float2 u2 = cadd(a[3], a[7]), u3 = csub(a[3], a[7]);
    float2 u3i = DIR ? make_float2(-u3.y, u3.x) : make_float2(u3.y, -u3.x);
    float2 O0 = cadd(u0, u2), O2 = csub(u0, u2);
    float2 O1 = cadd(u1, u3i), O3 = csub(u1, u3i);
    // w8^k * Ok
    float2 t1, t2, t3;
    if (DIR == 0){
        t1 = make_float2((O1.x + O1.y) * RS, (O1.y - O1.x) * RS);   // (1-i)/√2
        t2 = make_float2(O2.y, -O2.x);                              // -i
        t3 = make_float2((O3.y - O3.x) * RS, -(O3.x + O3.y) * RS);  // -(1+i)/√2
    } else {
        t1 = make_float2((O1.x - O1.y) * RS, (O1.x + O1.y) * RS);   // (1+i)/√2
        t2 = make_float2(-O2.y, O2.x);                              // +i
        t3 = make_float2(-(O3.x + O3.y) * RS, (O3.x - O3.y) * RS);  // (-1+i)/√2
    }
    X[0] = cadd(E0, O0);  X[4] = csub(E0, O0);
    X[1] = cadd(E1, t1);  X[5] = csub(E1, t1);
    X[2] = cadd(E2, t2);  X[6] = csub(E2, t2);
    X[3] = cadd(E3, t3);  X[7] = csub(E3, t3);
}

// ============================================================================
// 2048-point complex FFT: 3 radix-8 stages + 1 radix-4. 256 threads.
// Input bufA (caller synced), output bufA (swizzled via sidx). Trailing sync.
// W[k] = exp(-2*pi*i*k/2048) (unswizzled table).
// ============================================================================
template<int DIR>
__device__ __forceinline__ void fft2048_r8(float2* bufA, float2* bufB,
                                           const float2* __restrict__ W, int tid)
{
    float2* X = bufA;
    float2* Y = bufB;
    #pragma unroll
    for (int st = 0; st < 3; ++st){
        const int s  = (st == 0) ? 1 : (st == 1) ? 8 : 64;
        const int ps = tid & ~(s - 1);
        const int q  = tid & (s - 1);
        float2 a[8], o[8];
        #pragma unroll
        for (int r = 0; r < 8; ++r) a[r] = X[sidx(tid + 256 * r)];
        dft8<DIR>(a, o);
        const int ob = q + 8 * ps;
        Y[sidx(ob)] = o[0];
        #pragma unroll
        for (int r = 1; r < 8; ++r){
            float2 w = W[r * ps];
            if (DIR) w.y = -w.y;
            Y[sidx(ob + s * r)] = cmulf(w, o[r]);
        }
        __syncthreads();
        float2* tmp = X; X = Y; Y = tmp;
    }
    // final radix-4, s=512, no twiddles (p==0); X==bufB here, Y==bufA
    #pragma unroll
    for (int h = 0; h < 2; ++h){
        const int j = tid + 256 * h;
        float2 a = X[sidx(j)];
        float2 b = X[sidx(j + 512)];
        float2 c = X[sidx(j + 1024)];
        float2 d = X[sidx(j + 1536)];
        float2 apc = cadd(a, c), amc = csub(a, c);
        float2 bpd = cadd(b, d), bmd = csub(b, d);
        float2 ib  = make_float2(-bmd.y, bmd.x);   // i*(b-d)
        float2 x1, x3;
        if (DIR == 0){ x1 = csub(amc, ib); x3 = cadd(amc, ib); }
        else         { x1 = cadd(amc, ib); x3 = csub(amc, ib); }
        Y[sidx(j)]        = cadd(apc, bpd);
        Y[sidx(j + 512)]  = x1;
        Y[sidx(j + 1024)] = csub(apc, bpd);
        Y[sidx(j + 1536)] = x3;
    }
    __syncthreads();
}

// ============================================================================
__global__ void twiddle_kernel(float2* __restrict__ W)
{
    int k = blockIdx.x * blockDim.x + threadIdx.x;
    if (k < NFFT){
        double a = -2.0 * M_PI * (double)k / (double)NFFT;
        W[k] = make_float2((float)cos(a), (float)sin(a));
    }
}

__global__ void spectra_kernel(const float* __restrict__ ch, const float* __restrict__ cx,
                               const float2* __restrict__ Wg,
                               float2* __restrict__ FCh, float2* __restrict__ FCx)
{
    extern __shared__ float2 sm[];
    float2* bufA = sm;
    float2* bufB = sm + 2048;
    float2* Wc   = sm + 4096;
    const int tid = threadIdx.x;
    for (int k = tid; k < NFFT; k += 256){
        Wc[k] = Wg[k];
        bufA[sidx(k)] = make_float2(ch[k], cx[k]);
    }
    __syncthreads();
    fft2048_r8<0>(bufA, bufB, Wc, tid);
    const float inv = 1.0f / (float)NFFT;
    for (int k = tid; k < NFFT; k += 256){
        float2 A  = bufA[sidx(k)];
        float2 Zm = bufA[sidx((NFFT - k) & (NFFT - 1))];
        float2 Bc = make_float2(Zm.x, -Zm.y);
        float2 FH = make_float2(0.5f * (A.x + Bc.x), 0.5f * (A.y + Bc.y));
        float2 Dd = make_float2(A.x - Bc.x, A.y - Bc.y);
        float2 FX = make_float2(0.5f * Dd.y, -0.5f * Dd.x);
        FCh[k] = make_float2(FH.x * inv, FH.y * inv);
        FCx[k] = make_float2(FX.x * inv, FX.y * inv);
    }
}

// ============================================================================
// pre = circ_conv(c_x, x_proj) + b ; x_proj reconstructed from bf16 hi+lo.
// 256 threads / CTA, one row pair per CTA.
// ============================================================================
__global__ void conv_pre_kernel(const __nv_bfloat16* __restrict__ xph,
                                const __nv_bfloat16* __restrict__ xpl,
                                const float* __restrict__ bvec,
                                const float2* __restrict__ Wg, const float2* __restrict__ FCg,
                                float* __restrict__ pre)
{
    extern __shared__ float2 sm[];
    float2* bufA = sm;
    float2* bufB = sm + 2048;
    float2* Wc   = sm + 4096;
    float2* FC   = sm + 6144;
    const int tid = threadIdx.x;
    const size_t r0 = (size_t)blockIdx.x * 2;
    const __nv_bfloat16* h0p = xph + r0 * DI;
    const __nv_bfloat16* l0p = xpl + r0 * DI;
    for (int k = tid; k < NFFT; k += 256){
        Wc[k] = Wg[k];
        FC[k] = FCg[k];
        float v0 = __bfloat162float(h0p[k]) + __bfloat162float(l0p[k]);
        float v1 = __bfloat162float(h0p[DI + k]) + __bfloat162float(l0p[DI + k]);
        bufA[sidx(k)] = make_float2(v0, v1);
    }
    __syncthreads();
    fft2048_r8<0>(bufA, bufB, Wc, tid);
    for (int k = tid; k < NFFT; k += 256){
        int si = sidx(k);
        bufA[si] = cmulf(bufA[si], FC[k]);
    }
    __syncthreads();
    fft2048_r8<1>(bufA, bufB, Wc, tid);
    float* p0 = pre + r0 * DI;
    float* p1 = p0 + DI;
    for (int k = tid; k < NFFT; k += 256){
        const float bb = bvec[k];
        float2 v = bufA[sidx(k)];
        p0[k] = v.x + bb;
        p1[k] = v.y + bb;
    }
}

// ============================================================================
// Sequential scan: 4 CTAs (batch pairs packed complex), 256 threads.
// ============================================================================
__global__ void __launch_bounds__(256, 1) scan_kernel(
    const float* __restrict__ pre, float* __restrict__ hseq,
    const float2* __restrict__ Wg, const float2* __restrict__ FCg,
    const float* __restrict__ h0, float* __restrict__ hfinal)
{
    extern __shared__ float2 sm[];
    float2* bufA = sm;
    float2* bufB = sm + 2048;
    float2* Wc   = sm + 4096;
    float2* FC   = sm + 6144;
    const int tid = threadIdx.x;
    const int b0 = blockIdx.x * 2, b1 = b0 + 1;
    for (int k = tid; k < NFFT; k += 256){
        Wc[k] = Wg[k];
        FC[k] = FCg[k];
        bufA[sidx(k)] = make_float2(h0[(size_t)b0 * DI + k], h0[(size_t)b1 * DI + k]);
    }
    __syncthreads();
    const float* pre0 = pre  + (size_t)b0 * T_SZ * DI;
    const float* pre1 = pre  + (size_t)b1 * T_SZ * DI;
    float*       hs0  = hseq + (size_t)b0 * T_SZ * DI;
    float*       hs1  = hseq + (size_t)b1 * T_SZ * DI;

    for (int t = 0; t < T_SZ; ++t){
        fft2048_r8<0>(bufA, bufB, Wc, tid);
        #pragma unroll
        for (int j = 0; j < 8; ++j){
            const int si = sidx(tid + 256 * j);
            bufA[si] = cmulf(bufA[si], FC[tid + 256 * j]);
        }
        __syncthreads();

        // prefetch pre_t into registers (hidden under inverse FFT)
        const size_t off = (size_t)t * DI;
        float pr0[8], pr1[8];
        #pragma unroll
        for (int j = 0; j < 8; ++j){
            pr0[j] = pre0[off + tid + 256 * j];
            pr1[j] = pre1[off + tid + 256 * j];
        }

        fft2048_r8<1>(bufA, bufB, Wc, tid);

        #pragma unroll
        for (int j = 0; j < 8; ++j){
            const int k  = tid + 256 * j;
            const int si = sidx(k);
            float2 v = bufA[si];
            float hr = tanh_fast(v.x + pr0[j]);
            float hi = tanh_fast(v.y + pr1[j]);
            hs0[off + k] = hr;
            hs1[off + k] = hi;
            bufA[si] = make_float2(hr, hi);
        }
        __syncthreads();
    }
    if (hfinal){
        for (int k = tid; k < NFFT; k += 256){
            float2 v = bufA[sidx(k)];
            hfinal[(size_t)b0 * DI + k] = v.x;
            hfinal[(size_t)b1 * DI + k] = v.y;
        }
    }
}

// ============================================================================
// Elementwise split helpers
// ============================================================================
__global__ void split_kernel(const float* __restrict__ s,
                             __nv_bfloat16* __restrict__ hi, __nv_bfloat16* __restrict__ lo,
                             int n4)
{
    int i = blockIdx.x * blockDim.x + threadIdx.x;
    if (i >= n4) return;
    float4 v = ((const float4*)s)[i];
    __nv_bfloat16 h0 = __float2bfloat16(v.x), h1 = __float2bfloat16(v.y);
    __nv_bfloat16 h2 = __float2bfloat16(v.z), h3 = __float2bfloat16(v.w);
    __nv_bfloat16 l0 = __float2bfloat16(v.x - __bfloat162float(h0));
    __nv_bfloat16 l1 = __float2bfloat16(v.y - __bfloat162float(h1));
    __nv_bfloat16 l2 = __float2bfloat16(v.z - __bfloat162float(h2));
    __nv_bfloat16 l3 = __float2bfloat16(v.w - __bfloat162float(h3));
    ((__nv_bfloat162*)hi)[i * 2]     = __nv_bfloat162(h0, h1);
    ((__nv_bfloat162*)hi)[i * 2 + 1] = __nv_bfloat162(h2, h3);
    ((__nv_bfloat162*)lo)[i * 2]     = __nv_bfloat162(l0, l1);
    ((__nv_bfloat162*)lo)[i * 2 + 1] = __nv_bfloat162(l2, l3);
}

__global__ void cell_split_kernel(const float* __restrict__ a, const float* __restrict__ g,
                                  __nv_bfloat16* __restrict__ hi, __nv_bfloat16* __restrict__ lo,
                                  int n4)
{
    int i = blockIdx.x * blockDim.x + threadIdx.x;
    if (i >= n4) return;
    float4 va = ((const float4*)a)[i];
    float4 vg = ((const float4*)g)[i];
    float4 v = make_float4(va.x * vg.x, va.y * vg.y, va.z * vg.z, va.w * vg.w);
    __nv_bfloat16 h0 = __float2bfloat16(v.x), h1 = __float2bfloat16(v.y);
    __nv_bfloat16 h2 = __float2bfloat16(v.z), h3 = __float2bfloat16(v.w);
    __nv_bfloat16 l0 = __float2bfloat16(v.x - __bfloat162float(h0));
    __nv_bfloat16 l1 = __float2bfloat16(v.y - __bfloat162float(h1));
    __nv_bfloat16 l2 = __float2bfloat16(v.z - __bfloat162float(h2));
    __nv_bfloat16 l3 = __float2bfloat16(v.w - __bfloat162float(h3));
    ((__nv_bfloat162*)hi)[i * 2]     = __nv_bfloat162(h0, h1);
    ((__nv_bfloat162*)hi)[i * 2 + 1] = __nv_bfloat162(h2, h3);
    ((__nv_bfloat162*)lo)[i * 2]     = __nv_bfloat162(l0, l1);
    ((__nv_bfloat162*)lo)[i * 2 + 1] = __nv_bfloat162(l2, l3);
}

// ============================================================================
// mma.sync bf16 split GEMM: C[M,N] = A[M,K] * B[N,K]^T  (fp32 via 3-term split)
// CTA 128x128, K-chunk 64, cp.async double buffer, 8 warps (2x4), warp 64x32.
// EPI: 0 = fp32 store, 1 = silu(x+bias) fp32, 2 = bf16 hi/lo split store
// ============================================================================
#define KCH 64
#define STAGE_BYTES 65536   // 4 tiles x 16KB (Ahi, Alo, Bhi, Blo)

template<int EPI>
__global__ void __launch_bounds__(256, 1) gemm_mma(
    const __nv_bfloat16* __restrict__ Ahi, const __nv_bfloat16* __restrict__ Alo,
    const __nv_bfloat16* __restrict__ Bhi, const __nv_bfloat16* __restrict__ Blo,
    const float* __restrict__ bias,
    float* __restrict__ Cf,
    __nv_bfloat16* __restrict__ Chi, __nv_bfloat16* __restrict__ Clo,
    int K, int N)
{
    extern __shared__ char dsm[];
    const int tid  = threadIdx.x;
    const int wid  = tid >> 5;
    const int lane = tid & 31;
    const int wm = wid & 1;      // 0..1  (M)
    const int wn = wid >> 1;     // 0..3  (N)
    const int bm = blockIdx.y * 128;
    const int bn = blockIdx.x * 128;

    const uint32_t sbase = (smem_u32(dsm) + 1023u) & ~1023u;

    float acc[4][4][4];
    #pragma unroll
    for (int i = 0; i < 4; ++i)
        #pragma unroll
        for (int j = 0; j < 4; ++j)
            #pragma unroll
            for (int e = 0; e < 4; ++e) acc[i][j][e] = 0.0f;

    // ---- stage loader: 4 tiles of [128 rows][64 bf16] = 16KB each ----
    const int lrow = tid >> 3;       // 0..31
    const int lc   = tid & 7;        // 16B chunk 0..7
    auto load_stage = [&](int s, int k0){
        const uint32_t tA_hi = sbase + s * STAGE_BYTES;
        const uint32_t tA_lo = tA_hi + 16384;
        const uint32_t tB_hi = tA_hi + 32768;
        const uint32_t tB_lo = tA_hi + 49152;
        #pragma unroll
        for (int p = 0; p < 4; ++p){
            const int row = lrow + p * 32;
            const uint32_t sw = SWZ128((uint32_t)(row * 128 + lc * 16));
            const size_t ga = (size_t)(bm + row) * K + k0 + lc * 8;
            const size_t gb = (size_t)(bn + row) * K + k0 + lc * 8;
            cpasync16(tA_hi + sw, Ahi + ga);
            cpasync16(tA_lo + sw, Alo + ga);
            cpasync16(tB_hi + sw, Bhi + gb);
            cpasync16(tB_lo + sw, Blo + gb);
        }
        CP_COMMIT();
    };

    const int NIT = K / KCH;
    load_stage(0, 0);

    const int lr8  = (lane & 7) + ((lane & 8) ? 8 : 0);
    const int lk16 = (lane & 16) ? 16 : 0;

    for (int it = 0; it < NIT; ++it){
        if (it + 1 < NIT){
            load_stage((it + 1) & 1, (it + 1) * KCH);
            CP_WAIT(1);
        } else {
            CP_WAIT(0);
        }
        __syncthreads();

        const uint32_t st   = sbase + (it & 1) * STAGE_BYTES;
        const uint32_t sAhi = st;
        const uint32_t sAlo = st + 16384;
        const uint32_t sBhi = st + 32768;
        const uint32_t sBlo = st + 49152;

        #pragma unroll
        for (int ks = 0; ks < 4; ++ks){
            uint32_t ah[4][4], al[4][4], bh[2][4], bl[2][4];
            #pragma unroll
            for (int i = 0; i < 4; ++i){
                const int r = wm * 64 + i * 16 + lr8;
                const uint32_t off = SWZ128((uint32_t)(r * 128 + ks * 32 + lk16));
                ldsm_x4(ah[i], sAhi + off);
                ldsm_x4(al[i], sAlo + off);
            }
            #pragma unroll
            for (int np = 0; np < 2; ++np){
                const int r = wn * 32 + np * 16 + lr8;
                const uint32_t off = SWZ128((uint32_t)(r * 128 + ks * 32 + lk16));
                ldsm_x4(bh[np], sBhi + off);
                ldsm_x4(bl[np], sBlo + off);
            }
            #pragma unroll
            for (int i = 0; i < 4; ++i){
                #pragma unroll
                for (int j = 0; j < 4; ++j){
                    const int np = j >> 1, sl = j & 1;
                    mma16816(acc[i][j], ah[i], bh[np][sl], bh[np][sl + 2]);
                    mma16816(acc[i][j], al[i], bh[np][sl], bh[np][sl + 2]);
                    mma16816(acc[i][j], ah[i], bl[np][sl], bl[np][sl + 2]);
                }
            }
        }
        __syncthreads();
    }

    // ---- epilogue ----
    const int qr = lane >> 2;
    const int qc = (lane & 3) * 2;
    #pragma unroll
    for (int i = 0; i < 4; ++i){
        #pragma unroll
        for (int j = 0; j < 4; ++j){
            const int col = bn + wn * 32 + j * 8 + qc;
            #pragma unroll
            for (int h = 0; h < 2; ++h){
                const int row = bm + wm * 64 + i * 16 + qr + h * 8;
                float v0 = acc[i][j][h * 2];
                float v1 = acc[i][j][h * 2 + 1];
                if (EPI == 1){
                    v0 += bias[col];
                    v1 += bias[col + 1];
                    v0 = v0 / (1.0f + expf(-v0));
                    v1 = v1 / (1.0f + expf(-v1));
                    *(float2*)(Cf + (size_t)row * N + col) = make_float2(v0, v1);
                } else if (EPI == 2){
                    __nv_bfloat16 h0 = __float2bfloat16(v0);
                    __nv_bfloat16 h1 = __float2bfloat16(v1);
                    __nv_bfloat16 l0 = __float2bfloat16(v0 - __bfloat162float(h0));
                    __nv_bfloat16 l1 = __float2bfloat16(v1 - __bfloat162float(h1));
                    *(__nv_bfloat162*)(Chi + (size_t)row * N + col) = __nv_bfloat162(h0, h1);
                    *(__nv_bfloat162*)(Clo + (size_t)row * N + col) = __nv_bfloat162(l0, l1);
                } else {
                    *(float2*)(Cf + (size_t)row * N + col) = make_float2(v0, v1);
                }
            }
        }
    }
}

// ============================================================================
// Launch
// ============================================================================
extern "C" void kernel_launch(void* const* d_in, const int* in_sizes, int n_in,
                              void* d_out, int out_size)
{
    (void)in_sizes; (void)n_in;
    const float* x    = (const float*)d_in[0];
    const float* h0   = (const float*)d_in[1];
    const float* inw  = (const float*)d_in[2];
    const float* outw = (const float*)d_in[3];
    const float* ch   = (const float*)d_in[4];
    const float* cx   = (const float*)d_in[5];
    const float* bv   = (const float*)d_in[6];
    const float* wg   = (const float*)d_in[7];
    const float* bg   = (const float*)d_in[8];

    float* out = (float*)d_out;
    float* hfinal = (out_size >= (int)(ROWS * DIMX + B_SZ * DI))
                        ? out + (size_t)ROWS * DIMX : nullptr;

    float *p_gate, *p_pre, *p_hseq;
    float2 *p_W, *p_FCh, *p_FCx;
    __nv_bfloat16 *p_xhi, *p_xlo, *p_xphi, *p_xplo, *p_clhi, *p_cllo;
    __nv_bfloat16 *p_iwhi, *p_iwlo, *p_wghi, *p_wglo, *p_owhi, *p_owlo;
    cudaGetSymbolAddress((void**)&p_gate,  g_gate);
    cudaGetSymbolAddress((void**)&p_pre,   g_pre);
    cudaGetSymbolAddress((void**)&p_hseq,  g_hseq);
    cudaGetSymbolAddress((void**)&p_W,     g_W);
    cudaGetSymbolAddress((void**)&p_FCh,   g_FCh);
    cudaGetSymbolAddress((void**)&p_FCx,   g_FCx);
    cudaGetSymbolAddress((void**)&p_xhi,   g_xhi);
    cudaGetSymbolAddress((void**)&p_xlo,   g_xlo);
    cudaGetSymbolAddress((void**)&p_xphi,  g_xphi);
    cudaGetSymbolAddress((void**)&p_xplo,  g_xplo);
    cudaGetSymbolAddress((void**)&p_clhi,  g_clhi);
    cudaGetSymbolAddress((void**)&p_cllo,  g_cllo);
    cudaGetSymbolAddress((void**)&p_iwhi,  g_iwhi);
    cudaGetSymbolAddress((void**)&p_iwlo,  g_iwlo);
    cudaGetSymbolAddress((void**)&p_wghi,  g_wghi);
    cudaGetSymbolAddress((void**)&p_wglo,  g_wglo);
    cudaGetSymbolAddress((void**)&p_owhi,  g_owhi);
    cudaGetSymbolAddress((void**)&p_owlo,  g_owlo);

    cudaFuncSetAttribute(conv_pre_kernel, cudaFuncAttributeMaxDynamicSharedMemorySize, 65536);
    cudaFuncSetAttribute(scan_kernel,     cudaFuncAttributeMaxDynamicSharedMemorySize, 65536);
    cudaFuncSetAttribute(spectra_kernel,  cudaFuncAttributeMaxDynamicSharedMemorySize, 49152);
    const int GSM = 2 * STAGE_BYTES + 1024;
    cudaFuncSetAttribute(gemm_mma<0>, cudaFuncAttributeMaxDynamicSharedMemorySize, GSM);
    cudaFuncSetAttribute(gemm_mma<1>, cudaFuncAttributeMaxDynamicSharedMemorySize, GSM);
    cudaFuncSetAttribute(gemm_mma<2>, cudaFuncAttributeMaxDynamicSharedMemorySize, GSM);

    // setup
    twiddle_kernel<<<4, 512>>>(p_W);
    spectra_kernel<<<1, 256, 49152>>>(ch, cx, p_W, p_FCh, p_FCx);

    // split inputs / weights to bf16 hi/lo
    split_kernel<<<(ROWS * DIMX / 4 + 255) / 256, 256>>>(x,    p_xhi,  p_xlo,  ROWS * DIMX / 4);
    split_kernel<<<(DI * DIMX   / 4 + 255) / 256, 256>>>(inw,  p_iwhi, p_iwlo, DI * DIMX / 4);
    split_kernel<<<(DI * DI     / 4 + 255) / 256, 256>>>(wg,   p_wghi, p_wglo, DI * DI / 4);
    split_kernel<<<(DIMX * DI   / 4 + 255) / 256, 256>>>(outw, p_owhi, p_owlo, DIMX * DI / 4);

    // GEMM1: x_proj = x @ in_proj_w^T  -> bf16 split  [8192,2048]
    gemm_mma<2><<<dim3(DI / 128, ROWS / 128), 256, GSM>>>(
        p_xhi, p_xlo, p_iwhi, p_iwlo, nullptr, nullptr, p_xphi, p_xplo, DIMX, DI);

    // pre = circ_conv(c_x, x_proj) + b
    conv_pre_kernel<<<ROWS / 2, 256, 65536>>>(p_xphi, p_xplo, bv, p_W, p_FCx, p_pre);

    // GEMM2: gate = silu(x_proj @ W_gate^T + b_gate)
    gemm_mma<1><<<dim3(DI / 128, ROWS / 128), 256, GSM>>>(
        p_xphi, p_xplo, p_wghi, p_wglo, bg, p_gate, nullptr, nullptr, DI, DI);

    // sequential scan
    scan_kernel<<<4, 256, 65536>>>(p_pre, p_hseq, p_W, p_FCh, h0, hfinal);

    // cell = hseq * gate -> bf16 split
    cell_split_kernel<<<(ROWS * DI / 4 + 255) / 256, 256>>>(
        p_hseq, p_gate, p_clhi, p_cllo, ROWS * DI / 4);

    // GEMM3: output = cell @ out_proj_w^T
    gemm_mma<0><<<dim3(DIMX / 128, ROWS / 128), 256, GSM>>>(
        p_clhi, p_cllo, p_owhi, p_owlo, nullptr, out, nullptr, nullptr, DI, DIMX);
}

// round 5
// speedup vs baseline: 1.0462x; 1.0462x over previous
#include <cuda_runtime.h>
#include <cuda_bf16.h>
#include <math.h>
#include <stdint.h>

#ifndef M_PI
#define M_PI 3.14159265358979323846
#endif

// Problem constants
#define B_SZ   8
#define T_SZ   1024
#define DIMX   1024
#define DI     2048
#define NFFT   2048
#define ROWS   (B_SZ * T_SZ)   // 8192

// ----- device scratch (no runtime allocation allowed) -----
__device__ float  g_gate [(size_t)ROWS * DI];
__device__ float  g_pre  [(size_t)ROWS * DI];
__device__ float  g_hseq [(size_t)ROWS * DI];
__device__ float2 g_W  [NFFT];
__device__ float2 g_FCh[NFFT];
__device__ float2 g_FCx[NFFT];

// bf16 split operands
__device__ __nv_bfloat16 g_xhi [(size_t)ROWS * DIMX];
__device__ __nv_bfloat16 g_xlo [(size_t)ROWS * DIMX];
__device__ __nv_bfloat16 g_xphi[(size_t)ROWS * DI];
__device__ __nv_bfloat16 g_xplo[(size_t)ROWS * DI];
__device__ __nv_bfloat16 g_clhi[(size_t)ROWS * DI];
__device__ __nv_bfloat16 g_cllo[(size_t)ROWS * DI];
__device__ __nv_bfloat16 g_iwhi[(size_t)DI * DIMX];
__device__ __nv_bfloat16 g_iwlo[(size_t)DI * DIMX];
__device__ __nv_bfloat16 g_wghi[(size_t)DI * DI];
__device__ __nv_bfloat16 g_wglo[(size_t)DI * DI];
__device__ __nv_bfloat16 g_owhi[(size_t)DIMX * DI];
__device__ __nv_bfloat16 g_owlo[(size_t)DIMX * DI];

__device__ __forceinline__ float2 cmulf(float2 a, float2 b){
    return make_float2(fmaf(a.x, b.x, -a.y * b.y), fmaf(a.x, b.y, a.y * b.x));
}
__device__ __forceinline__ float2 cadd(float2 a, float2 b){ return make_float2(a.x+b.x, a.y+b.y); }
__device__ __forceinline__ float2 csub(float2 a, float2 b){ return make_float2(a.x-b.x, a.y-b.y); }

// fast tanh via MUFU.EX2 (rel err ~1e-7)
__device__ __forceinline__ float tanh_fast(float x){
    float ax = fabsf(x);
    float e  = __expf(-2.0f * ax);
    float r  = __fdividef(1.0f - e, 1.0f + e);
    return copysignf(r, x);
}

// bank swizzle for FFT smem buffers (float2 index space)
__device__ __forceinline__ int sidx(int i){ return i ^ ((i >> 4) & 15); }

// ============================================================================
// PTX helpers (plain sm_103 — NO tcgen05)
// ============================================================================
__device__ __forceinline__ uint32_t smem_u32(const void* p){
    uint32_t a;
    asm("{ .reg .u64 t; cvta.to.shared.u64 t, %1; cvt.u32.u64 %0, t; }" : "=r"(a) : "l"(p));
    return a;
}
__device__ __forceinline__ void cpasync16(uint32_t dst, const void* src){
    asm volatile("cp.async.cg.shared.global [%0], [%1], 16;" :: "r"(dst), "l"(src));
}
#define CP_COMMIT()  asm volatile("cp.async.commit_group;" ::: "memory")
#define CP_WAIT(n)   asm volatile("cp.async.wait_group %0;" :: "n"(n) : "memory")

__device__ __forceinline__ void ldsm_x4(uint32_t* r, uint32_t addr){
    asm volatile("ldmatrix.sync.aligned.m8n8.x4.shared.b16 {%0,%1,%2,%3}, [%4];"
        : "=r"(r[0]), "=r"(r[1]), "=r"(r[2]), "=r"(r[3]) : "r"(addr));
}
__device__ __forceinline__ void mma16816(float* c, const uint32_t* a,
                                         uint32_t b0, uint32_t b1){
    asm volatile("mma.sync.aligned.m16n8k16.row.col.f32.bf16.bf16.f32 "
        "{%0,%1,%2,%3}, {%4,%5,%6,%7}, {%8,%9}, {%0,%1,%2,%3};"
        : "+f"(c[0]), "+f"(c[1]), "+f"(c[2]), "+f"(c[3])
        : "r"(a[0]), "r"(a[1]), "r"(a[2]), "r"(a[3]), "r"(b0), "r"(b1));
}

#define SWZ128(o) ((o) ^ (((o) >> 3) & 0x70))

// ============================================================================
// Radix-8 DFT core (natural frequency order). DIR=0 fwd (e^-i), DIR=1 inv.
// ============================================================================
template<int DIR>
__device__ __forceinline__ void dft8(const float2* a, float2* X)
{
    const float RS = 0.70710678118654752f;
    float2 s0 = cadd(a[0], a[4]), s1 = csub(a[0], a[4]);
    float2 s2 = cadd(a[2], a[6]), s3 = csub(a[2], a[6]);
    float2 s3i = DIR ? make_float2(-s3.y, s3.x) : make_float2(s3.y, -s3.x);
    float2 E0 = cadd(s0, s2), E2 = csub(s0, s2);
    float2 E1 = cadd(s1, s3i), E3 = csub(s1, s3i);
    float2 u0 = cadd(a[1], a[5]), u1 = csub(a[1], a[5]);
    float2 u2 = cadd(a[3], a[7]), u3 = csub(a[3], a[7]);
    float2 u3i = DIR ? make_float2(-u3.y, u3.x) : make_float2(u3.y, -u3.x);
    float2 O0 = cadd(u0, u2), O2 = csub(u0, u2);
    float2 O1 = cadd(u1, u3i), O3 = csub(u1, u3i);
    float2 t1, t2, t3;
    if (DIR == 0){
        t1 = make_float2((O1.x + O1.y) * RS, (O1.y - O1.x) * RS);
        t2 = make_float2(O2.y, -O2.x);
        t3 = make_float2((O3.y - O3.x) * RS, -(O3.x + O3.y) * RS);
    } else {
        t1 = make_float2((O1.x - O1.y) * RS, (O1.x + O1.y) * RS);
        t2 = make_float2(-O2.y, O2.x);
        t3 = make_float2(-(O3.x + O3.y) * RS, (O3.x - O3.y) * RS);
    }
    X[0] = cadd(E0, O0);  X[4] = csub(E0, O0);
    X[1] = cadd(E1, t1);  X[5] = csub(E1, t1);
    X[2] = cadd(E2, t2);  X[6] = csub(E2, t2);
    X[3] = cadd(E3, t3);  X[7] = csub(E3, t3);
}

// Generic radix-8 stage with register twiddles. ob/stride precomputed.
template<int DIR>
__device__ __forceinline__ void stage_r8(const float2* X, float2* Y,
                                         const float2* tw, int ob, int stride, int tid)
{
    float2 a[8], o[8];
    #pragma unroll
    for (int r = 0; r < 8; ++r) a[r] = X[sidx(tid + 256 * r)];
    dft8<DIR>(a, o);
    Y[sidx(ob)] = o[0];
    #pragma unroll
    for (int r = 1; r < 8; ++r){
        float2 w = tw[r - 1];
        if (DIR) w.y = -w.y;
        Y[sidx(ob + stride * r)] = cmulf(w, o[r]);
    }
    __syncthreads();
}

// ============================================================================
// 2048-point complex FFT (generic, smem twiddle table) for setup/conv kernels.
// ============================================================================
template<int DIR>
__device__ __forceinline__ void fft2048_r8(float2* bufA, float2* bufB,
                                           const float2* __restrict__ W, int tid)
{
    float2* X = bufA;
    float2* Y = bufB;
    #pragma unroll
    for (int st = 0; st < 3; ++st){
        const int s  = (st == 0) ? 1 : (st == 1) ? 8 : 64;
        const int ps = tid & ~(s - 1);
        const int q  = tid & (s - 1);
        float2 a[8], o[8];
        #pragma unroll
        for (int r = 0; r < 8; ++r) a[r] = X[sidx(tid + 256 * r)];
        dft8<DIR>(a, o);
        const int ob = q + 8 * ps;
        Y[sidx(ob)] = o[0];
        #pragma unroll
        for (int r = 1; r < 8; ++r){
            float2 w = W[r * ps];
            if (DIR) w.y = -w.y;
            Y[sidx(ob + s * r)] = cmulf(w, o[r]);
        }
        __syncthreads();
        float2* tmp = X; X = Y; Y = tmp;
    }
    #pragma unroll
    for (int h = 0; h < 2; ++h){
        const int j = tid + 256 * h;
        float2 a = X[sidx(j)];
        float2 b = X[sidx(j + 512)];
        float2 c = X[sidx(j + 1024)];
        float2 d = X[sidx(j + 1536)];
        float2 apc = cadd(a, c), amc = csub(a, c);
        float2 bpd = cadd(b, d), bmd = csub(b, d);
        float2 ib  = make_float2(-bmd.y, bmd.x);
        float2 x1, x3;
        if (DIR == 0){ x1 = csub(amc, ib); x3 = cadd(amc, ib); }
        else         { x1 = cadd(amc, ib); x3 = csub(amc, ib); }
        Y[sidx(j)]        = cadd(apc, bpd);
        Y[sidx(j + 512)]  = x1;
        Y[sidx(j + 1024)] = csub(apc, bpd);
        Y[sidx(j + 1536)] = x3;
    }
    __syncthreads();
}

// ============================================================================
__global__ void twiddle_kernel(float2* __restrict__ W)
{
    int k = blockIdx.x * blockDim.x + threadIdx.x;
    if (k < NFFT){
        double a = -2.0 * M_PI * (double)k / (double)NFFT;
        W[k] = make_float2((float)cos(a), (float)sin(a));
    }
}

__global__ void spectra_kernel(const float* __restrict__ ch, const float* __restrict__ cx,
                               const float2* __restrict__ Wg,
                               float2* __restrict__ FCh, float2* __restrict__ FCx)
{
    extern __shared__ float2 sm[];
    float2* bufA = sm;
    float2* bufB = sm + 2048;
    float2* Wc   = sm + 4096;
    const int tid = threadIdx.x;
    for (int k = tid; k < NFFT; k += 256){
        Wc[k] = Wg[k];
        bufA[sidx(k)] = make_float2(ch[k], cx[k]);
    }
    __syncthreads();
    fft2048_r8<0>(bufA, bufB, Wc, tid);
    const float inv = 1.0f / (float)NFFT;
    for (int k = tid; k < NFFT; k += 256){
        float2 A  = bufA[sidx(k)];
        float2 Zm = bufA[sidx((NFFT - k) & (NFFT - 1))];
        float2 Bc = make_float2(Zm.x, -Zm.y);
        float2 FH = make_float2(0.5f * (A.x + Bc.x), 0.5f * (A.y + Bc.y));
        float2 Dd = make_float2(A.x - Bc.x, A.y - Bc.y);
        float2 FX = make_float2(0.5f * Dd.y, -0.5f * Dd.x);
        FCh[k] = make_float2(FH.x * inv, FH.y * inv);
        FCx[k] = make_float2(FX.x * inv, FX.y * inv);
    }
}

// ============================================================================
// pre = circ_conv(c_x, x_proj) + b ; x_proj reconstructed from bf16 hi+lo.
// ============================================================================
__global__ void conv_pre_kernel(const __nv_bfloat16* __restrict__ xph,
                                const __nv_bfloat16* __restrict__ xpl,
                                const float* __restrict__ bvec,
                                const float2* __restrict__ Wg, const float2* __restrict__ FCg,
                                float* __restrict__ pre)
{
    extern __shared__ float2 sm[];
    float2* bufA = sm;
    float2* bufB = sm + 2048;
    float2* Wc   = sm + 4096;
    float2* FC   = sm + 6144;
    const int tid = threadIdx.x;
    const size_t r0 = (size_t)blockIdx.x * 2;
    const __nv_bfloat16* h0p = xph + r0 * DI;
    const __nv_bfloat16* l0p = xpl + r0 * DI;
    for (int k = tid; k < NFFT; k += 256){
        Wc[k] = Wg[k];
        FC[k] = FCg[k];
        float v0 = __bfloat162float(h0p[k]) + __bfloat162float(l0p[k]);
        float v1 = __bfloat162float(h0p[DI + k]) + __bfloat162float(l0p[DI + k]);
        bufA[sidx(k)] = make_float2(v0, v1);
    }
    __syncthreads();
    fft2048_r8<0>(bufA, bufB, Wc, tid);
    for (int k = tid; k < NFFT; k += 256){
        int si = sidx(k);
        bufA[si] = cmulf(bufA[si], FC[k]);
    }
    __syncthreads();
    fft2048_r8<1>(bufA, bufB, Wc, tid);
    float* p0 = pre + r0 * DI;
    float* p1 = p0 + DI;
    for (int k = tid; k < NFFT; k += 256){
        const float bb = bvec[k];
        float2 v = bufA[sidx(k)];
        p0[k] = v.x + bb;
        p1[k] = v.y + bb;
    }
}

// ============================================================================
// Sequential scan: 4 CTAs (batch pairs packed complex), 256 threads.
// Fused: FC multiply into inverse stage-0 reads; tanh/pre/store into inverse
// final radix-4. Twiddles register-cached (21 float2/thread, fixed per tid).
// smem: bufA + bufB + FC = 48KB.
// ============================================================================
__global__ void __launch_bounds__(256, 1) scan_kernel(
    const float* __restrict__ pre, float* __restrict__ hseq,
    const float2* __restrict__ Wg, const float2* __restrict__ FCg,
    const float* __restrict__ h0, float* __restrict__ hfinal)
{
    extern __shared__ float2 sm[];
    float2* bufA = sm;
    float2* bufB = sm + 2048;
    float2* FC   = sm + 4096;
    const int tid = threadIdx.x;
    const int b0 = blockIdx.x * 2, b1 = b0 + 1;

    // register twiddles (fixed per thread for all steps)
    float2 tw0[7], tw1[7], tw2[7];
    {
        const int ps0 = tid, ps1 = tid & ~7, ps2 = tid & ~63;
        #pragma unroll
        for (int r = 0; r < 7; ++r){
            tw0[r] = Wg[(r + 1) * ps0];
            tw1[r] = Wg[(r + 1) * ps1];
            tw2[r] = Wg[(r + 1) * ps2];
        }
    }
    const int ob1 = (tid & 7)  + 8 * (tid & ~7);
    const int ob2 = (tid & 63) + 8 * (tid & ~63);

    for (int k = tid; k < NFFT; k += 256){
        FC[k] = FCg[k];
        bufA[sidx(k)] = make_float2(h0[(size_t)b0 * DI + k], h0[(size_t)b1 * DI + k]);
    }
    __syncthreads();

    const float* pre0 = pre  + (size_t)b0 * T_SZ * DI;
    const float* pre1 = pre  + (size_t)b1 * T_SZ * DI;
    float*       hs0  = hseq + (size_t)b0 * T_SZ * DI;
    float*       hs1  = hseq + (size_t)b1 * T_SZ * DI;

    for (int t = 0; t < T_SZ; ++t){
        const size_t off = (size_t)t * DI;
        // prefetch pre_t (consumed at the very end of the step)
        float pr0[8], pr1[8];
        #pragma unroll
        for (int j = 0; j < 8; ++j){
            pr0[j] = pre0[off + tid + 256 * j];
            pr1[j] = pre1[off + tid + 256 * j];
        }

        // ---- forward FFT ----
        stage_r8<0>(bufA, bufB, tw0, 8 * tid, 1, tid);
        stage_r8<0>(bufB, bufA, tw1, ob1, 8, tid);
        stage_r8<0>(bufA, bufB, tw2, ob2, 64, tid);
        #pragma unroll
        for (int h = 0; h < 2; ++h){
            const int j = tid + 256 * h;
            float2 a = bufB[sidx(j)];
            float2 b = bufB[sidx(j + 512)];
            float2 c = bufB[sidx(j + 1024)];
            float2 d = bufB[sidx(j + 1536)];
            float2 apc = cadd(a, c), amc = csub(a, c);
            float2 bpd = cadd(b, d), bmd = csub(b, d);
            float2 ib  = make_float2(-bmd.y, bmd.x);
            bufA[sidx(j)]        = cadd(apc, bpd);
            bufA[sidx(j + 512)]  = csub(amc, ib);
            bufA[sidx(j + 1024)] = csub(apc, bpd);
            bufA[sidx(j + 1536)] = cadd(amc, ib);
        }
        __syncthreads();

        // ---- inverse FFT, stage 0 with FC multiply fused ----
        {
            float2 a[8], o[8];
            #pragma unroll
            for (int r = 0; r < 8; ++r)
                a[r] = cmulf(bufA[sidx(tid + 256 * r)], FC[tid + 256 * r]);
            dft8<1>(a, o);
            const int ob = 8 * tid;
            bufB[sidx(ob)] = o[0];
            #pragma unroll
            for (int r = 1; r < 8; ++r){
                float2 w = tw0[r - 1]; w.y = -w.y;
                bufB[sidx(ob + r)] = cmulf(w, o[r]);
            }
            __syncthreads();
        }
        stage_r8<1>(bufB, bufA, tw1, ob1, 8, tid);
        stage_r8<1>(bufA, bufB, tw2, ob2, 64, tid);

        // ---- inverse final radix-4 fused with tanh + pre + stores ----
        #pragma unroll
        for (int h = 0; h < 2; ++h){
            const int j = tid + 256 * h;
            float2 a = bufB[sidx(j)];
            float2 b = bufB[sidx(j + 512)];
            float2 c = bufB[sidx(j + 1024)];
            float2 d = bufB[sidx(j + 1536)];
            float2 apc = cadd(a, c), amc = csub(a, c);
            float2 bpd = cadd(b, d), bmd = csub(b, d);
            float2 ib  = make_float2(-bmd.y, bmd.x);
            float2 os[4];
            os[0] = cadd(apc, bpd);
            os[1] = cadd(amc, ib);
            os[2] = csub(apc, bpd);
            os[3] = csub(amc, ib);
            #pragma unroll
            for (int r = 0; r < 4; ++r){
                const int k  = j + 512 * r;
                const int pj = h + 2 * r;
                float hr = tanh_fast(os[r].x + pr0[pj]);
                float hi = tanh_fast(os[r].y + pr1[pj]);
                hs0[off + k] = hr;
                hs1[off + k] = hi;
                bufA[sidx(k)] = make_float2(hr, hi);
            }
        }
        __syncthreads();
    }
    if (hfinal){
        for (int k = tid; k < NFFT; k += 256){
            float2 v = bufA[sidx(k)];
            hfinal[(size_t)b0 * DI + k] = v.x;
            hfinal[(size_t)b1 * DI + k] = v.y;
        }
    }
}

// ============================================================================
// Elementwise split helpers
// ============================================================================
__global__ void split_kernel(const float* __restrict__ s,
                             __nv_bfloat16* __restrict__ hi, __nv_bfloat16* __restrict__ lo,
                             int n4)
{
    int i = blockIdx.x * blockDim.x + threadIdx.x;
    if (i >= n4) return;
    float4 v = ((const float4*)s)[i];
    __nv_bfloat16 h0 = __float2bfloat16(v.x), h1 = __float2bfloat16(v.y);
    __nv_bfloat16 h2 = __float2bfloat16(v.z), h3 = __float2bfloat16(v.w);
    __nv_bfloat16 l0 = __float2bfloat16(v.x - __bfloat162float(h0));
    __nv_bfloat16 l1 = __float2bfloat16(v.y - __bfloat162float(h1));
    __nv_bfloat16 l2 = __float2bfloat16(v.z - __bfloat162float(h2));
    __nv_bfloat16 l3 = __float2bfloat16(v.w - __bfloat162float(h3));
    ((__nv_bfloat162*)hi)[i * 2]     = __nv_bfloat162(h0, h1);
    ((__nv_bfloat162*)hi)[i * 2 + 1] = __nv_bfloat162(h2, h3);
    ((__nv_bfloat162*)lo)[i * 2]     = __nv_bfloat162(l0, l1);
    ((__nv_bfloat162*)lo)[i * 2 + 1] = __nv_bfloat162(l2, l3);
}

__global__ void cell_split_kernel(const float* __restrict__ a, const float* __restrict__ g,
                                  __nv_bfloat16* __restrict__ hi, __nv_bfloat16* __restrict__ lo,
                                  int n4)
{
    int i = blockIdx.x * blockDim.x + threadIdx.x;
    if (i >= n4) return;
    float4 va = ((const float4*)a)[i];
    float4 vg = ((const float4*)g)[i];
    float4 v = make_float4(va.x * vg.x, va.y * vg.y, va.z * vg.z, va.w * vg.w);
    __nv_bfloat16 h0 = __float2bfloat16(v.x), h1 = __float2bfloat16(v.y);
    __nv_bfloat16 h2 = __float2bfloat16(v.z), h3 = __float2bfloat16(v.w);
    __nv_bfloat16 l0 = __float2bfloat16(v.x - __bfloat162float(h0));
    __nv_bfloat16 l1 = __float2bfloat16(v.y - __bfloat162float(h1));
    __nv_bfloat16 l2 = __float2bfloat16(v.z - __bfloat162float(h2));
    __nv_bfloat16 l3 = __float2bfloat16(v.w - __bfloat162float(h3));
    ((__nv_bfloat162*)hi)[i * 2]     = __nv_bfloat162(h0, h1);
    ((__nv_bfloat162*)hi)[i * 2 + 1] = __nv_bfloat162(h2, h3);
    ((__nv_bfloat162*)lo)[i * 2]     = __nv_bfloat162(l0, l1);
    ((__nv_bfloat162*)lo)[i * 2 + 1] = __nv_bfloat162(l2, l3);
}

// ============================================================================
// mma.sync bf16 split GEMM: C[M,N] = A[M,K] * B[N,K]^T  (fp32 via 3-term split)
// CTA 128x128, K-chunk 64, cp.async double buffer, 8 warps (2x4), warp 64x32.
// EPI: 0 = fp32 store, 1 = silu(x+bias) fp32, 2 = bf16 hi/lo split store
// ============================================================================
#define KCH 64
#define STAGE_BYTES 65536   // 4 tiles x 16KB (Ahi, Alo, Bhi, Blo)

template<int EPI>
__global__ void __launch_bounds__(256, 1) gemm_mma(
    const __nv_bfloat16* __restrict__ Ahi, const __nv_bfloat16* __restrict__ Alo,
    const __nv_bfloat16* __restrict__ Bhi, const __nv_bfloat16* __restrict__ Blo,
    const float* __restrict__ bias,
    float* __restrict__ Cf,
    __nv_bfloat16* __restrict__ Chi, __nv_bfloat16* __restrict__ Clo,
    int K, int N)
{
    extern __shared__ char dsm[];
    const int tid  = threadIdx.x;
    const int wid  = tid >> 5;
    const int lane = tid & 31;
    const int wm = wid & 1;
    const int wn = wid >> 1;
    const int bm = blockIdx.y * 128;
    const int bn = blockIdx.x * 128;

    const uint32_t sbase = (smem_u32(dsm) + 1023u) & ~1023u;

    float acc[4][4][4];
    #pragma unroll
    for (int i = 0; i < 4; ++i)
        #pragma unroll
        for (int j = 0; j < 4; ++j)
            #pragma unroll
            for (int e = 0; e < 4; ++e) acc[i][j][e] = 0.0f;

    const int lrow = tid >> 3;
    const int lc   = tid & 7;
    auto load_stage = [&](int s, int k0){
        const uint32_t tA_hi = sbase + s * STAGE_BYTES;
        const uint32_t tA_lo = tA_hi + 16384;
        const uint32_t tB_hi = tA_hi + 32768;
        const uint32_t tB_lo = tA_hi + 49152;
        #pragma unroll
        for (int p = 0; p < 4; ++p){
            const int row = lrow + p * 32;
            const uint32_t sw = SWZ128((uint32_t)(row * 128 + lc * 16));
            const size_t ga = (size_t)(bm + row) * K + k0 + lc * 8;
            const size_t gb = (size_t)(bn + row) * K + k0 + lc * 8;
            cpasync16(tA_hi + sw, Ahi + ga);
            cpasync16(tA_lo + sw, Alo + ga);
            cpasync16(tB_hi + sw, Bhi + gb);
            cpasync16(tB_lo + sw, Blo + gb);
        }
        CP_COMMIT();
    };

    const int NIT = K / KCH;
    load_stage(0, 0);

    const int lr8  = (lane & 7) + ((lane & 8) ? 8 : 0);
    const int lk16 = (lane & 16) ? 16 : 0;

    for (int it = 0; it < NIT; ++it){
        if (it + 1 < NIT){
            load_stage((it + 1) & 1, (it + 1) * KCH);
            CP_WAIT(1);
        } else {
            CP_WAIT(0);
        }
        __syncthreads();

        const uint32_t st   = sbase + (it & 1) * STAGE_BYTES;
        const uint32_t sAhi = st;
        const uint32_t sAlo = st + 16384;
        const uint32_t sBhi = st + 32768;
        const uint32_t sBlo = st + 49152;

        #pragma unroll
        for (int ks = 0; ks < 4; ++ks){
            uint32_t ah[4][4], al[4][4], bh[2][4], bl[2][4];
            #pragma unroll
            for (int i = 0; i < 4; ++i){
                const int r = wm * 64 + i * 16 + lr8;
                const uint32_t off = SWZ128((uint32_t)(r * 128 + ks * 32 + lk16));
                ldsm_x4(ah[i], sAhi + off);
                ldsm_x4(al[i], sAlo + off);
            }
            #pragma unroll
            for (int np = 0; np < 2; ++np){
                const int r = wn * 32 + np * 16 + lr8;
                const uint32_t off = SWZ128((uint32_t)(r * 128 + ks * 32 + lk16));
                ldsm_x4(bh[np], sBhi + off);
                ldsm_x4(bl[np], sBlo + off);
            }
            #pragma unroll
            for (int i = 0; i < 4; ++i){
                #pragma unroll
                for (int j = 0; j < 4; ++j){
                    const int np = j >> 1, sl = j & 1;
                    mma16816(acc[i][j], ah[i], bh[np][sl], bh[np][sl + 2]);
                    mma16816(acc[i][j], al[i], bh[np][sl], bh[np][sl + 2]);
                    mma16816(acc[i][j], ah[i], bl[np][sl], bl[np][sl + 2]);
                }
            }
        }
        __syncthreads();
    }

    const int qr = lane >> 2;
    const int qc = (lane & 3) * 2;
    #pragma unroll
    for (int i = 0; i < 4; ++i){
        #pragma unroll
        for (int j = 0; j < 4; ++j){
            const int col = bn + wn * 32 + j * 8 + qc;
            #pragma unroll
            for (int h = 0; h < 2; ++h){
                const int row = bm + wm * 64 + i * 16 + qr + h * 8;
                float v0 = acc[i][j][h * 2];
                float v1 = acc[i][j][h * 2 + 1];
                if (EPI == 1){
                    v0 += bias[col];
                    v1 += bias[col + 1];
                    v0 = v0 / (1.0f + expf(-v0));
                    v1 = v1 / (1.0f + expf(-v1));
                    *(float2*)(Cf + (size_t)row * N + col) = make_float2(v0, v1);
                } else if (EPI == 2){
                    __nv_bfloat16 h0 = __float2bfloat16(v0);
                    __nv_bfloat16 h1 = __float2bfloat16(v1);
                    __nv_bfloat16 l0 = __float2bfloat16(v0 - __bfloat162float(h0));
                    __nv_bfloat16 l1 = __float2bfloat16(v1 - __bfloat162float(h1));
                    *(__nv_bfloat162*)(Chi + (size_t)row * N + col) = __nv_bfloat162(h0, h1);
                    *(__nv_bfloat162*)(Clo + (size_t)row * N + col) = __nv_bfloat162(l0, l1);
                } else {
                    *(float2*)(Cf + (size_t)row * N + col) = make_float2(v0, v1);
                }
            }
        }
    }
}

// ============================================================================
// Launch
// ============================================================================
extern "C" void kernel_launch(void* const* d_in, const int* in_sizes, int n_in,
                              void* d_out, int out_size)
{
    (void)in_sizes; (void)n_in;
    const float* x    = (const float*)d_in[0];
    const float* h0   = (const float*)d_in[1];
    const float* inw  = (const float*)d_in[2];
    const float* outw = (const float*)d_in[3];
    const float* ch   = (const float*)d_in[4];
    const float* cx   = (const float*)d_in[5];
    const float* bv   = (const float*)d_in[6];
    const float* wg   = (const float*)d_in[7];
    const float* bg   = (const float*)d_in[8];

    float* out = (float*)d_out;
    float* hfinal = (out_size >= (int)(ROWS * DIMX + B_SZ * DI))
                        ? out + (size_t)ROWS * DIMX : nullptr;

    float *p_gate, *p_pre, *p_hseq;
    float2 *p_W, *p_FCh, *p_FCx;
    __nv_bfloat16 *p_xhi, *p_xlo, *p_xphi, *p_xplo, *p_clhi, *p_cllo;
    __nv_bfloat16 *p_iwhi, *p_iwlo, *p_wghi, *p_wglo, *p_owhi, *p_owlo;
    cudaGetSymbolAddress((void**)&p_gate,  g_gate);
    cudaGetSymbolAddress((void**)&p_pre,   g_pre);
    cudaGetSymbolAddress((void**)&p_hseq,  g_hseq);
    cudaGetSymbolAddress((void**)&p_W,     g_W);
    cudaGetSymbolAddress((void**)&p_FCh,   g_FCh);
    cudaGetSymbolAddress((void**)&p_FCx,   g_FCx);
    cudaGetSymbolAddress((void**)&p_xhi,   g_xhi);
    cudaGetSymbolAddress((void**)&p_xlo,   g_xlo);
    cudaGetSymbolAddress((void**)&p_xphi,  g_xphi);
    cudaGetSymbolAddress((void**)&p_xplo,  g_xplo);
    cudaGetSymbolAddress((void**)&p_clhi,  g_clhi);
    cudaGetSymbolAddress((void**)&p_cllo,  g_cllo);
    cudaGetSymbolAddress((void**)&p_iwhi,  g_iwhi);
    cudaGetSymbolAddress((void**)&p_iwlo,  g_iwlo);
    cudaGetSymbolAddress((void**)&p_wghi,  g_wghi);
    cudaGetSymbolAddress((void**)&p_wglo,  g_wglo);
    cudaGetSymbolAddress((void**)&p_owhi,  g_owhi);
    cudaGetSymbolAddress((void**)&p_owlo,  g_owlo);

    cudaFuncSetAttribute(conv_pre_kernel, cudaFuncAttributeMaxDynamicSharedMemorySize, 65536);
    cudaFuncSetAttribute(scan_kernel,     cudaFuncAttributeMaxDynamicSharedMemorySize, 49152);
    cudaFuncSetAttribute(spectra_kernel,  cudaFuncAttributeMaxDynamicSharedMemorySize, 49152);
    const int GSM = 2 * STAGE_BYTES + 1024;
    cudaFuncSetAttribute(gemm_mma<0>, cudaFuncAttributeMaxDynamicSharedMemorySize, GSM);
    cudaFuncSetAttribute(gemm_mma<1>, cudaFuncAttributeMaxDynamicSharedMemorySize, GSM);
    cudaFuncSetAttribute(gemm_mma<2>, cudaFuncAttributeMaxDynamicSharedMemorySize, GSM);

    // setup
    twiddle_kernel<<<4, 512>>>(p_W);
    spectra_kernel<<<1, 256, 49152>>>(ch, cx, p_W, p_FCh, p_FCx);

    // split inputs / weights to bf16 hi/lo
    split_kernel<<<(ROWS * DIMX / 4 + 255) / 256, 256>>>(x,    p_xhi,  p_xlo,  ROWS * DIMX / 4);
    split_kernel<<<(DI * DIMX   / 4 + 255) / 256, 256>>>(inw,  p_iwhi, p_iwlo, DI * DIMX / 4);
    split_kernel<<<(DI * DI     / 4 + 255) / 256, 256>>>(wg,   p_wghi, p_wglo, DI * DI / 4);
    split_kernel<<<(DIMX * DI   / 4 + 255) / 256, 256>>>(outw, p_owhi, p_owlo, DIMX * DI / 4);

    // GEMM1: x_proj = x @ in_proj_w^T  -> bf16 split  [8192,2048]
    gemm_mma<2><<<dim3(DI / 128, ROWS / 128), 256, GSM>>>(
        p_xhi, p_xlo, p_iwhi, p_iwlo, nullptr, nullptr, p_xphi, p_xplo, DIMX, DI);

    // ---- fork: GEMM2 (gate) runs concurrently with conv_pre + scan ----
    cudaStream_t s2;
    cudaEvent_t ev1, ev2;
    cudaStreamCreateWithFlags(&s2, cudaStreamNonBlocking);
    cudaEventCreateWithFlags(&ev1, cudaEventDisableTiming);
    cudaEventCreateWithFlags(&ev2, cudaEventDisableTiming);
    cudaEventRecord(ev1, 0);
    cudaStreamWaitEvent(s2, ev1, 0);

    // GEMM2 on side stream: gate = silu(x_proj @ W_gate^T + b_gate)
    gemm_mma<1><<<dim3(DI / 128, ROWS / 128), 256, GSM, s2>>>(
        p_xphi, p_xplo, p_wghi, p_wglo, bg, p_gate, nullptr, nullptr, DI, DI);
    cudaEventRecord(ev2, s2);

    // main stream: pre = circ_conv(c_x, x_proj) + b, then the scan
    conv_pre_kernel<<<ROWS / 2, 256, 65536>>>(p_xphi, p_xplo, bv, p_W, p_FCx, p_pre);
    scan_kernel<<<4, 256, 49152>>>(p_pre, p_hseq, p_W, p_FCh, h0, hfinal);

    // join
    cudaStreamWaitEvent(0, ev2, 0);

    // cell = hseq * gate -> bf16 split
    cell_split_kernel<<<(ROWS * DI / 4 + 255) / 256, 256>>>(
        p_hseq, p_gate, p_clhi, p_cllo, ROWS * DI / 4);

    // GEMM3: output = cell @ out_proj_w^T
    gemm_mma<0><<<dim3(DIMX / 128, ROWS / 128), 256, GSM>>>(
        p_clhi, p_cllo, p_owhi, p_owlo, nullptr, out, nullptr, nullptr, DI, DIMX);
}

// round 6
// speedup vs baseline: 1.5409x; 1.4728x over previous
#include <cuda_runtime.h>
#include <cuda_bf16.h>
#include <math.h>
#include <stdint.h>

#ifndef M_PI
#define M_PI 3.14159265358979323846
#endif

// Problem constants
#define B_SZ   8
#define T_SZ   1024
#define DIMX   1024
#define DI     2048
#define NFFT   2048
#define ROWS   (B_SZ * T_SZ)   // 8192

// ----- device scratch -----
__device__ float  g_gate [(size_t)ROWS * DI];
__device__ float  g_pre  [(size_t)ROWS * DI];
__device__ float  g_hseq [(size_t)ROWS * DI];
__device__ float2 g_W   [NFFT];
__device__ float2 g_FCh [NFFT];
__device__ float2 g_FCx [NFFT];
__device__ float2 g_FChP[NFFT];   // permuted spectrum of c_h (scan layout)

// bf16 split operands
__device__ __nv_bfloat16 g_xhi [(size_t)ROWS * DIMX];
__device__ __nv_bfloat16 g_xlo [(size_t)ROWS * DIMX];
__device__ __nv_bfloat16 g_xphi[(size_t)ROWS * DI];
__device__ __nv_bfloat16 g_xplo[(size_t)ROWS * DI];
__device__ __nv_bfloat16 g_clhi[(size_t)ROWS * DI];
__device__ __nv_bfloat16 g_cllo[(size_t)ROWS * DI];
__device__ __nv_bfloat16 g_iwhi[(size_t)DI * DIMX];
__device__ __nv_bfloat16 g_iwlo[(size_t)DI * DIMX];
__device__ __nv_bfloat16 g_wghi[(size_t)DI * DI];
__device__ __nv_bfloat16 g_wglo[(size_t)DI * DI];
__device__ __nv_bfloat16 g_owhi[(size_t)DIMX * DI];
__device__ __nv_bfloat16 g_owlo[(size_t)DIMX * DI];

__device__ __forceinline__ float2 cmulf(float2 a, float2 b){
    return make_float2(fmaf(a.x, b.x, -a.y * b.y), fmaf(a.x, b.y, a.y * b.x));
}
__device__ __forceinline__ float2 cadd(float2 a, float2 b){ return make_float2(a.x+b.x, a.y+b.y); }
__device__ __forceinline__ float2 csub(float2 a, float2 b){ return make_float2(a.x-b.x, a.y-b.y); }

__device__ __forceinline__ float tanh_fast(float x){
    float ax = fabsf(x);
    float e  = __expf(-2.0f * ax);
    float r  = __fdividef(1.0f - e, 1.0f + e);
    return copysignf(r, x);
}

// bank swizzle for old-style FFT smem buffers
__device__ __forceinline__ int sidx(int i){ return i ^ ((i >> 4) & 15); }

// ============================================================================
// PTX helpers (plain sm_103 — NO tcgen05)
// ============================================================================
__device__ __forceinline__ uint32_t smem_u32(const void* p){
    uint32_t a;
    asm("{ .reg .u64 t; cvta.to.shared.u64 t, %1; cvt.u32.u64 %0, t; }" : "=r"(a) : "l"(p));
    return a;
}
__device__ __forceinline__ void cpasync16(uint32_t dst, const void* src){
    asm volatile("cp.async.cg.shared.global [%0], [%1], 16;" :: "r"(dst), "l"(src));
}
#define CP_COMMIT()  asm volatile("cp.async.commit_group;" ::: "memory")
#define CP_WAIT(n)   asm volatile("cp.async.wait_group %0;" :: "n"(n) : "memory")

__device__ __forceinline__ void ldsm_x4(uint32_t* r, uint32_t addr){
    asm volatile("ldmatrix.sync.aligned.m8n8.x4.shared.b16 {%0,%1,%2,%3}, [%4];"
        : "=r"(r[0]), "=r"(r[1]), "=r"(r[2]), "=r"(r[3]) : "r"(addr));
}
__device__ __forceinline__ void mma16816(float* c, const uint32_t* a,
                                         uint32_t b0, uint32_t b1){
    asm volatile("mma.sync.aligned.m16n8k16.row.col.f32.bf16.bf16.f32 "
        "{%0,%1,%2,%3}, {%4,%5,%6,%7}, {%8,%9}, {%0,%1,%2,%3};"
        : "+f"(c[0]), "+f"(c[1]), "+f"(c[2]), "+f"(c[3])
        : "r"(a[0]), "r"(a[1]), "r"(a[2]), "r"(a[3]), "r"(b0), "r"(b1));
}

#define SWZ128(o) ((o) ^ (((o) >> 3) & 0x70))

// ============================================================================
// Radix-8 DFT core. DIR=0 fwd (e^-i), DIR=1 inv (e^+i). No scaling.
// ============================================================================
template<int DIR>
__device__ __forceinline__ void dft8(const float2* a, float2* X)
{
    const float RS = 0.70710678118654752f;
    float2 s0 = cadd(a[0], a[4]), s1 = csub(a[0], a[4]);
    float2 s2 = cadd(a[2], a[6]), s3 = csub(a[2], a[6]);
    float2 s3i = DIR ? make_float2(-s3.y, s3.x) : make_float2(s3.y, -s3.x);
    float2 E0 = cadd(s0, s2), E2 = csub(s0, s2);
    float2 E1 = cadd(s1, s3i), E3 = csub(s1, s3i);
    float2 u0 = cadd(a[1], a[5]), u1 = csub(a[1], a[5]);
    float2 u2 = cadd(a[3], a[7]), u3 = csub(a[3], a[7]);
    float2 u3i = DIR ? make_float2(-u3.y, u3.x) : make_float2(u3.y, -u3.x);
    float2 O0 = cadd(u0, u2), O2 = csub(u0, u2);
    float2 O1 = cadd(u1, u3i), O3 = csub(u1, u3i);
    float2 t1, t2, t3;
    if (DIR == 0){
        t1 = make_float2((O1.x + O1.y) * RS, (O1.y - O1.x) * RS);
        t2 = make_float2(O2.y, -O2.x);
        t3 = make_float2((O3.y - O3.x) * RS, -(O3.x + O3.y) * RS);
    } else {
        t1 = make_float2((O1.x - O1.y) * RS, (O1.x + O1.y) * RS);
        t2 = make_float2(-O2.y, O2.x);
        t3 = make_float2(-(O3.x + O3.y) * RS, (O3.x - O3.y) * RS);
    }
    X[0] = cadd(E0, O0);  X[4] = csub(E0, O0);
    X[1] = cadd(E1, t1);  X[5] = csub(E1, t1);
    X[2] = cadd(E2, t2);  X[6] = csub(E2, t2);
    X[3] = cadd(E3, t3);  X[7] = csub(E3, t3);
}

// ============================================================================
// Shuffle-based 2048-pt transform  T = P ∘ DFT2048 (fixed permutation P).
// 256 threads; thread t = w*32+l owns z[t + 256*r], r=0..8.
// fwd: reg radix-8 (+W_2048^{t r}) -> smem exchange -> warp radix-8 over w
//      (+W_256^{l c}) -> lane FFT-32 via shfl (DIF, no reorder).
// inv: exact mirror with conjugate twiddles. P never materialized: the
// pointwise spectrum (FC) is produced by the SAME fwd transform.
// ============================================================================
struct TW {
    float2 f1[7];  // W_2048^{t*r},  r=1..7
    float2 f2[7];  // W_256^{l*c},   c=1..7
    float2 lt[4];  // lane stages h=16,8,4,2: e^{-i·pi·(l&(h-1))/h}
};

__device__ __forceinline__ void make_tw(TW& tw, int t, int l){
    #pragma unroll
    for (int r = 1; r < 8; ++r){
        double a = -2.0 * M_PI * (double)((t * r) & 2047) / 2048.0;
        double s, c; sincos(a, &s, &c);
        tw.f1[r-1] = make_float2((float)c, (float)s);
    }
    #pragma unroll
    for (int c2 = 1; c2 < 8; ++c2){
        double a = -2.0 * M_PI * (double)((l * c2) & 255) / 256.0;
        double s, c; sincos(a, &s, &c);
        tw.f2[c2-1] = make_float2((float)c, (float)s);
    }
    #pragma unroll
    for (int s2 = 0; s2 < 4; ++s2){
        int h = 16 >> s2;
        double a = -M_PI * (double)(l & (h - 1)) / (double)h;
        double s, c; sincos(a, &s, &c);
        tw.lt[s2] = make_float2((float)c, (float)s);
    }
}

__device__ __forceinline__ float2 shfl_xor_c(float2 v, int m){
    float2 r;
    r.x = __shfl_xor_sync(0xffffffffu, v.x, m);
    r.y = __shfl_xor_sync(0xffffffffu, v.y, m);
    return r;
}

// forward transform: z[8] -> spec[8]. Uses ex[2048] smem; 2 barriers.
__device__ __forceinline__ void fwd2048(const float2* z, float2* spec, float2* ex,
                                        const TW& tw, int l, int w)
{
    float2 y[8];
    dft8<0>(z, y);
    #pragma unroll
    for (int r = 1; r < 8; ++r) y[r] = cmulf(y[r], tw.f1[r-1]);
    const int xr = (l >> 1) & 7;
    __syncthreads();                       // protect prior reads of ex
    #pragma unroll
    for (int r = 0; r < 8; ++r) ex[r*256 + l*8 + (w ^ xr)] = y[r];
    __syncthreads();
    float2 u[8];
    const int base = w*256 + l*8;
    #pragma unroll
    for (int j = 0; j < 8; ++j) u[j] = ex[base + (j ^ xr)];
    dft8<0>(u, spec);                      // over warps -> slot c
    #pragma unroll
    for (int c = 1; c < 8; ++c) spec[c] = cmulf(spec[c], tw.f2[c-1]);
    #pragma unroll
    for (int c = 0; c < 8; ++c){           // lane FFT-32, DIF, no reorder
        float2 v = spec[c];
        #pragma unroll
        for (int s = 0; s < 4; ++s){
            const int h = 16 >> s;
            float2 p = shfl_xor_c(v, h);
            if (l & h) v = cmulf(csub(p, v), tw.lt[s]);
            else       v = cadd(v, p);
        }
        {   float2 p = shfl_xor_c(v, 1);
            v = (l & 1) ? csub(p, v) : cadd(v, p); }
        spec[c] = v;
    }
}

// inverse transform: spec[8] -> z[8]. Exact mirror of fwd2048.
__device__ __forceinline__ void inv2048(float2* spec, float2* z, float2* ex,
                                        const TW& tw, int l, int w)
{
    #pragma unroll
    for (int c = 0; c < 8; ++c){           // lane inverse FFT-32 (DIT)
        float2 v = spec[c];
        {   float2 p = shfl_xor_c(v, 1);
            v = (l & 1) ? csub(p, v) : cadd(v, p); }
        #pragma unroll
        for (int s = 3; s >= 0; --s){
            const int h = 16 >> s;
            float2 wc = tw.lt[s]; wc.y = -wc.y;
            if (l & h) v = cmulf(v, wc);
            float2 p = shfl_xor_c(v, h);
            v = (l & h) ? csub(p, v) : cadd(v, p);
        }
        spec[c] = v;
    }
    #pragma unroll
    for (int c = 1; c < 8; ++c){
        float2 wc = tw.f2[c-1]; wc.y = -wc.y;
        spec[c] = cmulf(spec[c], wc);
    }
    float2 uu[8];
    dft8<1>(spec, uu);                     // inverse over slot c -> warps
    const int xr = (l >> 1) & 7;
    const int base = w*256 + l*8;
    __syncthreads();                       // protect fwd reads of ex
    #pragma unroll
    for (int j = 0; j < 8; ++j) ex[base + (j ^ xr)] = uu[j];
    __syncthreads();
    float2 y[8];
    #pragma unroll
    for (int r = 0; r < 8; ++r) y[r] = ex[r*256 + l*8 + (w ^ xr)];
    #pragma unroll
    for (int r = 1; r < 8; ++r){
        float2 wc = tw.f1[r-1]; wc.y = -wc.y;
        y[r] = cmulf(y[r], wc);
    }
    dft8<1>(y, z);
}

// prep: FChP = T(c_h) / 2048 in the scan's permuted layout
__global__ void prep_fchp_kernel(const float* __restrict__ ch, float2* __restrict__ FChP)
{
    __shared__ float2 ex[2048];
    const int t = threadIdx.x, l = t & 31, w = t >> 5;
    TW tw; make_tw(tw, t, l);
    float2 z[8], spec[8];
    #pragma unroll
    for (int r = 0; r < 8; ++r)
        z[r] = make_float2(ch[t + 256*r] * (1.0f/2048.0f), 0.0f);
    fwd2048(z, spec, ex, tw, l, w);
    #pragma unroll
    for (int c = 0; c < 8; ++c) FChP[t*8 + c] = spec[c];
}

// ============================================================================
// Sequential scan: 4 CTAs (batch pairs packed complex), 256 threads.
// State, twiddles and FC spectrum all live in registers; 2 smem exchanges
// + 4 barriers per step.
// ============================================================================
__global__ void __launch_bounds__(256, 1) scan_kernel(
    const float* __restrict__ pre, float* __restrict__ hseq,
    const float2* __restrict__ FChP,
    const float* __restrict__ h0, float* __restrict__ hfinal)
{
    __shared__ float2 ex[2048];
    const int t = threadIdx.x, l = t & 31, w = t >> 5;
    const int b0 = blockIdx.x * 2, b1 = b0 + 1;
    TW tw; make_tw(tw, t, l);
    float2 fc[8];
    #pragma unroll
    for (int c = 0; c < 8; ++c) fc[c] = FChP[t*8 + c];
    float2 z[8];
    #pragma unroll
    for (int r = 0; r < 8; ++r)
        z[r] = make_float2(h0[(size_t)b0 * DI + t + 256*r],
                           h0[(size_t)b1 * DI + t + 256*r]);

    const float* pre0 = pre  + (size_t)b0 * T_SZ * DI;
    const float* pre1 = pre  + (size_t)b1 * T_SZ * DI;
    float*       hs0  = hseq + (size_t)b0 * T_SZ * DI;
    float*       hs1  = hseq + (size_t)b1 * T_SZ * DI;

    for (int ts = 0; ts < T_SZ; ++ts){
        const size_t off = (size_t)ts * DI;
        float pr0[8], pr1[8];
        #pragma unroll
        for (int r = 0; r < 8; ++r){
            pr0[r] = pre0[off + t + 256*r];
            pr1[r] = pre1[off + t + 256*r];
        }
        float2 spec[8];
        fwd2048(z, spec, ex, tw, l, w);
        #pragma unroll
        for (int c = 0; c < 8; ++c) spec[c] = cmulf(spec[c], fc[c]);
        inv2048(spec, z, ex, tw, l, w);
        #pragma unroll
        for (int r = 0; r < 8; ++r){
            float hr = tanh_fast(z[r].x + pr0[r]);
            float hi = tanh_fast(z[r].y + pr1[r]);
            hs0[off + t + 256*r] = hr;
            hs1[off + t + 256*r] = hi;
            z[r] = make_float2(hr, hi);
        }
    }
    if (hfinal){
        #pragma unroll
        for (int r = 0; r < 8; ++r){
            hfinal[(size_t)b0 * DI + t + 256*r] = z[r].x;
            hfinal[(size_t)b1 * DI + t + 256*r] = z[r].y;
        }
    }
}

// ============================================================================
// OLD smem Stockham FFT path (verified) — kept for conv_pre / spectra.
// ============================================================================
template<int DIR>
__device__ __forceinline__ void fft2048_r8(float2* bufA, float2* bufB,
                                           const float2* __restrict__ W, int tid)
{
    float2* X = bufA;
    float2* Y = bufB;
    #pragma unroll
    for (int st = 0; st < 3; ++st){
        const int s  = (st == 0) ? 1 : (st == 1) ? 8 : 64;
        const int ps = tid & ~(s - 1);
        const int q  = tid & (s - 1);
        float2 a[8], o[8];
        #pragma unroll
        for (int r = 0; r < 8; ++r) a[r] = X[sidx(tid + 256 * r)];
        dft8<DIR>(a, o);
        const int ob = q + 8 * ps;
        Y[sidx(ob)] = o[0];
        #pragma unroll
        for (int r = 1; r < 8; ++r){
            float2 w = W[r * ps];
            if (DIR) w.y = -w.y;
            Y[sidx(ob + s * r)] = cmulf(w, o[r]);
        }
        __syncthreads();
        float2* tmp = X; X = Y; Y = tmp;
    }
    #pragma unroll
    for (int h = 0; h < 2; ++h){
        const int j = tid + 256 * h;
        float2 a = X[sidx(j)];
        float2 b = X[sidx(j + 512)];
        float2 c = X[sidx(j + 1024)];
        float2 d = X[sidx(j + 1536)];
        float2 apc = cadd(a, c), amc = csub(a, c);
        float2 bpd = cadd(b, d), bmd = csub(b, d);
        float2 ib  = make_float2(-bmd.y, bmd.x);
        float2 x1, x3;
        if (DIR == 0){ x1 = csub(amc, ib); x3 = cadd(amc, ib); }
        else         { x1 = cadd(amc, ib); x3 = csub(amc, ib); }
        Y[sidx(j)]        = cadd(apc, bpd);
        Y[sidx(j + 512)]  = x1;
        Y[sidx(j + 1024)] = csub(apc, bpd);
        Y[sidx(j + 1536)] = x3;
    }
    __syncthreads();
}

__global__ void twiddle_kernel(float2* __restrict__ W)
{
    int k = blockIdx.x * blockDim.x + threadIdx.x;
    if (k < NFFT){
        double a = -2.0 * M_PI * (double)k / (double)NFFT;
        W[k] = make_float2((float)cos(a), (float)sin(a));
    }
}

__global__ void spectra_kernel(const float* __restrict__ ch, const float* __restrict__ cx,
                               const float2* __restrict__ Wg,
                               float2* __restrict__ FCh, float2* __restrict__ FCx)
{
    extern __shared__ float2 sm[];
    float2* bufA = sm;
    float2* bufB = sm + 2048;
    float2* Wc   = sm + 4096;
    const int tid = threadIdx.x;
    for (int k = tid; k < NFFT; k += 256){
        Wc[k] = Wg[k];
        bufA[sidx(k)] = make_float2(ch[k], cx[k]);
    }
    __syncthreads();
    fft2048_r8<0>(bufA, bufB, Wc, tid);
    const float inv = 1.0f / (float)NFFT;
    for (int k = tid; k < NFFT; k += 256){
        float2 A  = bufA[sidx(k)];
        float2 Zm = bufA[sidx((NFFT - k) & (NFFT - 1))];
        float2 Bc = make_float2(Zm.x, -Zm.y);
        float2 FH = make_float2(0.5f * (A.x + Bc.x), 0.5f * (A.y + Bc.y));
        float2 Dd = make_float2(A.x - Bc.x, A.y - Bc.y);
        float2 FX = make_float2(0.5f * Dd.y, -0.5f * Dd.x);
        FCh[k] = make_float2(FH.x * inv, FH.y * inv);
        FCx[k] = make_float2(FX.x * inv, FX.y * inv);
    }
}

__global__ void conv_pre_kernel(const __nv_bfloat16* __restrict__ xph,
                                const __nv_bfloat16* __restrict__ xpl,
                                const float* __restrict__ bvec,
                                const float2* __restrict__ Wg, const float2* __restrict__ FCg,
                                float* __restrict__ pre)
{
    extern __shared__ float2 sm[];
    float2* bufA = sm;
    float2* bufB = sm + 2048;
    float2* Wc   = sm + 4096;
    float2* FC   = sm + 6144;
    const int tid = threadIdx.x;
    const size_t r0 = (size_t)blockIdx.x * 2;
    const __nv_bfloat16* h0p = xph + r0 * DI;
    const __nv_bfloat16* l0p = xpl + r0 * DI;
    for (int k = tid; k < NFFT; k += 256){
        Wc[k] = Wg[k];
        FC[k] = FCg[k];
        float v0 = __bfloat162float(h0p[k]) + __bfloat162float(l0p[k]);
        float v1 = __bfloat162float(h0p[DI + k]) + __bfloat162float(l0p[DI + k]);
        bufA[sidx(k)] = make_float2(v0, v1);
    }
    __syncthreads();
    fft2048_r8<0>(bufA, bufB, Wc, tid);
    for (int k = tid; k < NFFT; k += 256){
        int si = sidx(k);
        bufA[si] = cmulf(bufA[si], FC[k]);
    }
    __syncthreads();
    fft2048_r8<1>(bufA, bufB, Wc, tid);
    float* p0 = pre + r0 * DI;
    float* p1 = p0 + DI;
    for (int k = tid; k < NFFT; k += 256){
        const float bb = bvec[k];
        float2 v = bufA[sidx(k)];
        p0[k] = v.x + bb;
        p1[k] = v.y + bb;
    }
}

// ============================================================================
// Elementwise split helpers
// ============================================================================
__global__ void split_kernel(const float* __restrict__ s,
                             __nv_bfloat16* __restrict__ hi, __nv_bfloat16* __restrict__ lo,
                             int n4)
{
    int i = blockIdx.x * blockDim.x + threadIdx.x;
    if (i >= n4) return;
    float4 v = ((const float4*)s)[i];
    __nv_bfloat16 h0 = __float2bfloat16(v.x), h1 = __float2bfloat16(v.y);
    __nv_bfloat16 h2 = __float2bfloat16(v.z), h3 = __float2bfloat16(v.w);
    __nv_bfloat16 l0 = __float2bfloat16(v.x - __bfloat162float(h0));
    __nv_bfloat16 l1 = __float2bfloat16(v.y - __bfloat162float(h1));
    __nv_bfloat16 l2 = __float2bfloat16(v.z - __bfloat162float(h2));
    __nv_bfloat16 l3 = __float2bfloat16(v.w - __bfloat162float(h3));
    ((__nv_bfloat162*)hi)[i * 2]     = __nv_bfloat162(h0, h1);
    ((__nv_bfloat162*)hi)[i * 2 + 1] = __nv_bfloat162(h2, h3);
    ((__nv_bfloat162*)lo)[i * 2]     = __nv_bfloat162(l0, l1);
    ((__nv_bfloat162*)lo)[i * 2 + 1] = __nv_bfloat162(l2, l3);
}

__global__ void cell_split_kernel(const float* __restrict__ a, const float* __restrict__ g,
                                  __nv_bfloat16* __restrict__ hi, __nv_bfloat16* __restrict__ lo,
                                  int n4)
{
    int i = blockIdx.x * blockDim.x + threadIdx.x;
    if (i >= n4) return;
    float4 va = ((const float4*)a)[i];
    float4 vg = ((const float4*)g)[i];
    float4 v = make_float4(va.x * vg.x, va.y * vg.y, va.z * vg.z, va.w * vg.w);
    __nv_bfloat16 h0 = __float2bfloat16(v.x), h1 = __float2bfloat16(v.y);
    __nv_bfloat16 h2 = __float2bfloat16(v.z), h3 = __float2bfloat16(v.w);
    __nv_bfloat16 l0 = __float2bfloat16(v.x - __bfloat162float(h0));
    __nv_bfloat16 l1 = __float2bfloat16(v.y - __bfloat162float(h1));
    __nv_bfloat16 l2 = __float2bfloat16(v.z - __bfloat162float(h2));
    __nv_bfloat16 l3 = __float2bfloat16(v.w - __bfloat162float(h3));
    ((__nv_bfloat162*)hi)[i * 2]     = __nv_bfloat162(h0, h1);
    ((__nv_bfloat162*)hi)[i * 2 + 1] = __nv_bfloat162(h2, h3);
    ((__nv_bfloat162*)lo)[i * 2]     = __nv_bfloat162(l0, l1);
    ((__nv_bfloat162*)lo)[i * 2 + 1] = __nv_bfloat162(l2, l3);
}

// ============================================================================
// mma.sync bf16 split GEMM (unchanged from R5)
// ============================================================================
#define KCH 64
#define STAGE_BYTES 65536

template<int EPI>
__global__ void __launch_bounds__(256, 1) gemm_mma(
    const __nv_bfloat16* __restrict__ Ahi, const __nv_bfloat16* __restrict__ Alo,
    const __nv_bfloat16* __restrict__ Bhi, const __nv_bfloat16* __restrict__ Blo,
    const float* __restrict__ bias,
    float* __restrict__ Cf,
    __nv_bfloat16* __restrict__ Chi, __nv_bfloat16* __restrict__ Clo,
    int K, int N)
{
    extern __shared__ char dsm[];
    const int tid  = threadIdx.x;
    const int wid  = tid >> 5;
    const int lane = tid & 31;
    const int wm = wid & 1;
    const int wn = wid >> 1;
    const int bm = blockIdx.y * 128;
    const int bn = blockIdx.x * 128;

    const uint32_t sbase = (smem_u32(dsm) + 1023u) & ~1023u;

    float acc[4][4][4];
    #pragma unroll
    for (int i = 0; i < 4; ++i)
        #pragma unroll
        for (int j = 0; j < 4; ++j)
            #pragma unroll
            for (int e = 0; e < 4; ++e) acc[i][j][e] = 0.0f;

    const int lrow = tid >> 3;
    const int lc   = tid & 7;
    auto load_stage = [&](int s, int k0){
        const uint32_t tA_hi = sbase + s * STAGE_BYTES;
        const uint32_t tA_lo = tA_hi + 16384;
        const uint32_t tB_hi = tA_hi + 32768;
        const uint32_t tB_lo = tA_hi + 49152;
        #pragma unroll
        for (int p = 0; p < 4; ++p){
            const int row = lrow + p * 32;
            const uint32_t sw = SWZ128((uint32_t)(row * 128 + lc * 16));
            const size_t ga = (size_t)(bm + row) * K + k0 + lc * 8;
            const size_t gb = (size_t)(bn + row) * K + k0 + lc * 8;
            cpasync16(tA_hi + sw, Ahi + ga);
            cpasync16(tA_lo + sw, Alo + ga);
            cpasync16(tB_hi + sw, Bhi + gb);
            cpasync16(tB_lo + sw, Blo + gb);
        }
        CP_COMMIT();
    };

    const int NIT = K / KCH;
    load_stage(0, 0);

    const int lr8  = (lane & 7) + ((lane & 8) ? 8 : 0);
    const int lk16 = (lane & 16) ? 16 : 0;

    for (int it = 0; it < NIT; ++it){
        if (it + 1 < NIT){
            load_stage((it + 1) & 1, (it + 1) * KCH);
            CP_WAIT(1);
        } else {
            CP_WAIT(0);
        }
        __syncthreads();

        const uint32_t st   = sbase + (it & 1) * STAGE_BYTES;
        const uint32_t sAhi = st;
        const uint32_t sAlo = st + 16384;
        const uint32_t sBhi = st + 32768;
        const uint32_t sBlo = st + 49152;

        #pragma unroll
        for (int ks = 0; ks < 4; ++ks){
            uint32_t ah[4][4], al[4][4], bh[2][4], bl[2][4];
            #pragma unroll
            for (int i = 0; i < 4; ++i){
                const int r = wm * 64 + i * 16 + lr8;
                const uint32_t off = SWZ128((uint32_t)(r * 128 + ks * 32 + lk16));
                ldsm_x4(ah[i], sAhi + off);
                ldsm_x4(al[i], sAlo + off);
            }
            #pragma unroll
            for (int np = 0; np < 2; ++np){
                const int r = wn * 32 + np * 16 + lr8;
                const uint32_t off = SWZ128((uint32_t)(r * 128 + ks * 32 + lk16));
                ldsm_x4(bh[np], sBhi + off);
                ldsm_x4(bl[np], sBlo + off);
            }
            #pragma unroll
            for (int i = 0; i < 4; ++i){
                #pragma unroll
                for (int j = 0; j < 4; ++j){
                    const int np = j >> 1, sl = j & 1;
                    mma16816(acc[i][j], ah[i], bh[np][sl], bh[np][sl + 2]);
                    mma16816(acc[i][j], al[i], bh[np][sl], bh[np][sl + 2]);
                    mma16816(acc[i][j], ah[i], bl[np][sl], bl[np][sl + 2]);
                }
            }
        }
        __syncthreads();
    }

    const int qr = lane >> 2;
    const int qc = (lane & 3) * 2;
    #pragma unroll
    for (int i = 0; i < 4; ++i){
        #pragma unroll
        for (int j = 0; j < 4; ++j){
            const int col = bn + wn * 32 + j * 8 + qc;
            #pragma unroll
            for (int h = 0; h < 2; ++h){
                const int row = bm + wm * 64 + i * 16 + qr + h * 8;
                float v0 = acc[i][j][h * 2];
                float v1 = acc[i][j][h * 2 + 1];
                if (EPI == 1){
                    v0 += bias[col];
                    v1 += bias[col + 1];
                    v0 = v0 / (1.0f + expf(-v0));
                    v1 = v1 / (1.0f + expf(-v1));
                    *(float2*)(Cf + (size_t)row * N + col) = make_float2(v0, v1);
                } else if (EPI == 2){
                    __nv_bfloat16 h0 = __float2bfloat16(v0);
                    __nv_bfloat16 h1 = __float2bfloat16(v1);
                    __nv_bfloat16 l0 = __float2bfloat16(v0 - __bfloat162float(h0));
                    __nv_bfloat16 l1 = __float2bfloat16(v1 - __bfloat162float(h1));
                    *(__nv_bfloat162*)(Chi + (size_t)row * N + col) = __nv_bfloat162(h0, h1);
                    *(__nv_bfloat162*)(Clo + (size_t)row * N + col) = __nv_bfloat162(l0, l1);
                } else {
                    *(float2*)(Cf + (size_t)row * N + col) = make_float2(v0, v1);
                }
            }
        }
    }
}

// ============================================================================
// Launch
// ============================================================================
extern "C" void kernel_launch(void* const* d_in, const int* in_sizes, int n_in,
                              void* d_out, int out_size)
{
    (void)in_sizes; (void)n_in;
    const float* x    = (const float*)d_in[0];
    const float* h0   = (const float*)d_in[1];
    const float* inw  = (const float*)d_in[2];
    const float* outw = (const float*)d_in[3];
    const float* ch   = (const float*)d_in[4];
    const float* cx   = (const float*)d_in[5];
    const float* bv   = (const float*)d_in[6];
    const float* wg   = (const float*)d_in[7];
    const float* bg   = (const float*)d_in[8];

    float* out = (float*)d_out;
    float* hfinal = (out_size >= (int)(ROWS * DIMX + B_SZ * DI))
                        ? out + (size_t)ROWS * DIMX : nullptr;

    float *p_gate, *p_pre, *p_hseq;
    float2 *p_W, *p_FCh, *p_FCx, *p_FChP;
    __nv_bfloat16 *p_xhi, *p_xlo, *p_xphi, *p_xplo, *p_clhi, *p_cllo;
    __nv_bfloat16 *p_iwhi, *p_iwlo, *p_wghi, *p_wglo, *p_owhi, *p_owlo;
    cudaGetSymbolAddress((void**)&p_gate,  g_gate);
    cudaGetSymbolAddress((void**)&p_pre,   g_pre);
    cudaGetSymbolAddress((void**)&p_hseq,  g_hseq);
    cudaGetSymbolAddress((void**)&p_W,     g_W);
    cudaGetSymbolAddress((void**)&p_FCh,   g_FCh);
    cudaGetSymbolAddress((void**)&p_FCx,   g_FCx);
    cudaGetSymbolAddress((void**)&p_FChP,  g_FChP);
    cudaGetSymbolAddress((void**)&p_xhi,   g_xhi);
    cudaGetSymbolAddress((void**)&p_xlo,   g_xlo);
    cudaGetSymbolAddress((void**)&p_xphi,  g_xphi);
    cudaGetSymbolAddress((void**)&p_xplo,  g_xplo);
    cudaGetSymbolAddress((void**)&p_clhi,  g_clhi);
    cudaGetSymbolAddress((void**)&p_cllo,  g_cllo);
    cudaGetSymbolAddress((void**)&p_iwhi,  g_iwhi);
    cudaGetSymbolAddress((void**)&p_iwlo,  g_iwlo);
    cudaGetSymbolAddress((void**)&p_wghi,  g_wghi);
    cudaGetSymbolAddress((void**)&p_wglo,  g_wglo);
    cudaGetSymbolAddress((void**)&p_owhi,  g_owhi);
    cudaGetSymbolAddress((void**)&p_owlo,  g_owlo);

    cudaFuncSetAttribute(conv_pre_kernel, cudaFuncAttributeMaxDynamicSharedMemorySize, 65536);
    cudaFuncSetAttribute(spectra_kernel,  cudaFuncAttributeMaxDynamicSharedMemorySize, 49152);
    const int GSM = 2 * STAGE_BYTES + 1024;
    cudaFuncSetAttribute(gemm_mma<0>, cudaFuncAttributeMaxDynamicSharedMemorySize, GSM);
    cudaFuncSetAttribute(gemm_mma<1>, cudaFuncAttributeMaxDynamicSharedMemorySize, GSM);
    cudaFuncSetAttribute(gemm_mma<2>, cudaFuncAttributeMaxDynamicSharedMemorySize, GSM);

    // setup
    twiddle_kernel<<<4, 512>>>(p_W);
    spectra_kernel<<<1, 256, 49152>>>(ch, cx, p_W, p_FCh, p_FCx);
    prep_fchp_kernel<<<1, 256>>>(ch, p_FChP);

    // split inputs / weights to bf16 hi/lo
    split_kernel<<<(ROWS * DIMX / 4 + 255) / 256, 256>>>(x,    p_xhi,  p_xlo,  ROWS * DIMX / 4);
    split_kernel<<<(DI * DIMX   / 4 + 255) / 256, 256>>>(inw,  p_iwhi, p_iwlo, DI * DIMX / 4);
    split_kernel<<<(DI * DI     / 4 + 255) / 256, 256>>>(wg,   p_wghi, p_wglo, DI * DI / 4);
    split_kernel<<<(DIMX * DI   / 4 + 255) / 256, 256>>>(outw, p_owhi, p_owlo, DIMX * DI / 4);

    // GEMM1: x_proj = x @ in_proj_w^T -> bf16 split
    gemm_mma<2><<<dim3(DI / 128, ROWS / 128), 256, GSM>>>(
        p_xhi, p_xlo, p_iwhi, p_iwlo, nullptr, nullptr, p_xphi, p_xplo, DIMX, DI);

    // ---- fork: GEMM2 (gate) concurrent with conv_pre + scan ----
    cudaStream_t s2;
    cudaEvent_t ev1, ev2;
    cudaStreamCreateWithFlags(&s2, cudaStreamNonBlocking);
    cudaEventCreateWithFlags(&ev1, cudaEventDisableTiming);
    cudaEventCreateWithFlags(&ev2, cudaEventDisableTiming);
    cudaEventRecord(ev1, 0);
    cudaStreamWaitEvent(s2, ev1, 0);

    gemm_mma<1><<<dim3(DI / 128, ROWS / 128), 256, GSM, s2>>>(
        p_xphi, p_xplo, p_wghi, p_wglo, bg, p_gate, nullptr, nullptr, DI, DI);
    cudaEventRecord(ev2, s2);

    conv_pre_kernel<<<ROWS / 2, 256, 65536>>>(p_xphi, p_xplo, bv, p_W, p_FCx, p_pre);
    scan_kernel<<<4, 256>>>(p_pre, p_hseq, p_FChP, h0, hfinal);

    cudaStreamWaitEvent(0, ev2, 0);

    cell_split_kernel<<<(ROWS * DI / 4 + 255) / 256, 256>>>(
        p_hseq, p_gate, p_clhi, p_cllo, ROWS * DI / 4);

    gemm_mma<0><<<dim3(DIMX / 128, ROWS / 128), 256, GSM>>>(
        p_clhi, p_cllo, p_owhi, p_owlo, nullptr, out, nullptr, nullptr, DI, DIMX);
}

// round 8
// speedup vs baseline: 1.8830x; 1.2220x over previous
#include <cuda_runtime.h>
#include <cuda_bf16.h>
#include <math.h>
#include <stdint.h>

#ifndef M_PI
#define M_PI 3.14159265358979323846
#endif

// Problem constants
#define B_SZ   8
#define T_SZ   1024
#define DIMX   1024
#define DI     2048
#define NFFT   2048
#define ROWS   (B_SZ * T_SZ)   // 8192
#define THALF  512

// ----- device scratch -----
__device__ float  g_gate [(size_t)ROWS * DI];
__device__ float  g_pre  [(size_t)ROWS * DI];
__device__ float  g_hseq [(size_t)ROWS * DI];
__device__ float  g_hstate[(size_t)B_SZ * DI];
__device__ float2 g_W   [NFFT];
__device__ float2 g_FCh [NFFT];
__device__ float2 g_FCx [NFFT];
__device__ float2 g_FChP[NFFT];

// bf16 split operands
__device__ __nv_bfloat16 g_xhi [(size_t)ROWS * DIMX];
__device__ __nv_bfloat16 g_xlo [(size_t)ROWS * DIMX];
__device__ __nv_bfloat16 g_xphi[(size_t)ROWS * DI];
__device__ __nv_bfloat16 g_xplo[(size_t)ROWS * DI];
__device__ __nv_bfloat16 g_clhi[(size_t)ROWS * DI];
__device__ __nv_bfloat16 g_cllo[(size_t)ROWS * DI];
__device__ __nv_bfloat16 g_iwhi[(size_t)DI * DIMX];
__device__ __nv_bfloat16 g_iwlo[(size_t)DI * DIMX];
__device__ __nv_bfloat16 g_wghi[(size_t)DI * DI];
__device__ __nv_bfloat16 g_wglo[(size_t)DI * DI];
__device__ __nv_bfloat16 g_owhi[(size_t)DIMX * DI];
__device__ __nv_bfloat16 g_owlo[(size_t)DIMX * DI];

__device__ __forceinline__ float2 cmulf(float2 a, float2 b){
    return make_float2(fmaf(a.x, b.x, -a.y * b.y), fmaf(a.x, b.y, a.y * b.x));
}
__device__ __forceinline__ float2 cadd(float2 a, float2 b){ return make_float2(a.x+b.x, a.y+b.y); }
__device__ __forceinline__ float2 csub(float2 a, float2 b){ return make_float2(a.x-b.x, a.y-b.y); }

__device__ __forceinline__ float tanh_fast(float x){
    float ax = fabsf(x);
    float e  = __expf(-2.0f * ax);
    float r  = __fdividef(1.0f - e, 1.0f + e);
    return copysignf(r, x);
}

__device__ __forceinline__ int sidx(int i){ return i ^ ((i >> 4) & 15); }

// ============================================================================
// PTX helpers
// ============================================================================
__device__ __forceinline__ uint32_t smem_u32(const void* p){
    uint32_t a;
    asm("{ .reg .u64 t; cvta.to.shared.u64 t, %1; cvt.u32.u64 %0, t; }" : "=r"(a) : "l"(p));
    return a;
}
__device__ __forceinline__ void cpasync16(uint32_t dst, const void* src){
    asm volatile("cp.async.cg.shared.global [%0], [%1], 16;" :: "r"(dst), "l"(src));
}
#define CP_COMMIT()  asm volatile("cp.async.commit_group;" ::: "memory")
#define CP_WAIT(n)   asm volatile("cp.async.wait_group %0;" :: "n"(n) : "memory")

__device__ __forceinline__ void ldsm_x4(uint32_t* r, uint32_t addr){
    asm volatile("ldmatrix.sync.aligned.m8n8.x4.shared.b16 {%0,%1,%2,%3}, [%4];"
        : "=r"(r[0]), "=r"(r[1]), "=r"(r[2]), "=r"(r[3]) : "r"(addr));
}
__device__ __forceinline__ void mma16816(float* c, const uint32_t* a,
                                         uint32_t b0, uint32_t b1){
    asm volatile("mma.sync.aligned.m16n8k16.row.col.f32.bf16.bf16.f32 "
        "{%0,%1,%2,%3}, {%4,%5,%6,%7}, {%8,%9}, {%0,%1,%2,%3};"
        : "+f"(c[0]), "+f"(c[1]), "+f"(c[2]), "+f"(c[3])
        : "r"(a[0]), "r"(a[1]), "r"(a[2]), "r"(a[3]), "r"(b0), "r"(b1));
}

#define SWZ128(o) ((o) ^ (((o) >> 3) & 0x70))

// ============================================================================
// Radix-8 DFT core
// ============================================================================
template<int DIR>
__device__ __forceinline__ void dft8(const float2* a, float2* X)
{
    const float RS = 0.70710678118654752f;
    float2 s0 = cadd(a[0], a[4]), s1 = csub(a[0], a[4]);
    float2 s2 = cadd(a[2], a[6]), s3 = csub(a[2], a[6]);
    float2 s3i = DIR ? make_float2(-s3.y, s3.x) : make_float2(s3.y, -s3.x);
    float2 E0 = cadd(s0, s2), E2 = csub(s0, s2);
    float2 E1 = cadd(s1, s3i), E3 = csub(s1, s3i);
    float2 u0 = cadd(a[1], a[5]), u1 = csub(a[1], a[5]);
    float2 u2 = cadd(a[3], a[7]), u3 = csub(a[3], a[7]);
    float2 u3i = DIR ? make_float2(-u3.y, u3.x) : make_float2(u3.y, -u3.x);
    float2 O0 = cadd(u0, u2), O2 = csub(u0, u2);
    float2 O1 = cadd(u1, u3i), O3 = csub(u1, u3i);
    float2 t1, t2, t3;
    if (DIR == 0){
        t1 = make_float2((O1.x + O1.y) * RS, (O1.y - O1.x) * RS);
        t2 = make_float2(O2.y, -O2.x);
        t3 = make_float2((O3.y - O3.x) * RS, -(O3.x + O3.y) * RS);
    } else {
        t1 = make_float2((O1.x - O1.y) * RS, (O1.x + O1.y) * RS);
        t2 = make_float2(-O2.y, O2.x);
        t3 = make_float2(-(O3.x + O3.y) * RS, (O3.x - O3.y) * RS);
    }
    X[0] = cadd(E0, O0);  X[4] = csub(E0, O0);
    X[1] = cadd(E1, t1);  X[5] = csub(E1, t1);
    X[2] = cadd(E2, t2);  X[6] = csub(E2, t2);
    X[3] = cadd(E3, t3);  X[7] = csub(E3, t3);
}

// ============================================================================
// Shuffle-based 2048-pt transform T = P ∘ DFT2048. Double-buffered exchange.
// ============================================================================
struct TW {
    float2 f1[7];
    float2 f2[7];
    float2 lt[4];
};

__device__ __forceinline__ void make_tw(TW& tw, int t, int l){
    #pragma unroll
    for (int r = 1; r < 8; ++r){
        double a = -2.0 * M_PI * (double)((t * r) & 2047) / 2048.0;
        double s, c; sincos(a, &s, &c);
        tw.f1[r-1] = make_float2((float)c, (float)s);
    }
    #pragma unroll
    for (int c2 = 1; c2 < 8; ++c2){
        double a = -2.0 * M_PI * (double)((l * c2) & 255) / 256.0;
        double s, c; sincos(a, &s, &c);
        tw.f2[c2-1] = make_float2((float)c, (float)s);
    }
    #pragma unroll
    for (int s2 = 0; s2 < 4; ++s2){
        int h = 16 >> s2;
        double a = -M_PI * (double)(l & (h - 1)) / (double)h;
        double s, c; sincos(a, &s, &c);
        tw.lt[s2] = make_float2((float)c, (float)s);
    }
}

__device__ __forceinline__ float2 shfl_xor_c(float2 v, int m){
    float2 r;
    r.x = __shfl_xor_sync(0xffffffffu, v.x, m);
    r.y = __shfl_xor_sync(0xffffffffu, v.y, m);
    return r;
}

__device__ __forceinline__ void fwd2048(const float2* z, float2* spec, float2* exF,
                                        const TW& tw, int l, int w)
{
    float2 y[8];
    dft8<0>(z, y);
    #pragma unroll
    for (int r = 1; r < 8; ++r) y[r] = cmulf(y[r], tw.f1[r-1]);
    const int xr = (l >> 1) & 7;
    #pragma unroll
    for (int r = 0; r < 8; ++r) exF[r*256 + l*8 + (w ^ xr)] = y[r];
    __syncthreads();
    float2 u[8];
    const int base = w*256 + l*8;
    #pragma unroll
    for (int j = 0; j < 8; ++j) u[j] = exF[base + (j ^ xr)];
    dft8<0>(u, spec);
    #pragma unroll
    for (int c = 1; c < 8; ++c) spec[c] = cmulf(spec[c], tw.f2[c-1]);
    #pragma unroll
    for (int c = 0; c < 8; ++c){
        float2 v = spec[c];
        #pragma unroll
        for (int s = 0; s < 4; ++s){
            const int h = 16 >> s;
            float2 p = shfl_xor_c(v, h);
            if (l & h) v = cmulf(csub(p, v), tw.lt[s]);
            else       v = cadd(v, p);
        }
        {   float2 p = shfl_xor_c(v, 1);
            v = (l & 1) ? csub(p, v) : cadd(v, p); }
        spec[c] = v;
    }
}

__device__ __forceinline__ void inv2048(float2* spec, float2* z, float2* exI,
                                        const TW& tw, int l, int w)
{
    #pragma unroll
    for (int c = 0; c < 8; ++c){
        float2 v = spec[c];
        {   float2 p = shfl_xor_c(v, 1);
            v = (l & 1) ? csub(p, v) : cadd(v, p); }
        #pragma unroll
        for (int s = 3; s >= 0; --s){
            const int h = 16 >> s;
            float2 wc = tw.lt[s]; wc.y = -wc.y;
            if (l & h) v = cmulf(v, wc);
            float2 p = shfl_xor_c(v, h);
            v = (l & h) ? csub(p, v) : cadd(v, p);
        }
        spec[c] = v;
    }
    #pragma unroll
    for (int c = 1; c < 8; ++c){
        float2 wc = tw.f2[c-1]; wc.y = -wc.y;
        spec[c] = cmulf(spec[c], wc);
    }
    float2 uu[8];
    dft8<1>(spec, uu);
    const int xr = (l >> 1) & 7;
    const int base = w*256 + l*8;
    #pragma unroll
    for (int j = 0; j < 8; ++j) exI[base + (j ^ xr)] = uu[j];
    __syncthreads();
    float2 y[8];
    #pragma unroll
    for (int r = 0; r < 8; ++r) y[r] = exI[r*256 + l*8 + (w ^ xr)];
    #pragma unroll
    for (int r = 1; r < 8; ++r){
        float2 wc = tw.f1[r-1]; wc.y = -wc.y;
        y[r] = cmulf(y[r], wc);
    }
    dft8<1>(y, z);
}

// prep: FChP = T(c_h)/2048 in the scan's permuted layout
__global__ void prep_fchp_kernel(const float* __restrict__ ch, float2* __restrict__ FChP)
{
    __shared__ float2 ex[2048];
    const int t = threadIdx.x, l = t & 31, w = t >> 5;
    TW tw; make_tw(tw, t, l);
    float2 z[8], spec[8];
    #pragma unroll
    for (int r = 0; r < 8; ++r)
        z[r] = make_float2(ch[t + 256*r] * (1.0f/2048.0f), 0.0f);
    fwd2048(z, spec, ex, tw, l, w);
    #pragma unroll
    for (int c = 0; c < 8; ++c) FChP[t*8 + c] = spec[c];
}

// ============================================================================
// Scan part kernel: steps [t0,t1). 4 CTAs, 256 threads, state via hin/hstate.
// ============================================================================
__global__ void __launch_bounds__(256, 1) scan_part_kernel(
    const float* __restrict__ pre, float* __restrict__ hseq,
    const float2* __restrict__ FChP,
    const float* __restrict__ hin, float* __restrict__ hstate,
    float* __restrict__ hfinal, int t0, int t1)
{
    __shared__ float2 exF[2048];
    __shared__ float2 exI[2048];
    const int t = threadIdx.x, l = t & 31, w = t >> 5;
    const int b0 = blockIdx.x * 2, b1 = b0 + 1;
    TW tw; make_tw(tw, t, l);
    float2 fc[8];
    #pragma unroll
    for (int c = 0; c < 8; ++c) fc[c] = FChP[t*8 + c];
    float2 z[8];
    #pragma unroll
    for (int r = 0; r < 8; ++r)
        z[r] = make_float2(hin[(size_t)b0 * DI + t + 256*r],
                           hin[(size_t)b1 * DI + t + 256*r]);

    const float* pre0 = pre  + (size_t)b0 * T_SZ * DI;
    const float* pre1 = pre  + (size_t)b1 * T_SZ * DI;
    float*       hs0  = hseq + (size_t)b0 * T_SZ * DI;
    float*       hs1  = hseq + (size_t)b1 * T_SZ * DI;

    for (int ts = t0; ts < t1; ++ts){
        const size_t off = (size_t)ts * DI;
        float pr0[8], pr1[8];
        #pragma unroll
        for (int r = 0; r < 8; ++r){
            pr0[r] = pre0[off + t + 256*r];
            pr1[r] = pre1[off + t + 256*r];
        }
        float2 spec[8];
        fwd2048(z, spec, exF, tw, l, w);
        #pragma unroll
        for (int c = 0; c < 8; ++c) spec[c] = cmulf(spec[c], fc[c]);
        inv2048(spec, z, exI, tw, l, w);
        #pragma unroll
        for (int r = 0; r < 8; ++r){
            float hr = tanh_fast(z[r].x + pr0[r]);
            float hi = tanh_fast(z[r].y + pr1[r]);
            hs0[off + t + 256*r] = hr;
            hs1[off + t + 256*r] = hi;
            z[r] = make_float2(hr, hi);
        }
    }
    #pragma unroll
    for (int r = 0; r < 8; ++r){
        hstate[(size_t)b0 * DI + t + 256*r] = z[r].x;
        hstate[(size_t)b1 * DI + t + 256*r] = z[r].y;
    }
    if (hfinal){
        #pragma unroll
        for (int r = 0; r < 8; ++r){
            hfinal[(size_t)b0 * DI + t + 256*r] = z[r].x;
            hfinal[(size_t)b1 * DI + t + 256*r] = z[r].y;
        }
    }
}

// ============================================================================
// Smem Stockham FFT path for setup/conv (verified).
// ============================================================================
template<int DIR>
__device__ __forceinline__ void fft2048_r8(float2* bufA, float2* bufB,
                                           const float2* __restrict__ W, int tid)
{
    float2* X = bufA;
    float2* Y = bufB;
    #pragma unroll
    for (int st = 0; st < 3; ++st){
        const int s  = (st == 0) ? 1 : (st == 1) ? 8 : 64;
        const int ps = tid & ~(s - 1);
        const int q  = tid & (s - 1);
        float2 a[8], o[8];
        #pragma unroll
        for (int r = 0; r < 8; ++r) a[r] = X[sidx(tid + 256 * r)];
        dft8<DIR>(a, o);
        const int ob = q + 8 * ps;
        Y[sidx(ob)] = o[0];
        #pragma unroll
        for (int r = 1; r < 8; ++r){
            float2 w = W[r * ps];
            if (DIR) w.y = -w.y;
            Y[sidx(ob + s * r)] = cmulf(w, o[r]);
        }
        __syncthreads();
        float2* tmp = X; X = Y; Y = tmp;
    }
    #pragma unroll
    for (int h = 0; h < 2; ++h){
        const int j = tid + 256 * h;
        float2 a = X[sidx(j)];
        float2 b = X[sidx(j + 512)];
        float2 c = X[sidx(j + 1024)];
        float2 d = X[sidx(j + 1536)];
        float2 apc = cadd(a, c), amc = csub(a, c);
        float2 bpd = cadd(b, d), bmd = csub(b, d);
        float2 ib  = make_float2(-bmd.y, bmd.x);
        float2 x1, x3;
        if (DIR == 0){ x1 = csub(amc, ib); x3 = cadd(amc, ib); }
        else         { x1 = cadd(amc, ib); x3 = csub(amc, ib); }
        Y[sidx(j)]        = cadd(apc, bpd);
        Y[sidx(j + 512)]  = x1;
        Y[sidx(j + 1024)] = csub(apc, bpd);
        Y[sidx(j + 1536)] = x3;
    }
    __syncthreads();
}

__global__ void twiddle_kernel(float2* __restrict__ W)
{
    int k = blockIdx.x * blockDim.x + threadIdx.x;
    if (k < NFFT){
        double a = -2.0 * M_PI * (double)k / (double)NFFT;
        W[k] = make_float2((float)cos(a), (float)sin(a));
    }
}

__global__ void spectra_kernel(const float* __restrict__ ch, const float* __restrict__ cx,
                               const float2* __restrict__ Wg,
                               float2* __restrict__ FCh, float2* __restrict__ FCx)
{
    extern __shared__ float2 sm[];
    float2* bufA = sm;
    float2* bufB = sm + 2048;
    float2* Wc   = sm + 4096;
    const int tid = threadIdx.x;
    for (int k = tid; k < NFFT; k += 256){
        Wc[k] = Wg[k];
        bufA[sidx(k)] = make_float2(ch[k], cx[k]);
    }
    __syncthreads();
    fft2048_r8<0>(bufA, bufB, Wc, tid);
    const float inv = 1.0f / (float)NFFT;
    for (int k = tid; k < NFFT; k += 256){
        float2 A  = bufA[sidx(k)];
        float2 Zm = bufA[sidx((NFFT - k) & (NFFT - 1))];
        float2 Bc = make_float2(Zm.x, -Zm.y);
        float2 FH = make_float2(0.5f * (A.x + Bc.x), 0.5f * (A.y + Bc.y));
        float2 Dd = make_float2(A.x - Bc.x, A.y - Bc.y);
        float2 FX = make_float2(0.5f * Dd.y, -0.5f * Dd.x);
        FCh[k] = make_float2(FH.x * inv, FH.y * inv);
        FCx[k] = make_float2(FX.x * inv, FX.y * inv);
    }
}

// conv_pre chunked over T: CTAs cover rows (b, t) with t in [toff, toff+THALF)
__global__ void conv_pre_kernel(const __nv_bfloat16* __restrict__ xph,
                                const __nv_bfloat16* __restrict__ xpl,
                                const float* __restrict__ bvec,
                                const float2* __restrict__ Wg, const float2* __restrict__ FCg,
                                float* __restrict__ pre, int toff)
{
    extern __shared__ float2 sm[];
    float2* bufA = sm;
    float2* bufB = sm + 2048;
    float2* Wc   = sm + 4096;
    float2* FC   = sm + 6144;
    const int tid = threadIdx.x;
    const int bid = blockIdx.x;                  // [0, 2048)
    const size_t r0 = (size_t)(bid >> 8) * T_SZ + (size_t)(bid & 255) * 2 + toff;
    const __nv_bfloat16* h0p = xph + r0 * DI;
    const __nv_bfloat16* l0p = xpl + r0 * DI;
    for (int k = tid; k < NFFT; k += 256){
        Wc[k] = Wg[k];
        FC[k] = FCg[k];
        float v0 = __bfloat162float(h0p[k]) + __bfloat162float(l0p[k]);
        float v1 = __bfloat162float(h0p[DI + k]) + __bfloat162float(l0p[DI + k]);
        bufA[sidx(k)] = make_float2(v0, v1);
    }
    __syncthreads();
    fft2048_r8<0>(bufA, bufB, Wc, tid);
    for (int k = tid; k < NFFT; k += 256){
        int si = sidx(k);
        bufA[si] = cmulf(bufA[si], FC[k]);
    }
    __syncthreads();
    fft2048_r8<1>(bufA, bufB, Wc, tid);
    float* p0 = pre + r0 * DI;
    float* p1 = p0 + DI;
    for (int k = tid; k < NFFT; k += 256){
        const float bb = bvec[k];
        float2 v = bufA[sidx(k)];
        p0[k] = v.x + bb;
        p1[k] = v.y + bb;
    }
}

// ============================================================================
// Elementwise split helpers
// ============================================================================
__global__ void split_kernel(const float* __restrict__ s,
                             __nv_bfloat16* __restrict__ hi, __nv_bfloat16* __restrict__ lo,
                             int n4)
{
    int i = blockIdx.x * blockDim.x + threadIdx.x;
    if (i >= n4) return;
    float4 v = ((const float4*)s)[i];
    __nv_bfloat16 h0 = __float2bfloat16(v.x), h1 = __float2bfloat16(v.y);
    __nv_bfloat16 h2 = __float2bfloat16(v.z), h3 = __float2bfloat16(v.w);
    __nv_bfloat16 l0 = __float2bfloat16(v.x - __bfloat162float(h0));
    __nv_bfloat16 l1 = __float2bfloat16(v.y - __bfloat162float(h1));
    __nv_bfloat16 l2 = __float2bfloat16(v.z - __bfloat162float(h2));
    __nv_bfloat16 l3 = __float2bfloat16(v.w - __bfloat162float(h3));
    ((__nv_bfloat162*)hi)[i * 2]     = __nv_bfloat162(h0, h1);
    ((__nv_bfloat162*)hi)[i * 2 + 1] = __nv_bfloat162(h2, h3);
    ((__nv_bfloat162*)lo)[i * 2]     = __nv_bfloat162(l0, l1);
    ((__nv_bfloat162*)lo)[i * 2 + 1] = __nv_bfloat162(l2, l3);
}

// cell = hseq * gate, split to bf16, chunked over T.
__global__ void cell_split_kernel(const float* __restrict__ a, const float* __restrict__ g,
                                  __nv_bfloat16* __restrict__ hi, __nv_bfloat16* __restrict__ lo,
                                  int toff)
{
    const int gg = blockIdx.x * blockDim.x + threadIdx.x;
    const int rloc = gg >> 9;
    const int c    = gg & 511;
    const size_t row = (size_t)(rloc >> 9) * T_SZ + (size_t)(rloc & 511) + toff;
    const size_t i = row * (DI / 4) + c;
    float4 va = ((const float4*)a)[i];
    float4 vg = ((const float4*)g)[i];
    float4 v = make_float4(va.x * vg.x, va.y * vg.y, va.z * vg.z, va.w * vg.w);
    __nv_bfloat16 h0 = __float2bfloat16(v.x), h1 = __float2bfloat16(v.y);
    __nv_bfloat16 h2 = __float2bfloat16(v.z), h3 = __float2bfloat16(v.w);
    __nv_bfloat16 l0 = __float2bfloat16(v.x - __bfloat162float(h0));
    __nv_bfloat16 l1 = __float2bfloat16(v.y - __bfloat162float(h1));
    __nv_bfloat16 l2 = __float2bfloat16(v.z - __bfloat162float(h2));
    __nv_bfloat16 l3 = __float2bfloat16(v.w - __bfloat162float(h3));
    ((__nv_bfloat162*)hi)[i * 2]     = __nv_bfloat162(h0, h1);
    ((__nv_bfloat162*)hi)[i * 2 + 1] = __nv_bfloat162(h2, h3);
    ((__nv_bfloat162*)lo)[i * 2]     = __nv_bfloat162(l0, l1);
    ((__nv_bfloat162*)lo)[i * 2 + 1] = __nv_bfloat162(l2, l3);
}

// ============================================================================
// mma.sync bf16 split GEMM with T-chunked row mapping:
// bm = (by>>2)*1024 + (by&3)*128 + moff   (grid.y = 32 per chunk)
// ============================================================================
#define KCH 64
#define STAGE_BYTES 65536

template<int EPI>
__global__ void __launch_bounds__(256, 1) gemm_mma(
    const __nv_bfloat16* __restrict__ Ahi, const __nv_bfloat16* __restrict__ Alo,
    const __nv_bfloat16* __restrict__ Bhi, const __nv_bfloat16* __restrict__ Blo,
    const float* __restrict__ bias,
    float* __restrict__ Cf,
    __nv_bfloat16* __restrict__ Chi, __nv_bfloat16* __restrict__ Clo,
    int K, int N, int moff)
{
    extern __shared__ char dsm[];
    const int tid  = threadIdx.x;
    const int wid  = tid >> 5;
    const int lane = tid & 31;
    const int wm = wid & 1;
    const int wn = wid >> 1;
    const int by = blockIdx.y;
    const int bm = (by >> 2) * 1024 + (by & 3) * 128 + moff;
    const int bn = blockIdx.x * 128;

    const uint32_t sbase = (smem_u32(dsm) + 1023u) & ~1023u;

    float acc[4][4][4];
    #pragma unroll
    for (int i = 0; i < 4; ++i)
        #pragma unroll
        for (int j = 0; j < 4; ++j)
            #pragma unroll
            for (int e = 0; e < 4; ++e) acc[i][j][e] = 0.0f;

    const int lrow = tid >> 3;
    const int lc   = tid & 7;
    auto load_stage = [&](int s, int k0){
        const uint32_t tA_hi = sbase + s * STAGE_BYTES;
        const uint32_t tA_lo = tA_hi + 16384;
        const uint32_t tB_hi = tA_hi + 32768;
        const uint32_t tB_lo = tA_hi + 49152;
        #pragma unroll
        for (int p = 0; p < 4; ++p){
            const int row = lrow + p * 32;
            const uint32_t sw = SWZ128((uint32_t)(row * 128 + lc * 16));
            const size_t ga = (size_t)(bm + row) * K + k0 + lc * 8;
            const size_t gb = (size_t)(bn + row) * K + k0 + lc * 8;
            cpasync16(tA_hi + sw, Ahi + ga);
            cpasync16(tA_lo + sw, Alo + ga);
            cpasync16(tB_hi + sw, Bhi + gb);
            cpasync16(tB_lo + sw, Blo + gb);
        }
        CP_COMMIT();
    };

    const int NIT = K / KCH;
    load_stage(0, 0);

    const int lr8  = (lane & 7) + ((lane & 8) ? 8 : 0);
    const int lk16 = (lane & 16) ? 16 : 0;

    for (int it = 0; it < NIT; ++it){
        if (it + 1 < NIT){
            load_stage((it + 1) & 1, (it + 1) * KCH);
            CP_WAIT(1);
        } else {
            CP_WAIT(0);
        }
        __syncthreads();

        const uint32_t st   = sbase + (it & 1) * STAGE_BYTES;
        const uint32_t sAhi = st;
        const uint32_t sAlo = st + 16384;
        const uint32_t sBhi = st + 32768;
        const uint32_t sBlo = st + 49152;

        #pragma unroll
        for (int ks = 0; ks < 4; ++ks){
            uint32_t ah[4][4], al[4][4], bh[2][4], bl[2][4];
            #pragma unroll
            for (int i = 0; i < 4; ++i){
                const int r = wm * 64 + i * 16 + lr8;
                const uint32_t off = SWZ128((uint32_t)(r * 128 + ks * 32 + lk16));
                ldsm_x4(ah[i], sAhi + off);
                ldsm_x4(al[i], sAlo + off);
            }
            #pragma unroll
            for (int np = 0; np < 2; ++np){
                const int r = wn * 32 + np * 16 + lr8;
                const uint32_t off = SWZ128((uint32_t)(r * 128 + ks * 32 + lk16));
                ldsm_x4(bh[np], sBhi + off);
                ldsm_x4(bl[np], sBlo + off);
            }
            #pragma unroll
            for (int i = 0; i < 4; ++i){
                #pragma unroll
                for (int j = 0; j < 4; ++j){
                    const int np = j >> 1, sl = j & 1;
                    mma16816(acc[i][j], ah[i], bh[np][sl], bh[np][sl + 2]);
                    mma16816(acc[i][j], al[i], bh[np][sl], bh[np][sl + 2]);
                    mma16816(acc[i][j], ah[i], bl[np][sl], bl[np][sl + 2]);
                }
            }
        }
        __syncthreads();
    }

    const int qr = lane >> 2;
    const int qc = (lane & 3) * 2;
    #pragma unroll
    for (int i = 0; i < 4; ++i){
        #pragma unroll
        for (int j = 0; j < 4; ++j){
            const int col = bn + wn * 32 + j * 8 + qc;
            #pragma unroll
            for (int h = 0; h < 2; ++h){
                const int row = bm + wm * 64 + i * 16 + qr + h * 8;
                float v0 = acc[i][j][h * 2];
                float v1 = acc[i][j][h * 2 + 1];
                if (EPI == 1){
                    v0 += bias[col];
                    v1 += bias[col + 1];
                    v0 = v0 / (1.0f + expf(-v0));
                    v1 = v1 / (1.0f + expf(-v1));
                    *(float2*)(Cf + (size_t)row * N + col) = make_float2(v0, v1);
                } else if (EPI == 2){
                    __nv_bfloat16 h0 = __float2bfloat16(v0);
                    __nv_bfloat16 h1 = __float2bfloat16(v1);
                    __nv_bfloat16 l0 = __float2bfloat16(v0 - __bfloat162float(h0));
                    __nv_bfloat16 l1 = __float2bfloat16(v1 - __bfloat162float(h1));
                    *(__nv_bfloat162*)(Chi + (size_t)row * N + col) = __nv_bfloat162(h0, h1);
                    *(__nv_bfloat162*)(Clo + (size_t)row * N + col) = __nv_bfloat162(l0, l1);
                } else {
                    *(float2*)(Cf + (size_t)row * N + col) = make_float2(v0, v1);
                }
            }
        }
    }
}

// ============================================================================
// Launch — pipelined T-halves across 3 streams. Streams/events are created
// ONCE (first call = correctness run, before the pre-capture baseline) and
// cached, so the capture call allocates nothing and teardown returns to
// baseline exactly.
// ============================================================================
extern "C" void kernel_launch(void* const* d_in, const int* in_sizes, int n_in,
                              void* d_out, int out_size)
{
    (void)in_sizes; (void)n_in;
    const float* x    = (const float*)d_in[0];
    const float* h0   = (const float*)d_in[1];
    const float* inw  = (const float*)d_in[2];
    const float* outw = (const float*)d_in[3];
    const float* ch   = (const float*)d_in[4];
    const float* cx   = (const float*)d_in[5];
    const float* bv   = (const float*)d_in[6];
    const float* wg   = (const float*)d_in[7];
    const float* bg   = (const float*)d_in[8];

    float* out = (float*)d_out;
    float* hfinal = (out_size >= (int)(ROWS * DIMX + B_SZ * DI))
                        ? out + (size_t)ROWS * DIMX : nullptr;

    float *p_gate, *p_pre, *p_hseq, *p_hstate;
    float2 *p_W, *p_FCh, *p_FCx, *p_FChP;
    __nv_bfloat16 *p_xhi, *p_xlo, *p_xphi, *p_xplo, *p_clhi, *p_cllo;
    __nv_bfloat16 *p_iwhi, *p_iwlo, *p_wghi, *p_wglo, *p_owhi, *p_owlo;
    cudaGetSymbolAddress((void**)&p_gate,   g_gate);
    cudaGetSymbolAddress((void**)&p_pre,    g_pre);
    cudaGetSymbolAddress((void**)&p_hseq,   g_hseq);
    cudaGetSymbolAddress((void**)&p_hstate, g_hstate);
    cudaGetSymbolAddress((void**)&p_W,     g_W);
    cudaGetSymbolAddress((void**)&p_FCh,   g_FCh);
    cudaGetSymbolAddress((void**)&p_FCx,   g_FCx);
    cudaGetSymbolAddress((void**)&p_FChP,  g_FChP);
    cudaGetSymbolAddress((void**)&p_xhi,   g_xhi);
    cudaGetSymbolAddress((void**)&p_xlo,   g_xlo);
    cudaGetSymbolAddress((void**)&p_xphi,  g_xphi);
    cudaGetSymbolAddress((void**)&p_xplo,  g_xplo);
    cudaGetSymbolAddress((void**)&p_clhi,  g_clhi);
    cudaGetSymbolAddress((void**)&p_cllo,  g_cllo);
    cudaGetSymbolAddress((void**)&p_iwhi,  g_iwhi);
    cudaGetSymbolAddress((void**)&p_iwlo,  g_iwlo);
    cudaGetSymbolAddress((void**)&p_wghi,  g_wghi);
    cudaGetSymbolAddress((void**)&p_wglo,  g_wglo);
    cudaGetSymbolAddress((void**)&p_owhi,  g_owhi);
    cudaGetSymbolAddress((void**)&p_owlo,  g_owlo);

    cudaFuncSetAttribute(conv_pre_kernel, cudaFuncAttributeMaxDynamicSharedMemorySize, 65536);
    cudaFuncSetAttribute(spectra_kernel,  cudaFuncAttributeMaxDynamicSharedMemorySize, 49152);
    const int GSM = 2 * STAGE_BYTES + 1024;
    cudaFuncSetAttribute(gemm_mma<0>, cudaFuncAttributeMaxDynamicSharedMemorySize, GSM);
    cudaFuncSetAttribute(gemm_mma<1>, cudaFuncAttributeMaxDynamicSharedMemorySize, GSM);
    cudaFuncSetAttribute(gemm_mma<2>, cudaFuncAttributeMaxDynamicSharedMemorySize, GSM);

    // ---- cached streams/events (created once, before capture baseline) ----
    static cudaStream_t s2 = nullptr, s3 = nullptr;
    static cudaEvent_t ev0, evSplit, evG1c1, evC2, evG2c1, evG2c2, evS1, evO1;
    if (s2 == nullptr){
        cudaStreamCreateWithFlags(&s2, cudaStreamNonBlocking);
        cudaStreamCreateWithFlags(&s3, cudaStreamNonBlocking);
        cudaEventCreateWithFlags(&ev0,    cudaEventDisableTiming);
        cudaEventCreateWithFlags(&evSplit,cudaEventDisableTiming);
        cudaEventCreateWithFlags(&evG1c1, cudaEventDisableTiming);
        cudaEventCreateWithFlags(&evC2,   cudaEventDisableTiming);
        cudaEventCreateWithFlags(&evG2c1, cudaEventDisableTiming);
        cudaEventCreateWithFlags(&evG2c2, cudaEventDisableTiming);
        cudaEventCreateWithFlags(&evS1,   cudaEventDisableTiming);
        cudaEventCreateWithFlags(&evO1,   cudaEventDisableTiming);
    }

    const dim3 gThr(256);

    // ---- main stream: setup + GEMM1 chunk1 path ----
    twiddle_kernel<<<4, 512>>>(p_W);
    spectra_kernel<<<1, 256, 49152>>>(ch, cx, p_W, p_FCh, p_FCx);
    prep_fchp_kernel<<<1, 256>>>(ch, p_FChP);
    cudaEventRecord(ev0, 0);

    split_kernel<<<ROWS * DIMX / 4 / 256, gThr>>>(x,   p_xhi,  p_xlo,  ROWS * DIMX / 4);
    split_kernel<<<DI * DIMX   / 4 / 256, gThr>>>(inw, p_iwhi, p_iwlo, DI * DIMX / 4);
    cudaEventRecord(evSplit, 0);

    // side stream s2: weight splits for GEMM2/GEMM3 (independent)
    cudaStreamWaitEvent(s2, ev0, 0);
    split_kernel<<<DI * DI   / 4 / 256, gThr, 0, s2>>>(wg,   p_wghi, p_wglo, DI * DI / 4);
    split_kernel<<<DIMX * DI / 4 / 256, gThr, 0, s2>>>(outw, p_owhi, p_owlo, DIMX * DI / 4);

    // GEMM1 chunk1 (rows t<512)  -> bf16 split x_proj
    gemm_mma<2><<<dim3(DI / 128, 32), 256, GSM>>>(
        p_xhi, p_xlo, p_iwhi, p_iwlo, nullptr, nullptr, p_xphi, p_xplo, DIMX, DI, 0);
    cudaEventRecord(evG1c1, 0);
    conv_pre_kernel<<<2048, 256, 65536>>>(p_xphi, p_xplo, bv, p_W, p_FCx, p_pre, 0);

    // s2: GEMM1 chunk2 + conv chunk2, then GEMM2 (chunked)
    cudaStreamWaitEvent(s2, evSplit, 0);
    gemm_mma<2><<<dim3(DI / 128, 32), 256, GSM, s2>>>(
        p_xhi, p_xlo, p_iwhi, p_iwlo, nullptr, nullptr, p_xphi, p_xplo, DIMX, DI, THALF);
    conv_pre_kernel<<<2048, 256, 65536, s2>>>(p_xphi, p_xplo, bv, p_W, p_FCx, p_pre, THALF);
    cudaEventRecord(evC2, s2);
    cudaStreamWaitEvent(s2, evG1c1, 0);
    gemm_mma<1><<<dim3(DI / 128, 32), 256, GSM, s2>>>(
        p_xphi, p_xplo, p_wghi, p_wglo, bg, p_gate, nullptr, nullptr, DI, DI, 0);
    cudaEventRecord(evG2c1, s2);
    gemm_mma<1><<<dim3(DI / 128, 32), 256, GSM, s2>>>(
        p_xphi, p_xplo, p_wghi, p_wglo, bg, p_gate, nullptr, nullptr, DI, DI, THALF);
    cudaEventRecord(evG2c2, s2);

    // main: scan part 1 (t 0..512)
    scan_part_kernel<<<4, 256>>>(p_pre, p_hseq, p_FChP, h0, p_hstate, nullptr, 0, THALF);
    cudaEventRecord(evS1, 0);

    // main: scan part 2 (t 512..1024), needs conv chunk2
    cudaStreamWaitEvent(0, evC2, 0);
    scan_part_kernel<<<4, 256>>>(p_pre, p_hseq, p_FChP, p_hstate, p_hstate, hfinal, THALF, T_SZ);

    // s3: cell_split + GEMM3 chunk1 concurrent with scan part 2
    cudaStreamWaitEvent(s3, evS1, 0);
    cudaStreamWaitEvent(s3, evG2c1, 0);
    cell_split_kernel<<<8192, 256, 0, s3>>>(p_hseq, p_gate, p_clhi, p_cllo, 0);
    gemm_mma<0><<<dim3(DIMX / 128, 32), 256, GSM, s3>>>(
        p_clhi, p_cllo, p_owhi, p_owlo, nullptr, out, nullptr, nullptr, DI, DIMX, 0);
    cudaEventRecord(evO1, s3);

    // main: chunk2 epilogue after scan part 2
    cudaStreamWaitEvent(0, evG2c2, 0);
    cell_split_kernel<<<8192, 256>>>(p_hseq, p_gate, p_clhi, p_cllo, THALF);
    gemm_mma<0><<<dim3(DIMX / 128, 32), 256, GSM>>>(
        p_clhi, p_cllo, p_owhi, p_owlo, nullptr, out, nullptr, nullptr, DI, DIMX, THALF);

    // join s3
    cudaStreamWaitEvent(0, evO1, 0);
}

// round 9
// speedup vs baseline: 1.9943x; 1.0591x over previous
#include <cuda_runtime.h>
#include <cuda_bf16.h>
#include <math.h>
#include <stdint.h>

#ifndef M_PI
#define M_PI 3.14159265358979323846
#endif

// Problem constants
#define B_SZ   8
#define T_SZ   1024
#define DIMX   1024
#define DI     2048
#define NFFT   2048
#define ROWS   (B_SZ * T_SZ)   // 8192
#define TQ     256             // T quarter

// ----- device scratch -----
__device__ float  g_gate [(size_t)ROWS * DI];
__device__ float  g_pre  [(size_t)ROWS * DI];
__device__ float  g_hseq [(size_t)ROWS * DI];
__device__ float  g_hstate[(size_t)B_SZ * DI];
__device__ float2 g_W   [NFFT];
__device__ float2 g_FCh [NFFT];
__device__ float2 g_FCx [NFFT];
__device__ float2 g_FChP[NFFT];

// bf16 split operands
__device__ __nv_bfloat16 g_xhi [(size_t)ROWS * DIMX];
__device__ __nv_bfloat16 g_xlo [(size_t)ROWS * DIMX];
__device__ __nv_bfloat16 g_xphi[(size_t)ROWS * DI];
__device__ __nv_bfloat16 g_xplo[(size_t)ROWS * DI];
__device__ __nv_bfloat16 g_clhi[(size_t)ROWS * DI];
__device__ __nv_bfloat16 g_cllo[(size_t)ROWS * DI];
__device__ __nv_bfloat16 g_iwhi[(size_t)DI * DIMX];
__device__ __nv_bfloat16 g_iwlo[(size_t)DI * DIMX];
__device__ __nv_bfloat16 g_wghi[(size_t)DI * DI];
__device__ __nv_bfloat16 g_wglo[(size_t)DI * DI];
__device__ __nv_bfloat16 g_owhi[(size_t)DIMX * DI];
__device__ __nv_bfloat16 g_owlo[(size_t)DIMX * DI];

__device__ __forceinline__ float2 cmulf(float2 a, float2 b){
    return make_float2(fmaf(a.x, b.x, -a.y * b.y), fmaf(a.x, b.y, a.y * b.x));
}
__device__ __forceinline__ float2 cadd(float2 a, float2 b){ return make_float2(a.x+b.x, a.y+b.y); }
__device__ __forceinline__ float2 csub(float2 a, float2 b){ return make_float2(a.x-b.x, a.y-b.y); }

__device__ __forceinline__ float tanh_fast(float x){
    float ax = fabsf(x);
    float e  = __expf(-2.0f * ax);
    float r  = __fdividef(1.0f - e, 1.0f + e);
    return copysignf(r, x);
}

__device__ __forceinline__ int sidx(int i){ return i ^ ((i >> 4) & 15); }

// ============================================================================
// PTX helpers
// ============================================================================
__device__ __forceinline__ uint32_t smem_u32(const void* p){
    uint32_t a;
    asm("{ .reg .u64 t; cvta.to.shared.u64 t, %1; cvt.u32.u64 %0, t; }" : "=r"(a) : "l"(p));
    return a;
}
__device__ __forceinline__ void cpasync16(uint32_t dst, const void* src){
    asm volatile("cp.async.cg.shared.global [%0], [%1], 16;" :: "r"(dst), "l"(src));
}
#define CP_COMMIT()  asm volatile("cp.async.commit_group;" ::: "memory")
#define CP_WAIT(n)   asm volatile("cp.async.wait_group %0;" :: "n"(n) : "memory")

__device__ __forceinline__ void ldsm_x4(uint32_t* r, uint32_t addr){
    asm volatile("ldmatrix.sync.aligned.m8n8.x4.shared.b16 {%0,%1,%2,%3}, [%4];"
        : "=r"(r[0]), "=r"(r[1]), "=r"(r[2]), "=r"(r[3]) : "r"(addr));
}
__device__ __forceinline__ void mma16816(float* c, const uint32_t* a,
                                         uint32_t b0, uint32_t b1){
    asm volatile("mma.sync.aligned.m16n8k16.row.col.f32.bf16.bf16.f32 "
        "{%0,%1,%2,%3}, {%4,%5,%6,%7}, {%8,%9}, {%0,%1,%2,%3};"
        : "+f"(c[0]), "+f"(c[1]), "+f"(c[2]), "+f"(c[3])
        : "r"(a[0]), "r"(a[1]), "r"(a[2]), "r"(a[3]), "r"(b0), "r"(b1));
}

#define SWZ128(o) ((o) ^ (((o) >> 3) & 0x70))

// ============================================================================
// Radix-8 DFT core
// ============================================================================
template<int DIR>
__device__ __forceinline__ void dft8(const float2* a, float2* X)
{
    const float RS = 0.70710678118654752f;
    float2 s0 = cadd(a[0], a[4]), s1 = csub(a[0], a[4]);
    float2 s2 = cadd(a[2], a[6]), s3 = csub(a[2], a[6]);
    float2 s3i = DIR ? make_float2(-s3.y, s3.x) : make_float2(s3.y, -s3.x);
    float2 E0 = cadd(s0, s2), E2 = csub(s0, s2);
    float2 E1 = cadd(s1, s3i), E3 = csub(s1, s3i);
    float2 u0 = cadd(a[1], a[5]), u1 = csub(a[1], a[5]);
    float2 u2 = cadd(a[3], a[7]), u3 = csub(a[3], a[7]);
    float2 u3i = DIR ? make_float2(-u3.y, u3.x) : make_float2(u3.y, -u3.x);
    float2 O0 = cadd(u0, u2), O2 = csub(u0, u2);
    float2 O1 = cadd(u1, u3i), O3 = csub(u1, u3i);
    float2 t1, t2, t3;
    if (DIR == 0){
        t1 = make_float2((O1.x + O1.y) * RS, (O1.y - O1.x) * RS);
        t2 = make_float2(O2.y, -O2.x);
        t3 = make_float2((O3.y - O3.x) * RS, -(O3.x + O3.y) * RS);
    } else {
        t1 = make_float2((O1.x - O1.y) * RS, (O1.x + O1.y) * RS);
        t2 = make_float2(-O2.y, O2.x);
        t3 = make_float2(-(O3.x + O3.y) * RS, (O3.x - O3.y) * RS);
    }
    X[0] = cadd(E0, O0);  X[4] = csub(E0, O0);
    X[1] = cadd(E1, t1);  X[5] = csub(E1, t1);
    X[2] = cadd(E2, t2);  X[6] = csub(E2, t2);
    X[3] = cadd(E3, t3);  X[7] = csub(E3, t3);
}

// ============================================================================
// Shuffle-based 2048-pt transform T = P ∘ DFT2048. Double-buffered exchange.
// ============================================================================
struct TW {
    float2 f1[7];
    float2 f2[7];
    float2 lt[4];
};

__device__ __forceinline__ void make_tw(TW& tw, int t, int l){
    #pragma unroll
    for (int r = 1; r < 8; ++r){
        double a = -2.0 * M_PI * (double)((t * r) & 2047) / 2048.0;
        double s, c; sincos(a, &s, &c);
        tw.f1[r-1] = make_float2((float)c, (float)s);
    }
    #pragma unroll
    for (int c2 = 1; c2 < 8; ++c2){
        double a = -2.0 * M_PI * (double)((l * c2) & 255) / 256.0;
        double s, c; sincos(a, &s, &c);
        tw.f2[c2-1] = make_float2((float)c, (float)s);
    }
    #pragma unroll
    for (int s2 = 0; s2 < 4; ++s2){
        int h = 16 >> s2;
        double a = -M_PI * (double)(l & (h - 1)) / (double)h;
        double s, c; sincos(a, &s, &c);
        tw.lt[s2] = make_float2((float)c, (float)s);
    }
}

__device__ __forceinline__ float2 shfl_xor_c(float2 v, int m){
    float2 r;
    r.x = __shfl_xor_sync(0xffffffffu, v.x, m);
    r.y = __shfl_xor_sync(0xffffffffu, v.y, m);
    return r;
}

__device__ __forceinline__ void fwd2048(const float2* z, float2* spec, float2* exF,
                                        const TW& tw, int l, int w)
{
    float2 y[8];
    dft8<0>(z, y);
    #pragma unroll
    for (int r = 1; r < 8; ++r) y[r] = cmulf(y[r], tw.f1[r-1]);
    const int xr = (l >> 1) & 7;
    #pragma unroll
    for (int r = 0; r < 8; ++r) exF[r*256 + l*8 + (w ^ xr)] = y[r];
    __syncthreads();
    float2 u[8];
    const int base = w*256 + l*8;
    #pragma unroll
    for (int j = 0; j < 8; ++j) u[j] = exF[base + (j ^ xr)];
    dft8<0>(u, spec);
    #pragma unroll
    for (int c = 1; c < 8; ++c) spec[c] = cmulf(spec[c], tw.f2[c-1]);
    #pragma unroll
    for (int c = 0; c < 8; ++c){
        float2 v = spec[c];
        #pragma unroll
        for (int s = 0; s < 4; ++s){
            const int h = 16 >> s;
            float2 p = shfl_xor_c(v, h);
            if (l & h) v = cmulf(csub(p, v), tw.lt[s]);
            else       v = cadd(v, p);
        }
        {   float2 p = shfl_xor_c(v, 1);
            v = (l & 1) ? csub(p, v) : cadd(v, p); }
        spec[c] = v;
    }
}

__device__ __forceinline__ void inv2048(float2* spec, float2* z, float2* exI,
                                        const TW& tw, int l, int w)
{
    #pragma unroll
    for (int c = 0; c < 8; ++c){
        float2 v = spec[c];
        {   float2 p = shfl_xor_c(v, 1);
            v = (l & 1) ? csub(p, v) : cadd(v, p); }
        #pragma unroll
        for (int s = 3; s >= 0; --s){
            const int h = 16 >> s;
            float2 wc = tw.lt[s]; wc.y = -wc.y;
            if (l & h) v = cmulf(v, wc);
            float2 p = shfl_xor_c(v, h);
            v = (l & h) ? csub(p, v) : cadd(v, p);
        }
        spec[c] = v;
    }
    #pragma unroll
    for (int c = 1; c < 8; ++c){
        float2 wc = tw.f2[c-1]; wc.y = -wc.y;
        spec[c] = cmulf(spec[c], wc);
    }
    float2 uu[8];
    dft8<1>(spec, uu);
    const int xr = (l >> 1) & 7;
    const int base = w*256 + l*8;
    #pragma unroll
    for (int j = 0; j < 8; ++j) exI[base + (j ^ xr)] = uu[j];
    __syncthreads();
    float2 y[8];
    #pragma unroll
    for (int r = 0; r < 8; ++r) y[r] = exI[r*256 + l*8 + (w ^ xr)];
    #pragma unroll
    for (int r = 1; r < 8; ++r){
        float2 wc = tw.f1[r-1]; wc.y = -wc.y;
        y[r] = cmulf(y[r], wc);
    }
    dft8<1>(y, z);
}

// prep: FChP = T(c_h)/2048 in the scan's permuted layout
__global__ void prep_fchp_kernel(const float* __restrict__ ch, float2* __restrict__ FChP)
{
    __shared__ float2 ex[2048];
    const int t = threadIdx.x, l = t & 31, w = t >> 5;
    TW tw; make_tw(tw, t, l);
    float2 z[8], spec[8];
    #pragma unroll
    for (int r = 0; r < 8; ++r)
        z[r] = make_float2(ch[t + 256*r] * (1.0f/2048.0f), 0.0f);
    fwd2048(z, spec, ex, tw, l, w);
    #pragma unroll
    for (int c = 0; c < 8; ++c) FChP[t*8 + c] = spec[c];
}

// ============================================================================
// Scan part kernel: steps [t0,t1). 4 CTAs, 256 threads, state via hin/hstate.
// ============================================================================
__global__ void __launch_bounds__(256, 1) scan_part_kernel(
    const float* __restrict__ pre, float* __restrict__ hseq,
    const float2* __restrict__ FChP,
    const float* __restrict__ hin, float* __restrict__ hstate,
    float* __restrict__ hfinal, int t0, int t1)
{
    __shared__ float2 exF[2048];
    __shared__ float2 exI[2048];
    const int t = threadIdx.x, l = t & 31, w = t >> 5;
    const int b0 = blockIdx.x * 2, b1 = b0 + 1;
    TW tw; make_tw(tw, t, l);
    float2 fc[8];
    #pragma unroll
    for (int c = 0; c < 8; ++c) fc[c] = FChP[t*8 + c];
    float2 z[8];
    #pragma unroll
    for (int r = 0; r < 8; ++r)
        z[r] = make_float2(hin[(size_t)b0 * DI + t + 256*r],
                           hin[(size_t)b1 * DI + t + 256*r]);

    const float* pre0 = pre  + (size_t)b0 * T_SZ * DI;
    const float* pre1 = pre  + (size_t)b1 * T_SZ * DI;
    float*       hs0  = hseq + (size_t)b0 * T_SZ * DI;
    float*       hs1  = hseq + (size_t)b1 * T_SZ * DI;

    for (int ts = t0; ts < t1; ++ts){
        const size_t off = (size_t)ts * DI;
        float pr0[8], pr1[8];
        #pragma unroll
        for (int r = 0; r < 8; ++r){
            pr0[r] = pre0[off + t + 256*r];
            pr1[r] = pre1[off + t + 256*r];
        }
        float2 spec[8];
        fwd2048(z, spec, exF, tw, l, w);
        #pragma unroll
        for (int c = 0; c < 8; ++c) spec[c] = cmulf(spec[c], fc[c]);
        inv2048(spec, z, exI, tw, l, w);
        #pragma unroll
        for (int r = 0; r < 8; ++r){
            float hr = tanh_fast(z[r].x + pr0[r]);
            float hi = tanh_fast(z[r].y + pr1[r]);
            hs0[off + t + 256*r] = hr;
            hs1[off + t + 256*r] = hi;
            z[r] = make_float2(hr, hi);
        }
    }
    #pragma unroll
    for (int r = 0; r < 8; ++r){
        hstate[(size_t)b0 * DI + t + 256*r] = z[r].x;
        hstate[(size_t)b1 * DI + t + 256*r] = z[r].y;
    }
    if (hfinal){
        #pragma unroll
        for (int r = 0; r < 8; ++r){
            hfinal[(size_t)b0 * DI + t + 256*r] = z[r].x;
            hfinal[(size_t)b1 * DI + t + 256*r] = z[r].y;
        }
    }
}

// ============================================================================
// Smem Stockham FFT path for setup/conv (verified).
// ============================================================================
template<int DIR>
__device__ __forceinline__ void fft2048_r8(float2* bufA, float2* bufB,
                                           const float2* __restrict__ W, int tid)
{
    float2* X = bufA;
    float2* Y = bufB;
    #pragma unroll
    for (int st = 0; st < 3; ++st){
        const int s  = (st == 0) ? 1 : (st == 1) ? 8 : 64;
        const int ps = tid & ~(s - 1);
        const int q  = tid & (s - 1);
        float2 a[8], o[8];
        #pragma unroll
        for (int r = 0; r < 8; ++r) a[r] = X[sidx(tid + 256 * r)];
        dft8<DIR>(a, o);
        const int ob = q + 8 * ps;
        Y[sidx(ob)] = o[0];
        #pragma unroll
        for (int r = 1; r < 8; ++r){
            float2 w = W[r * ps];
            if (DIR) w.y = -w.y;
            Y[sidx(ob + s * r)] = cmulf(w, o[r]);
        }
        __syncthreads();
        float2* tmp = X; X = Y; Y = tmp;
    }
    #pragma unroll
    for (int h = 0; h < 2; ++h){
        const int j = tid + 256 * h;
        float2 a = X[sidx(j)];
        float2 b = X[sidx(j + 512)];
        float2 c = X[sidx(j + 1024)];
        float2 d = X[sidx(j + 1536)];
        float2 apc = cadd(a, c), amc = csub(a, c);
        float2 bpd = cadd(b, d), bmd = csub(b, d);
        float2 ib  = make_float2(-bmd.y, bmd.x);
        float2 x1, x3;
        if (DIR == 0){ x1 = csub(amc, ib); x3 = cadd(amc, ib); }
        else         { x1 = cadd(amc, ib); x3 = csub(amc, ib); }
        Y[sidx(j)]        = cadd(apc, bpd);
        Y[sidx(j + 512)]  = x1;
        Y[sidx(j + 1024)] = csub(apc, bpd);
        Y[sidx(j + 1536)] = x3;
    }
    __syncthreads();
}

__global__ void twiddle_kernel(float2* __restrict__ W)
{
    int k = blockIdx.x * blockDim.x + threadIdx.x;
    if (k < NFFT){
        double a = -2.0 * M_PI * (double)k / (double)NFFT;
        W[k] = make_float2((float)cos(a), (float)sin(a));
    }
}

__global__ void spectra_kernel(const float* __restrict__ ch, const float* __restrict__ cx,
                               const float2* __restrict__ Wg,
                               float2* __restrict__ FCh, float2* __restrict__ FCx)
{
    extern __shared__ float2 sm[];
    float2* bufA = sm;
    float2* bufB = sm + 2048;
    float2* Wc   = sm + 4096;
    const int tid = threadIdx.x;
    for (int k = tid; k < NFFT; k += 256){
        Wc[k] = Wg[k];
        bufA[sidx(k)] = make_float2(ch[k], cx[k]);
    }
    __syncthreads();
    fft2048_r8<0>(bufA, bufB, Wc, tid);
    const float inv = 1.0f / (float)NFFT;
    for (int k = tid; k < NFFT; k += 256){
        float2 A  = bufA[sidx(k)];
        float2 Zm = bufA[sidx((NFFT - k) & (NFFT - 1))];
        float2 Bc = make_float2(Zm.x, -Zm.y);
        float2 FH = make_float2(0.5f * (A.x + Bc.x), 0.5f * (A.y + Bc.y));
        float2 Dd = make_float2(A.x - Bc.x, A.y - Bc.y);
        float2 FX = make_float2(0.5f * Dd.y, -0.5f * Dd.x);
        FCh[k] = make_float2(FH.x * inv, FH.y * inv);
        FCx[k] = make_float2(FX.x * inv, FX.y * inv);
    }
}

// conv_pre chunked over T-quarters: 1024 CTAs cover 8 batches x 128 row-pairs
__global__ void conv_pre_kernel(const __nv_bfloat16* __restrict__ xph,
                                const __nv_bfloat16* __restrict__ xpl,
                                const float* __restrict__ bvec,
                                const float2* __restrict__ Wg, const float2* __restrict__ FCg,
                                float* __restrict__ pre, int toff)
{
    extern __shared__ float2 sm[];
    float2* bufA = sm;
    float2* bufB = sm + 2048;
    float2* Wc   = sm + 4096;
    float2* FC   = sm + 6144;
    const int tid = threadIdx.x;
    const int bid = blockIdx.x;                  // [0, 1024)
    const size_t r0 = (size_t)(bid >> 7) * T_SZ + (size_t)(bid & 127) * 2 + toff;
    const __nv_bfloat16* h0p = xph + r0 * DI;
    const __nv_bfloat16* l0p = xpl + r0 * DI;
    for (int k = tid; k < NFFT; k += 256){
        Wc[k] = Wg[k];
        FC[k] = FCg[k];
        float v0 = __bfloat162float(h0p[k]) + __bfloat162float(l0p[k]);
        float v1 = __bfloat162float(h0p[DI + k]) + __bfloat162float(l0p[DI + k]);
        bufA[sidx(k)] = make_float2(v0, v1);
    }
    __syncthreads();
    fft2048_r8<0>(bufA, bufB, Wc, tid);
    for (int k = tid; k < NFFT; k += 256){
        int si = sidx(k);
        bufA[si] = cmulf(bufA[si], FC[k]);
    }
    __syncthreads();
    fft2048_r8<1>(bufA, bufB, Wc, tid);
    float* p0 = pre + r0 * DI;
    float* p1 = p0 + DI;
    for (int k = tid; k < NFFT; k += 256){
        const float bb = bvec[k];
        float2 v = bufA[sidx(k)];
        p0[k] = v.x + bb;
        p1[k] = v.y + bb;
    }
}

// ============================================================================
// Elementwise split helpers
// ============================================================================
__global__ void split_kernel(const float* __restrict__ s,
                             __nv_bfloat16* __restrict__ hi, __nv_bfloat16* __restrict__ lo,
                             int n4)
{
    int i = blockIdx.x * blockDim.x + threadIdx.x;
    if (i >= n4) return;
    float4 v = ((const float4*)s)[i];
    __nv_bfloat16 h0 = __float2bfloat16(v.x), h1 = __float2bfloat16(v.y);
    __nv_bfloat16 h2 = __float2bfloat16(v.z), h3 = __float2bfloat16(v.w);
    __nv_bfloat16 l0 = __float2bfloat16(v.x - __bfloat162float(h0));
    __nv_bfloat16 l1 = __float2bfloat16(v.y - __bfloat162float(h1));
    __nv_bfloat16 l2 = __float2bfloat16(v.z - __bfloat162float(h2));
    __nv_bfloat16 l3 = __float2bfloat16(v.w - __bfloat162float(h3));
    ((__nv_bfloat162*)hi)[i * 2]     = __nv_bfloat162(h0, h1);
    ((__nv_bfloat162*)hi)[i * 2 + 1] = __nv_bfloat162(h2, h3);
    ((__nv_bfloat162*)lo)[i * 2]     = __nv_bfloat162(l0, l1);
    ((__nv_bfloat162*)lo)[i * 2 + 1] = __nv_bfloat162(l2, l3);
}

// cell = hseq * gate, split to bf16, T-quarter chunked. grid 4096 x 256.
__global__ void cell_split_kernel(const float* __restrict__ a, const float* __restrict__ g,
                                  __nv_bfloat16* __restrict__ hi, __nv_bfloat16* __restrict__ lo,
                                  int toff)
{
    const int gg = blockIdx.x * blockDim.x + threadIdx.x;
    const int rloc = gg >> 9;               // 0..2047
    const int c    = gg & 511;              // float4 col
    const size_t row = (size_t)(rloc >> 8) * T_SZ + (size_t)(rloc & 255) + toff;
    const size_t i = row * (DI / 4) + c;
    float4 va = ((const float4*)a)[i];
    float4 vg = ((const float4*)g)[i];
    float4 v = make_float4(va.x * vg.x, va.y * vg.y, va.z * vg.z, va.w * vg.w);
    __nv_bfloat16 h0 = __float2bfloat16(v.x), h1 = __float2bfloat16(v.y);
    __nv_bfloat16 h2 = __float2bfloat16(v.z), h3 = __float2bfloat16(v.w);
    __nv_bfloat16 l0 = __float2bfloat16(v.x - __bfloat162float(h0));
    __nv_bfloat16 l1 = __float2bfloat16(v.y - __bfloat162float(h1));
    __nv_bfloat16 l2 = __float2bfloat16(v.z - __bfloat162float(h2));
    __nv_bfloat16 l3 = __float2bfloat16(v.w - __bfloat162float(h3));
    ((__nv_bfloat162*)hi)[i * 2]     = __nv_bfloat162(h0, h1);
    ((__nv_bfloat162*)hi)[i * 2 + 1] = __nv_bfloat162(h2, h3);
    ((__nv_bfloat162*)lo)[i * 2]     = __nv_bfloat162(l0, l1);
    ((__nv_bfloat162*)lo)[i * 2 + 1] = __nv_bfloat162(l2, l3);
}

// ============================================================================
// mma.sync bf16 split GEMM, T-quarter row mapping:
// bm = (by>>1)*1024 + (by&1)*128 + moff   (grid.y = 16 per quarter)
// ============================================================================
#define KCH 64
#define STAGE_BYTES 65536

template<int EPI>
__global__ void __launch_bounds__(256, 1) gemm_mma(
    const __nv_bfloat16* __restrict__ Ahi, const __nv_bfloat16* __restrict__ Alo,
    const __nv_bfloat16* __restrict__ Bhi, const __nv_bfloat16* __restrict__ Blo,
    const float* __restrict__ bias,
    float* __restrict__ Cf,
    __nv_bfloat16* __restrict__ Chi, __nv_bfloat16* __restrict__ Clo,
    int K, int N, int moff)
{
    extern __shared__ char dsm[];
    const int tid  = threadIdx.x;
    const int wid  = tid >> 5;
    const int lane = tid & 31;
    const int wm = wid & 1;
    const int wn = wid >> 1;
    const int by = blockIdx.y;
    const int bm = (by >> 1) * 1024 + (by & 1) * 128 + moff;
    const int bn = blockIdx.x * 128;

    const uint32_t sbase = (smem_u32(dsm) + 1023u) & ~1023u;

    float acc[4][4][4];
    #pragma unroll
    for (int i = 0; i < 4; ++i)
        #pragma unroll
        for (int j = 0; j < 4; ++j)
            #pragma unroll
            for (int e = 0; e < 4; ++e) acc[i][j][e] = 0.0f;

    const int lrow = tid >> 3;
    const int lc   = tid & 7;
    auto load_stage = [&](int s, int k0){
        const uint32_t tA_hi = sbase + s * STAGE_BYTES;
        const uint32_t tA_lo = tA_hi + 16384;
        const uint32_t tB_hi = tA_hi + 32768;
        const uint32_t tB_lo = tA_hi + 49152;
        #pragma unroll
        for (int p = 0; p < 4; ++p){
            const int row = lrow + p * 32;
            const uint32_t sw = SWZ128((uint32_t)(row * 128 + lc * 16));
            const size_t ga = (size_t)(bm + row) * K + k0 + lc * 8;
            const size_t gb = (size_t)(bn + row) * K + k0 + lc * 8;
            cpasync16(tA_hi + sw, Ahi + ga);
            cpasync16(tA_lo + sw, Alo + ga);
            cpasync16(tB_hi + sw, Bhi + gb);
            cpasync16(tB_lo + sw, Blo + gb);
        }
        CP_COMMIT();
    };

    const int NIT = K / KCH;
    load_stage(0, 0);

    const int lr8  = (lane & 7) + ((lane & 8) ? 8 : 0);
    const int lk16 = (lane & 16) ? 16 : 0;

    for (int it = 0; it < NIT; ++it){
        if (it + 1 < NIT){
            load_stage((it + 1) & 1, (it + 1) * KCH);
            CP_WAIT(1);
        } else {
            CP_WAIT(0);
        }
        __syncthreads();

        const uint32_t st   = sbase + (it & 1) * STAGE_BYTES;
        const uint32_t sAhi = st;
        const uint32_t sAlo = st + 16384;
        const uint32_t sBhi = st + 32768;
        const uint32_t sBlo = st + 49152;

        #pragma unroll
        for (int ks = 0; ks < 4; ++ks){
            uint32_t ah[4][4], al[4][4], bh[2][4], bl[2][4];
            #pragma unroll
            for (int i = 0; i < 4; ++i){
                const int r = wm * 64 + i * 16 + lr8;
                const uint32_t off = SWZ128((uint32_t)(r * 128 + ks * 32 + lk16));
                ldsm_x4(ah[i], sAhi + off);
                ldsm_x4(al[i], sAlo + off);
            }
            #pragma unroll
            for (int np = 0; np < 2; ++np){
                const int r = wn * 32 + np * 16 + lr8;
                const uint32_t off = SWZ128((uint32_t)(r * 128 + ks * 32 + lk16));
                ldsm_x4(bh[np], sBhi + off);
                ldsm_x4(bl[np], sBlo + off);
            }
            #pragma unroll
            for (int i = 0; i < 4; ++i){
                #pragma unroll
                for (int j = 0; j < 4; ++j){
                    const int np = j >> 1, sl = j & 1;
                    mma16816(acc[i][j], ah[i], bh[np][sl], bh[np][sl + 2]);
                    mma16816(acc[i][j], al[i], bh[np][sl], bh[np][sl + 2]);
                    mma16816(acc[i][j], ah[i], bl[np][sl], bl[np][sl + 2]);
                }
            }
        }
        __syncthreads();
    }

    const int qr = lane >> 2;
    const int qc = (lane & 3) * 2;
    #pragma unroll
    for (int i = 0; i < 4; ++i){
        #pragma unroll
        for (int j = 0; j < 4; ++j){
            const int col = bn + wn * 32 + j * 8 + qc;
            #pragma unroll
            for (int h = 0; h < 2; ++h){
                const int row = bm + wm * 64 + i * 16 + qr + h * 8;
                float v0 = acc[i][j][h * 2];
                float v1 = acc[i][j][h * 2 + 1];
                if (EPI == 1){
                    v0 += bias[col];
                    v1 += bias[col + 1];
                    v0 = v0 / (1.0f + expf(-v0));
                    v1 = v1 / (1.0f + expf(-v1));
                    *(float2*)(Cf + (size_t)row * N + col) = make_float2(v0, v1);
                } else if (EPI == 2){
                    __nv_bfloat16 h0 = __float2bfloat16(v0);
                    __nv_bfloat16 h1 = __float2bfloat16(v1);
                    __nv_bfloat16 l0 = __float2bfloat16(v0 - __bfloat162float(h0));
                    __nv_bfloat16 l1 = __float2bfloat16(v1 - __bfloat162float(h1));
                    *(__nv_bfloat162*)(Chi + (size_t)row * N + col) = __nv_bfloat162(h0, h1);
                    *(__nv_bfloat162*)(Clo + (size_t)row * N + col) = __nv_bfloat162(l0, l1);
                } else {
                    *(float2*)(Cf + (size_t)row * N + col) = make_float2(v0, v1);
                }
            }
        }
    }
}

// ============================================================================
// Launch — T-quarter pipeline across 3 streams (handles static-cached).
// ============================================================================
extern "C" void kernel_launch(void* const* d_in, const int* in_sizes, int n_in,
                              void* d_out, int out_size)
{
    (void)in_sizes; (void)n_in;
    const float* x    = (const float*)d_in[0];
    const float* h0   = (const float*)d_in[1];
    const float* inw  = (const float*)d_in[2];
    const float* outw = (const float*)d_in[3];
    const float* ch   = (const float*)d_in[4];
    const float* cx   = (const float*)d_in[5];
    const float* bv   = (const float*)d_in[6];
    const float* wg   = (const float*)d_in[7];
    const float* bg   = (const float*)d_in[8];

    float* out = (float*)d_out;
    float* hfinal = (out_size >= (int)(ROWS * DIMX + B_SZ * DI))
                        ? out + (size_t)ROWS * DIMX : nullptr;

    float *p_gate, *p_pre, *p_hseq, *p_hstate;
    float2 *p_W, *p_FCh, *p_FCx, *p_FChP;
    __nv_bfloat16 *p_xhi, *p_xlo, *p_xphi, *p_xplo, *p_clhi, *p_cllo;
    __nv_bfloat16 *p_iwhi, *p_iwlo, *p_wghi, *p_wglo, *p_owhi, *p_owlo;
    cudaGetSymbolAddress((void**)&p_gate,   g_gate);
    cudaGetSymbolAddress((void**)&p_pre,    g_pre);
    cudaGetSymbolAddress((void**)&p_hseq,   g_hseq);
    cudaGetSymbolAddress((void**)&p_hstate, g_hstate);
    cudaGetSymbolAddress((void**)&p_W,     g_W);
    cudaGetSymbolAddress((void**)&p_FCh,   g_FCh);
    cudaGetSymbolAddress((void**)&p_FCx,   g_FCx);
    cudaGetSymbolAddress((void**)&p_FChP,  g_FChP);
    cudaGetSymbolAddress((void**)&p_xhi,   g_xhi);
    cudaGetSymbolAddress((void**)&p_xlo,   g_xlo);
    cudaGetSymbolAddress((void**)&p_xphi,  g_xphi);
    cudaGetSymbolAddress((void**)&p_xplo,  g_xplo);
    cudaGetSymbolAddress((void**)&p_clhi,  g_clhi);
    cudaGetSymbolAddress((void**)&p_cllo,  g_cllo);
    cudaGetSymbolAddress((void**)&p_iwhi,  g_iwhi);
    cudaGetSymbolAddress((void**)&p_iwlo,  g_iwlo);
    cudaGetSymbolAddress((void**)&p_wghi,  g_wghi);
    cudaGetSymbolAddress((void**)&p_wglo,  g_wglo);
    cudaGetSymbolAddress((void**)&p_owhi,  g_owhi);
    cudaGetSymbolAddress((void**)&p_owlo,  g_owlo);

    cudaFuncSetAttribute(conv_pre_kernel, cudaFuncAttributeMaxDynamicSharedMemorySize, 65536);
    cudaFuncSetAttribute(spectra_kernel,  cudaFuncAttributeMaxDynamicSharedMemorySize, 49152);
    const int GSM = 2 * STAGE_BYTES + 1024;
    cudaFuncSetAttribute(gemm_mma<0>, cudaFuncAttributeMaxDynamicSharedMemorySize, GSM);
    cudaFuncSetAttribute(gemm_mma<1>, cudaFuncAttributeMaxDynamicSharedMemorySize, GSM);
    cudaFuncSetAttribute(gemm_mma<2>, cudaFuncAttributeMaxDynamicSharedMemorySize, GSM);

    // ---- cached streams/events (created once, before capture baseline) ----
    static cudaStream_t s2 = nullptr, s3 = nullptr;
    static cudaEvent_t ev0, evSplit, evG1m;
    static cudaEvent_t evC[4];    // conv quarter done (1..3 used)
    static cudaEvent_t evG2[4];   // gate quarter done
    static cudaEvent_t evS[4];    // scan quarter done (0..2 used)
    static cudaEvent_t evO;       // s3 epilogue done
    if (s2 == nullptr){
        cudaStreamCreateWithFlags(&s2, cudaStreamNonBlocking);
        cudaStreamCreateWithFlags(&s3, cudaStreamNonBlocking);
        cudaEventCreateWithFlags(&ev0,    cudaEventDisableTiming);
        cudaEventCreateWithFlags(&evSplit,cudaEventDisableTiming);
        cudaEventCreateWithFlags(&evG1m,  cudaEventDisableTiming);
        for (int i = 0; i < 4; ++i){
            cudaEventCreateWithFlags(&evC[i],  cudaEventDisableTiming);
            cudaEventCreateWithFlags(&evG2[i], cudaEventDisableTiming);
            cudaEventCreateWithFlags(&evS[i],  cudaEventDisableTiming);
        }
        cudaEventCreateWithFlags(&evO, cudaEventDisableTiming);
    }

    const dim3 gThr(256);

    // ---- main: setup ----
    twiddle_kernel<<<4, 512>>>(p_W);
    spectra_kernel<<<1, 256, 49152>>>(ch, cx, p_W, p_FCh, p_FCx);
    prep_fchp_kernel<<<1, 256>>>(ch, p_FChP);
    cudaEventRecord(ev0, 0);

    split_kernel<<<ROWS * DIMX / 4 / 256, gThr>>>(x,   p_xhi,  p_xlo,  ROWS * DIMX / 4);
    split_kernel<<<DI * DIMX   / 4 / 256, gThr>>>(inw, p_iwhi, p_iwlo, DI * DIMX / 4);
    cudaEventRecord(evSplit, 0);

    // s2: weight splits for GEMM2/GEMM3
    cudaStreamWaitEvent(s2, ev0, 0);
    split_kernel<<<DI * DI   / 4 / 256, gThr, 0, s2>>>(wg,   p_wghi, p_wglo, DI * DI / 4);
    split_kernel<<<DIMX * DI / 4 / 256, gThr, 0, s2>>>(outw, p_owhi, p_owlo, DIMX * DI / 4);

    // main: GEMM1 q0 + conv q0
    gemm_mma<2><<<dim3(DI / 128, 16), 256, GSM>>>(
        p_xhi, p_xlo, p_iwhi, p_iwlo, nullptr, nullptr, p_xphi, p_xplo, DIMX, DI, 0);
    cudaEventRecord(evG1m, 0);
    conv_pre_kernel<<<1024, 256, 65536>>>(p_xphi, p_xplo, bv, p_W, p_FCx, p_pre, 0);

    // s2: GEMM1 q1-3 + conv q1-3
    cudaStreamWaitEvent(s2, evSplit, 0);
    for (int q = 1; q < 4; ++q){
        gemm_mma<2><<<dim3(DI / 128, 16), 256, GSM, s2>>>(
            p_xhi, p_xlo, p_iwhi, p_iwlo, nullptr, nullptr, p_xphi, p_xplo, DIMX, DI, q * TQ);
        conv_pre_kernel<<<1024, 256, 65536, s2>>>(p_xphi, p_xplo, bv, p_W, p_FCx, p_pre, q * TQ);
        cudaEventRecord(evC[q], s2);
    }
    // s2: GEMM2 quarters (q0 needs main's x_proj q0)
    cudaStreamWaitEvent(s2, evG1m, 0);
    for (int q = 0; q < 4; ++q){
        gemm_mma<1><<<dim3(DI / 128, 16), 256, GSM, s2>>>(
            p_xphi, p_xplo, p_wghi, p_wglo, bg, p_gate, nullptr, nullptr, DI, DI, q * TQ);
        cudaEventRecord(evG2[q], s2);
    }

    // main: scan quarters
    scan_part_kernel<<<4, 256>>>(p_pre, p_hseq, p_FChP, h0, p_hstate, nullptr, 0, TQ);
    cudaEventRecord(evS[0], 0);
    for (int q = 1; q < 4; ++q){
        cudaStreamWaitEvent(0, evC[q], 0);
        scan_part_kernel<<<4, 256>>>(p_pre, p_hseq, p_FChP, p_hstate, p_hstate,
                                     (q == 3) ? hfinal : nullptr, q * TQ, (q + 1) * TQ);
        if (q < 3) cudaEventRecord(evS[q], 0);
    }

    // s3: epilogue quarters 0..2 under the scan
    for (int q = 0; q < 3; ++q){
        cudaStreamWaitEvent(s3, evS[q], 0);
        cudaStreamWaitEvent(s3, evG2[q], 0);
        cell_split_kernel<<<4096, 256, 0, s3>>>(p_hseq, p_gate, p_clhi, p_cllo, q * TQ);
        gemm_mma<0><<<dim3(DIMX / 128, 16), 256, GSM, s3>>>(
            p_clhi, p_cllo, p_owhi, p_owlo, nullptr, out, nullptr, nullptr, DI, DIMX, q * TQ);
    }
    cudaEventRecord(evO, s3);

    // main: last quarter epilogue
    cudaStreamWaitEvent(0, evG2[3], 0);
    cell_split_kernel<<<4096, 256>>>(p_hseq, p_gate, p_clhi, p_cllo, 3 * TQ);
    gemm_mma<0><<<dim3(DIMX / 128, 16), 256, GSM>>>(
        p_clhi, p_cllo, p_owhi, p_owlo, nullptr, out, nullptr, nullptr, DI, DIMX, 3 * TQ);

    // join s3
    cudaStreamWaitEvent(0, evO, 0);
}

// round 10
// speedup vs baseline: 2.0428x; 1.0243x over previous
#include <cuda_runtime.h>
#include <cuda_bf16.h>
#include <math.h>
#include <stdint.h>

#ifndef M_PI
#define M_PI 3.14159265358979323846
#endif

// Problem constants
#define B_SZ   8
#define T_SZ   1024
#define DIMX   1024
#define DI     2048
#define NFFT   2048
#define ROWS   (B_SZ * T_SZ)   // 8192
#define TQ     256             // T quarter

// ----- device scratch -----
__device__ float  g_gate [(size_t)ROWS * DI];
__device__ float  g_pre  [(size_t)ROWS * DI];
__device__ float  g_hseq [(size_t)ROWS * DI];
__device__ float  g_hstate[(size_t)B_SZ * DI];
__device__ float2 g_W   [NFFT];
__device__ float2 g_FCh [NFFT];
__device__ float2 g_FCx [NFFT];
__device__ float2 g_FChP[NFFT];

// bf16 split operands
__device__ __nv_bfloat16 g_xhi [(size_t)ROWS * DIMX];
__device__ __nv_bfloat16 g_xlo [(size_t)ROWS * DIMX];
__device__ __nv_bfloat16 g_xphi[(size_t)ROWS * DI];
__device__ __nv_bfloat16 g_xplo[(size_t)ROWS * DI];
__device__ __nv_bfloat16 g_clhi[(size_t)ROWS * DI];
__device__ __nv_bfloat16 g_cllo[(size_t)ROWS * DI];
__device__ __nv_bfloat16 g_iwhi[(size_t)DI * DIMX];
__device__ __nv_bfloat16 g_iwlo[(size_t)DI * DIMX];
__device__ __nv_bfloat16 g_wghi[(size_t)DI * DI];
__device__ __nv_bfloat16 g_wglo[(size_t)DI * DI];
__device__ __nv_bfloat16 g_owhi[(size_t)DIMX * DI];
__device__ __nv_bfloat16 g_owlo[(size_t)DIMX * DI];

__device__ __forceinline__ float2 cmulf(float2 a, float2 b){
    return make_float2(fmaf(a.x, b.x, -a.y * b.y), fmaf(a.x, b.y, a.y * b.x));
}
__device__ __forceinline__ float2 cadd(float2 a, float2 b){ return make_float2(a.x+b.x, a.y+b.y); }
__device__ __forceinline__ float2 csub(float2 a, float2 b){ return make_float2(a.x-b.x, a.y-b.y); }

__device__ __forceinline__ float tanh_fast(float x){
    float ax = fabsf(x);
    float e  = __expf(-2.0f * ax);
    float r  = __fdividef(1.0f - e, 1.0f + e);
    return copysignf(r, x);
}

__device__ __forceinline__ int sidx(int i){ return i ^ ((i >> 4) & 15); }

// ============================================================================
// PTX helpers
// ============================================================================
__device__ __forceinline__ uint32_t smem_u32(const void* p){
    uint32_t a;
    asm("{ .reg .u64 t; cvta.to.shared.u64 t, %1; cvt.u32.u64 %0, t; }" : "=r"(a) : "l"(p));
    return a;
}
__device__ __forceinline__ void cpasync16(uint32_t dst, const void* src){
    asm volatile("cp.async.cg.shared.global [%0], [%1], 16;" :: "r"(dst), "l"(src));
}
#define CP_COMMIT()  asm volatile("cp.async.commit_group;" ::: "memory")
#define CP_WAIT(n)   asm volatile("cp.async.wait_group %0;" :: "n"(n) : "memory")

__device__ __forceinline__ void ldsm_x4(uint32_t* r, uint32_t addr){
    asm volatile("ldmatrix.sync.aligned.m8n8.x4.shared.b16 {%0,%1,%2,%3}, [%4];"
        : "=r"(r[0]), "=r"(r[1]), "=r"(r[2]), "=r"(r[3]) : "r"(addr));
}
__device__ __forceinline__ void mma16816(float* c, const uint32_t* a,
                                         uint32_t b0, uint32_t b1){
    asm volatile("mma.sync.aligned.m16n8k16.row.col.f32.bf16.bf16.f32 "
        "{%0,%1,%2,%3}, {%4,%5,%6,%7}, {%8,%9}, {%0,%1,%2,%3};"
        : "+f"(c[0]), "+f"(c[1]), "+f"(c[2]), "+f"(c[3])
        : "r"(a[0]), "r"(a[1]), "r"(a[2]), "r"(a[3]), "r"(b0), "r"(b1));
}

#define SWZ128(o) ((o) ^ (((o) >> 3) & 0x70))

// ============================================================================
// DFT cores. DIR=0 fwd (e^-i), DIR=1 inv (e^+i). No scaling.
// ============================================================================
template<int DIR>
__device__ __forceinline__ void dft4(const float2* a, float2* X)
{
    float2 s0 = cadd(a[0], a[2]), s1 = csub(a[0], a[2]);
    float2 s2 = cadd(a[1], a[3]), s3 = csub(a[1], a[3]);
    float2 is3 = DIR ? make_float2(-s3.y, s3.x) : make_float2(s3.y, -s3.x);
    X[0] = cadd(s0, s2); X[2] = csub(s0, s2);
    X[1] = cadd(s1, is3); X[3] = csub(s1, is3);
}

template<int DIR>
__device__ __forceinline__ void dft8(const float2* a, float2* X)
{
    const float RS = 0.70710678118654752f;
    float2 s0 = cadd(a[0], a[4]), s1 = csub(a[0], a[4]);
    float2 s2 = cadd(a[2], a[6]), s3 = csub(a[2], a[6]);
    float2 s3i = DIR ? make_float2(-s3.y, s3.x) : make_float2(s3.y, -s3.x);
    float2 E0 = cadd(s0, s2), E2 = csub(s0, s2);
    float2 E1 = cadd(s1, s3i), E3 = csub(s1, s3i);
    float2 u0 = cadd(a[1], a[5]), u1 = csub(a[1], a[5]);
    float2 u2 = cadd(a[3], a[7]), u3 = csub(a[3], a[7]);
    float2 u3i = DIR ? make_float2(-u3.y, u3.x) : make_float2(u3.y, -u3.x);
    float2 O0 = cadd(u0, u2), O2 = csub(u0, u2);
    float2 O1 = cadd(u1, u3i), O3 = csub(u1, u3i);
    float2 t1, t2, t3;
    if (DIR == 0){
        t1 = make_float2((O1.x + O1.y) * RS, (O1.y - O1.x) * RS);
        t2 = make_float2(O2.y, -O2.x);
        t3 = make_float2((O3.y - O3.x) * RS, -(O3.x + O3.y) * RS);
    } else {
        t1 = make_float2((O1.x - O1.y) * RS, (O1.x + O1.y) * RS);
        t2 = make_float2(-O2.y, O2.x);
        t3 = make_float2(-(O3.x + O3.y) * RS, (O3.x - O3.y) * RS);
    }
    X[0] = cadd(E0, O0);  X[4] = csub(E0, O0);
    X[1] = cadd(E1, t1);  X[5] = csub(E1, t1);
    X[2] = cadd(E2, t2);  X[6] = csub(E2, t2);
    X[3] = cadd(E3, t3);  X[7] = csub(E3, t3);
}

// ============================================================================
// 512-thread transform  T = P ∘ DFT2048.  4 points/thread.
// 2048 = 4 (reg, W2048) × 4 (x-warp A, W512) × 4 (x-warp B, W128) × 32 (lane).
// fwd: exA then exB; inv: exA then exB. 4 barriers/step total.
// ============================================================================
struct TW5 {
    float2 t1[3];  // W_2048^{tid·r}
    float2 t2[3];  // W_512^{q·s},  q = tid & 127
    float2 t3[3];  // W_128^{l·c},  l = tid & 31
    float2 lt[4];  // lane stages h=16,8,4,2
};

__device__ __forceinline__ void make_tw5(TW5& tw, int tid){
    const int q = tid & 127, l = tid & 31;
    #pragma unroll
    for (int r = 1; r < 4; ++r){
        double a = -2.0 * M_PI * (double)((tid * r) & 2047) / 2048.0;
        double s, c; sincos(a, &s, &c);
        tw.t1[r-1] = make_float2((float)c, (float)s);
    }
    #pragma unroll
    for (int s2 = 1; s2 < 4; ++s2){
        double a = -2.0 * M_PI * (double)((q * s2) & 511) / 512.0;
        double s, c; sincos(a, &s, &c);
        tw.t2[s2-1] = make_float2((float)c, (float)s);
    }
    #pragma unroll
    for (int c2 = 1; c2 < 4; ++c2){
        double a = -2.0 * M_PI * (double)((l * c2) & 127) / 128.0;
        double s, c; sincos(a, &s, &c);
        tw.t3[c2-1] = make_float2((float)c, (float)s);
    }
    #pragma unroll
    for (int s2 = 0; s2 < 4; ++s2){
        int h = 16 >> s2;
        double a = -M_PI * (double)(l & (h - 1)) / (double)h;
        double s, c; sincos(a, &s, &c);
        tw.lt[s2] = make_float2((float)c, (float)s);
    }
}

__device__ __forceinline__ float2 shfl_xor_c(float2 v, int m){
    float2 r;
    r.x = __shfl_xor_sync(0xffffffffu, v.x, m);
    r.y = __shfl_xor_sync(0xffffffffu, v.y, m);
    return r;
}

// forward: z[4] (z[p] = X[tid + 512p]) -> spec[4]
__device__ __forceinline__ void fwd2048_512(const float2* z, float2* spec,
                                            float2* exA, float2* exB,
                                            const TW5& tw, int tid, int l)
{
    float2 y[4];
    dft4<0>(z, y);
    #pragma unroll
    for (int r = 1; r < 4; ++r) y[r] = cmulf(y[r], tw.t1[r-1]);
    #pragma unroll
    for (int r = 0; r < 4; ++r) exA[r*512 + tid] = y[r];
    __syncthreads();
    const int r_ = tid >> 7, q = tid & 127;
    float2 a[4];
    #pragma unroll
    for (int p = 0; p < 4; ++p) a[p] = exA[r_*512 + q + 128*p];
    float2 As[4];
    dft4<0>(a, As);
    #pragma unroll
    for (int s = 1; s < 4; ++s) As[s] = cmulf(As[s], tw.t2[s-1]);
    #pragma unroll
    for (int s = 0; s < 4; ++s) exB[((r_<<2) + s)*128 + q] = As[s];
    __syncthreads();
    const int rs = tid >> 5;
    float2 b[4];
    #pragma unroll
    for (int w0 = 0; w0 < 4; ++w0) b[w0] = exB[rs*128 + 32*w0 + l];
    dft4<0>(b, spec);
    #pragma unroll
    for (int c = 1; c < 4; ++c) spec[c] = cmulf(spec[c], tw.t3[c-1]);
    #pragma unroll
    for (int c = 0; c < 4; ++c){
        float2 v = spec[c];
        #pragma unroll
        for (int s = 0; s < 4; ++s){
            const int h = 16 >> s;
            float2 p = shfl_xor_c(v, h);
            if (l & h) v = cmulf(csub(p, v), tw.lt[s]);
            else       v = cadd(v, p);
        }
        {   float2 p = shfl_xor_c(v, 1);
            v = (l & 1) ? csub(p, v) : cadd(v, p); }
        spec[c] = v;
    }
}

// inverse: spec[4] -> z[4] (exact mirror, conjugate twiddles)
__device__ __forceinline__ void inv2048_512(float2* spec, float2* z,
                                            float2* exA, float2* exB,
                                            const TW5& tw, int tid, int l)
{
    #pragma unroll
    for (int c = 0; c < 4; ++c){
        float2 v = spec[c];
        {   float2 p = shfl_xor_c(v, 1);
            v = (l & 1) ? csub(p, v) : cadd(v, p); }
        #pragma unroll
        for (int s = 3; s >= 0; --s){
            const int h = 16 >> s;
            float2 wc = tw.lt[s]; wc.y = -wc.y;
            if (l & h) v = cmulf(v, wc);
            float2 p = shfl_xor_c(v, h);
            v = (l & h) ? csub(p, v) : cadd(v, p);
        }
        spec[c] = v;
    }
    #pragma unroll
    for (int c = 1; c < 4; ++c){
        float2 wc = tw.t3[c-1]; wc.y = -wc.y;
        spec[c] = cmulf(spec[c], wc);
    }
    const int rs = tid >> 5;
    float2 b[4];
    dft4<1>(spec, b);                       // -> index w0
    #pragma unroll
    for (int w0 = 0; w0 < 4; ++w0) exA[rs*128 + 32*w0 + l] = b[w0];
    __syncthreads();
    const int r_ = tid >> 7, q = tid & 127;
    float2 As[4];
    #pragma unroll
    for (int s = 0; s < 4; ++s) As[s] = exA[((r_<<2) + s)*128 + q];
    #pragma unroll
    for (int s = 1; s < 4; ++s){
        float2 wc = tw.t2[s-1]; wc.y = -wc.y;
        As[s] = cmulf(As[s], wc);
    }
    float2 a[4];
    dft4<1>(As, a);                         // -> index p
    #pragma unroll
    for (int p = 0; p < 4; ++p) exB[r_*512 + q + 128*p] = a[p];
    __syncthreads();
    float2 y[4];
    #pragma unroll
    for (int r = 0; r < 4; ++r) y[r] = exB[r*512 + tid];
    #pragma unroll
    for (int r = 1; r < 4; ++r){
        float2 wc = tw.t1[r-1]; wc.y = -wc.y;
        y[r] = cmulf(y[r], wc);
    }
    dft4<1>(y, z);
}

// prep: FChP = T(c_h)/2048 in the 512-thread transform's permuted layout
__global__ void __launch_bounds__(512, 1) prep_fchp_kernel(
    const float* __restrict__ ch, float2* __restrict__ FChP)
{
    __shared__ float2 exA[2048];
    __shared__ float2 exB[2048];
    const int tid = threadIdx.x, l = tid & 31;
    TW5 tw; make_tw5(tw, tid);
    float2 z[4], spec[4];
    #pragma unroll
    for (int p = 0; p < 4; ++p)
        z[p] = make_float2(ch[tid + 512*p] * (1.0f/2048.0f), 0.0f);
    fwd2048_512(z, spec, exA, exB, tw, tid, l);
    #pragma unroll
    for (int c = 0; c < 4; ++c) FChP[tid*4 + c] = spec[c];
}

// ============================================================================
// Scan part kernel: steps [t0,t1). 4 CTAs, 512 threads.
// ============================================================================
__global__ void __launch_bounds__(512, 1) scan_part_kernel(
    const float* __restrict__ pre, float* __restrict__ hseq,
    const float2* __restrict__ FChP,
    const float* __restrict__ hin, float* __restrict__ hstate,
    float* __restrict__ hfinal, int t0, int t1)
{
    __shared__ float2 exA[2048];
    __shared__ float2 exB[2048];
    const int tid = threadIdx.x, l = tid & 31;
    const int b0 = blockIdx.x * 2, b1 = b0 + 1;
    TW5 tw; make_tw5(tw, tid);
    float2 fc[4];
    #pragma unroll
    for (int c = 0; c < 4; ++c) fc[c] = FChP[tid*4 + c];
    float2 z[4];
    #pragma unroll
    for (int p = 0; p < 4; ++p)
        z[p] = make_float2(hin[(size_t)b0 * DI + tid + 512*p],
                           hin[(size_t)b1 * DI + tid + 512*p]);

    const float* pre0 = pre  + (size_t)b0 * T_SZ * DI;
    const float* pre1 = pre  + (size_t)b1 * T_SZ * DI;
    float*       hs0  = hseq + (size_t)b0 * T_SZ * DI;
    float*       hs1  = hseq + (size_t)b1 * T_SZ * DI;

    for (int ts = t0; ts < t1; ++ts){
        const size_t off = (size_t)ts * DI;
        float pr0[4], pr1[4];
        #pragma unroll
        for (int p = 0; p < 4; ++p){
            pr0[p] = pre0[off + tid + 512*p];
            pr1[p] = pre1[off + tid + 512*p];
        }
        float2 spec[4];
        fwd2048_512(z, spec, exA, exB, tw, tid, l);
        #pragma unroll
        for (int c = 0; c < 4; ++c) spec[c] = cmulf(spec[c], fc[c]);
        inv2048_512(spec, z, exA, exB, tw, tid, l);
        #pragma unroll
        for (int p = 0; p < 4; ++p){
            float hr = tanh_fast(z[p].x + pr0[p]);
            float hi = tanh_fast(z[p].y + pr1[p]);
            hs0[off + tid + 512*p] = hr;
            hs1[off + tid + 512*p] = hi;
            z[p] = make_float2(hr, hi);
        }
    }
    #pragma unroll
    for (int p = 0; p < 4; ++p){
        hstate[(size_t)b0 * DI + tid + 512*p] = z[p].x;
        hstate[(size_t)b1 * DI + tid + 512*p] = z[p].y;
    }
    if (hfinal){
        #pragma unroll
        for (int p = 0; p < 4; ++p){
            hfinal[(size_t)b0 * DI + tid + 512*p] = z[p].x;
            hfinal[(size_t)b1 * DI + tid + 512*p] = z[p].y;
        }
    }
}

// ============================================================================
// Smem Stockham FFT path for setup/conv (verified, 256 threads).
// ============================================================================
template<int DIR>
__device__ __forceinline__ void fft2048_r8(float2* bufA, float2* bufB,
                                           const float2* __restrict__ W, int tid)
{
    float2* X = bufA;
    float2* Y = bufB;
    #pragma unroll
    for (int st = 0; st < 3; ++st){
        const int s  = (st == 0) ? 1 : (st == 1) ? 8 : 64;
        const int ps = tid & ~(s - 1);
        const int q  = tid & (s - 1);
        float2 a[8], o[8];
        #pragma unroll
        for (int r = 0; r < 8; ++r) a[r] = X[sidx(tid + 256 * r)];
        dft8<DIR>(a, o);
        const int ob = q + 8 * ps;
        Y[sidx(ob)] = o[0];
        #pragma unroll
        for (int r = 1; r < 8; ++r){
            float2 w = W[r * ps];
            if (DIR) w.y = -w.y;
            Y[sidx(ob + s * r)] = cmulf(w, o[r]);
        }
        __syncthreads();
        float2* tmp = X; X = Y; Y = tmp;
    }
    #pragma unroll
    for (int h = 0; h < 2; ++h){
        const int j = tid + 256 * h;
        float2 a = X[sidx(j)];
        float2 b = X[sidx(j + 512)];
        float2 c = X[sidx(j + 1024)];
        float2 d = X[sidx(j + 1536)];
        float2 apc = cadd(a, c), amc = csub(a, c);
        float2 bpd = cadd(b, d), bmd = csub(b, d);
        float2 ib  = make_float2(-bmd.y, bmd.x);
        float2 x1, x3;
        if (DIR == 0){ x1 = csub(amc, ib); x3 = cadd(amc, ib); }
        else         { x1 = cadd(amc, ib); x3 = csub(amc, ib); }
        Y[sidx(j)]        = cadd(apc, bpd);
        Y[sidx(j + 512)]  = x1;
        Y[sidx(j + 1024)] = csub(apc, bpd);
        Y[sidx(j + 1536)] = x3;
    }
    __syncthreads();
}

__global__ void twiddle_kernel(float2* __restrict__ W)
{
    int k = blockIdx.x * blockDim.x + threadIdx.x;
    if (k < NFFT){
        double a = -2.0 * M_PI * (double)k / (double)NFFT;
        W[k] = make_float2((float)cos(a), (float)sin(a));
    }
}

__global__ void spectra_kernel(const float* __restrict__ ch, const float* __restrict__ cx,
                               const float2* __restrict__ Wg,
                               float2* __restrict__ FCh, float2* __restrict__ FCx)
{
    extern __shared__ float2 sm[];
    float2* bufA = sm;
    float2* bufB = sm + 2048;
    float2* Wc   = sm + 4096;
    const int tid = threadIdx.x;
    for (int k = tid; k < NFFT; k += 256){
        Wc[k] = Wg[k];
        bufA[sidx(k)] = make_float2(ch[k], cx[k]);
    }
    __syncthreads();
    fft2048_r8<0>(bufA, bufB, Wc, tid);
    const float inv = 1.0f / (float)NFFT;
    for (int k = tid; k < NFFT; k += 256){
        float2 A  = bufA[sidx(k)];
        float2 Zm = bufA[sidx((NFFT - k) & (NFFT - 1))];
        float2 Bc = make_float2(Zm.x, -Zm.y);
        float2 FH = make_float2(0.5f * (A.x + Bc.x), 0.5f * (A.y + Bc.y));
        float2 Dd = make_float2(A.x - Bc.x, A.y - Bc.y);
        float2 FX = make_float2(0.5f * Dd.y, -0.5f * Dd.x);
        FCh[k] = make_float2(FH.x * inv, FH.y * inv);
        FCx[k] = make_float2(FX.x * inv, FX.y * inv);
    }
}

// conv_pre chunked over T-quarters: 1024 CTAs cover 8 batches x 128 row-pairs
__global__ void conv_pre_kernel(const __nv_bfloat16* __restrict__ xph,
                                const __nv_bfloat16* __restrict__ xpl,
                                const float* __restrict__ bvec,
                                const float2* __restrict__ Wg, const float2* __restrict__ FCg,
                                float* __restrict__ pre, int toff)
{
    extern __shared__ float2 sm[];
    float2* bufA = sm;
    float2* bufB = sm + 2048;
    float2* Wc   = sm + 4096;
    float2* FC   = sm + 6144;
    const int tid = threadIdx.x;
    const int bid = blockIdx.x;                  // [0, 1024)
    const size_t r0 = (size_t)(bid >> 7) * T_SZ + (size_t)(bid & 127) * 2 + toff;
    const __nv_bfloat16* h0p = xph + r0 * DI;
    const __nv_bfloat16* l0p = xpl + r0 * DI;
    for (int k = tid; k < NFFT; k += 256){
        Wc[k] = Wg[k];
        FC[k] = FCg[k];
        float v0 = __bfloat162float(h0p[k]) + __bfloat162float(l0p[k]);
        float v1 = __bfloat162float(h0p[DI + k]) + __bfloat162float(l0p[DI + k]);
        bufA[sidx(k)] = make_float2(v0, v1);
    }
    __syncthreads();
    fft2048_r8<0>(bufA, bufB, Wc, tid);
    for (int k = tid; k < NFFT; k += 256){
        int si = sidx(k);
        bufA[si] = cmulf(bufA[si], FC[k]);
    }
    __syncthreads();
    fft2048_r8<1>(bufA, bufB, Wc, tid);
    float* p0 = pre + r0 * DI;
    float* p1 = p0 + DI;
    for (int k = tid; k < NFFT; k += 256){
        const float bb = bvec[k];
        float2 v = bufA[sidx(k)];
        p0[k] = v.x + bb;
        p1[k] = v.y + bb;
    }
}

// ============================================================================
// Elementwise split helpers
// ============================================================================
__global__ void split_kernel(const float* __restrict__ s,
                             __nv_bfloat16* __restrict__ hi, __nv_bfloat16* __restrict__ lo,
                             int n4)
{
    int i = blockIdx.x * blockDim.x + threadIdx.x;
    if (i >= n4) return;
    float4 v = ((const float4*)s)[i];
    __nv_bfloat16 h0 = __float2bfloat16(v.x), h1 = __float2bfloat16(v.y);
    __nv_bfloat16 h2 = __float2bfloat16(v.z), h3 = __float2bfloat16(v.w);
    __nv_bfloat16 l0 = __float2bfloat16(v.x - __bfloat162float(h0));
    __nv_bfloat16 l1 = __float2bfloat16(v.y - __bfloat162float(h1));
    __nv_bfloat16 l2 = __float2bfloat16(v.z - __bfloat162float(h2));
    __nv_bfloat16 l3 = __float2bfloat16(v.w - __bfloat162float(h3));
    ((__nv_bfloat162*)hi)[i * 2]     = __nv_bfloat162(h0, h1);
    ((__nv_bfloat162*)hi)[i * 2 + 1] = __nv_bfloat162(h2, h3);
    ((__nv_bfloat162*)lo)[i * 2]     = __nv_bfloat162(l0, l1);
    ((__nv_bfloat162*)lo)[i * 2 + 1] = __nv_bfloat162(l2, l3);
}

// cell = hseq * gate, split to bf16, T-quarter chunked. grid 4096 x 256.
__global__ void cell_split_kernel(const float* __restrict__ a, const float* __restrict__ g,
                                  __nv_bfloat16* __restrict__ hi, __nv_bfloat16* __restrict__ lo,
                                  int toff)
{
    const int gg = blockIdx.x * blockDim.x + threadIdx.x;
    const int rloc = gg >> 9;
    const int c    = gg & 511;
    const size_t row = (size_t)(rloc >> 8) * T_SZ + (size_t)(rloc & 255) + toff;
    const size_t i = row * (DI / 4) + c;
    float4 va = ((const float4*)a)[i];
    float4 vg = ((const float4*)g)[i];
    float4 v = make_float4(va.x * vg.x, va.y * vg.y, va.z * vg.z, va.w * vg.w);
    __nv_bfloat16 h0 = __float2bfloat16(v.x), h1 = __float2bfloat16(v.y);
    __nv_bfloat16 h2 = __float2bfloat16(v.z), h3 = __float2bfloat16(v.w);
    __nv_bfloat16 l0 = __float2bfloat16(v.x - __bfloat162float(h0));
    __nv_bfloat16 l1 = __float2bfloat16(v.y - __bfloat162float(h1));
    __nv_bfloat16 l2 = __float2bfloat16(v.z - __bfloat162float(h2));
    __nv_bfloat16 l3 = __float2bfloat16(v.w - __bfloat162float(h3));
    ((__nv_bfloat162*)hi)[i * 2]     = __nv_bfloat162(h0, h1);
    ((__nv_bfloat162*)hi)[i * 2 + 1] = __nv_bfloat162(h2, h3);
    ((__nv_bfloat162*)lo)[i * 2]     = __nv_bfloat162(l0, l1);
    ((__nv_bfloat162*)lo)[i * 2 + 1] = __nv_bfloat162(l2, l3);
}

// ============================================================================
// mma.sync bf16 split GEMM, T-quarter row mapping:
// bm = (by>>1)*1024 + (by&1)*128 + moff   (grid.y = 16 per quarter)
// ============================================================================
#define KCH 64
#define STAGE_BYTES 65536

template<int EPI>
__global__ void __launch_bounds__(256, 1) gemm_mma(
    const __nv_bfloat16* __restrict__ Ahi, const __nv_bfloat16* __restrict__ Alo,
    const __nv_bfloat16* __restrict__ Bhi, const __nv_bfloat16* __restrict__ Blo,
    const float* __restrict__ bias,
    float* __restrict__ Cf,
    __nv_bfloat16* __restrict__ Chi, __nv_bfloat16* __restrict__ Clo,
    int K, int N, int moff)
{
    extern __shared__ char dsm[];
    const int tid  = threadIdx.x;
    const int wid  = tid >> 5;
    const int lane = tid & 31;
    const int wm = wid & 1;
    const int wn = wid >> 1;
    const int by = blockIdx.y;
    const int bm = (by >> 1) * 1024 + (by & 1) * 128 + moff;
    const int bn = blockIdx.x * 128;

    const uint32_t sbase = (smem_u32(dsm) + 1023u) & ~1023u;

    float acc[4][4][4];
    #pragma unroll
    for (int i = 0; i < 4; ++i)
        #pragma unroll
        for (int j = 0; j < 4; ++j)
            #pragma unroll
            for (int e = 0; e < 4; ++e) acc[i][j][e] = 0.0f;

    const int lrow = tid >> 3;
    const int lc   = tid & 7;
    auto load_stage = [&](int s, int k0){
        const uint32_t tA_hi = sbase + s * STAGE_BYTES;
        const uint32_t tA_lo = tA_hi + 16384;
        const uint32_t tB_hi = tA_hi + 32768;
        const uint32_t tB_lo = tA_hi + 49152;
        #pragma unroll
        for (int p = 0; p < 4; ++p){
            const int row = lrow + p * 32;
            const uint32_t sw = SWZ128((uint32_t)(row * 128 + lc * 16));
            const size_t ga = (size_t)(bm + row) * K + k0 + lc * 8;
            const size_t gb = (size_t)(bn + row) * K + k0 + lc * 8;
            cpasync16(tA_hi + sw, Ahi + ga);
            cpasync16(tA_lo + sw, Alo + ga);
            cpasync16(tB_hi + sw, Bhi + gb);
            cpasync16(tB_lo + sw, Blo + gb);
        }
        CP_COMMIT();
    };

    const int NIT = K / KCH;
    load_stage(0, 0);

    const int lr8  = (lane & 7) + ((lane & 8) ? 8 : 0);
    const int lk16 = (lane & 16) ? 16 : 0;

    for (int it = 0; it < NIT; ++it){
        if (it + 1 < NIT){
            load_stage((it + 1) & 1, (it + 1) * KCH);
            CP_WAIT(1);
        } else {
            CP_WAIT(0);
        }
        __syncthreads();

        const uint32_t st   = sbase + (it & 1) * STAGE_BYTES;
        const uint32_t sAhi = st;
        const uint32_t sAlo = st + 16384;
        const uint32_t sBhi = st + 32768;
        const uint32_t sBlo = st + 49152;

        #pragma unroll
        for (int ks = 0; ks < 4; ++ks){
            uint32_t ah[4][4], al[4][4], bh[2][4], bl[2][4];
            #pragma unroll
            for (int i = 0; i < 4; ++i){
                const int r = wm * 64 + i * 16 + lr8;
                const uint32_t off = SWZ128((uint32_t)(r * 128 + ks * 32 + lk16));
                ldsm_x4(ah[i], sAhi + off);
                ldsm_x4(al[i], sAlo + off);
            }
            #pragma unroll
            for (int np = 0; np < 2; ++np){
                const int r = wn * 32 + np * 16 + lr8;
                const uint32_t off = SWZ128((uint32_t)(r * 128 + ks * 32 + lk16));
                ldsm_x4(bh[np], sBhi + off);
                ldsm_x4(bl[np], sBlo + off);
            }
            #pragma unroll
            for (int i = 0; i < 4; ++i){
                #pragma unroll
                for (int j = 0; j < 4; ++j){
                    const int np = j >> 1, sl = j & 1;
                    mma16816(acc[i][j], ah[i], bh[np][sl], bh[np][sl + 2]);
                    mma16816(acc[i][j], al[i], bh[np][sl], bh[np][sl + 2]);
                    mma16816(acc[i][j], ah[i], bl[np][sl], bl[np][sl + 2]);
                }
            }
        }
        __syncthreads();
    }

    const int qr = lane >> 2;
    const int qc = (lane & 3) * 2;
    #pragma unroll
    for (int i = 0; i < 4; ++i){
        #pragma unroll
        for (int j = 0; j < 4; ++j){
            const int col = bn + wn * 32 + j * 8 + qc;
            #pragma unroll
            for (int h = 0; h < 2; ++h){
                const int row = bm + wm * 64 + i * 16 + qr + h * 8;
                float v0 = acc[i][j][h * 2];
                float v1 = acc[i][j][h * 2 + 1];
                if (EPI == 1){
                    v0 += bias[col];
                    v1 += bias[col + 1];
                    v0 = v0 / (1.0f + expf(-v0));
                    v1 = v1 / (1.0f + expf(-v1));
                    *(float2*)(Cf + (size_t)row * N + col) = make_float2(v0, v1);
                } else if (EPI == 2){
                    __nv_bfloat16 h0 = __float2bfloat16(v0);
                    __nv_bfloat16 h1 = __float2bfloat16(v1);
                    __nv_bfloat16 l0 = __float2bfloat16(v0 - __bfloat162float(h0));
                    __nv_bfloat16 l1 = __float2bfloat16(v1 - __bfloat162float(h1));
                    *(__nv_bfloat162*)(Chi + (size_t)row * N + col) = __nv_bfloat162(h0, h1);
                    *(__nv_bfloat162*)(Clo + (size_t)row * N + col) = __nv_bfloat162(l0, l1);
                } else {
                    *(float2*)(Cf + (size_t)row * N + col) = make_float2(v0, v1);
                }
            }
        }
    }
}

// ============================================================================
// Launch — T-quarter pipeline across 3 streams (handles static-cached).
// ============================================================================
extern "C" void kernel_launch(void* const* d_in, const int* in_sizes, int n_in,
                              void* d_out, int out_size)
{
    (void)in_sizes; (void)n_in;
    const float* x    = (const float*)d_in[0];
    const float* h0   = (const float*)d_in[1];
    const float* inw  = (const float*)d_in[2];
    const float* outw = (const float*)d_in[3];
    const float* ch   = (const float*)d_in[4];
    const float* cx   = (const float*)d_in[5];
    const float* bv   = (const float*)d_in[6];
    const float* wg   = (const float*)d_in[7];
    const float* bg   = (const float*)d_in[8];

    float* out = (float*)d_out;
    float* hfinal = (out_size >= (int)(ROWS * DIMX + B_SZ * DI))
                        ? out + (size_t)ROWS * DIMX : nullptr;

    float *p_gate, *p_pre, *p_hseq, *p_hstate;
    float2 *p_W, *p_FCh, *p_FCx, *p_FChP;
    __nv_bfloat16 *p_xhi, *p_xlo, *p_xphi, *p_xplo, *p_clhi, *p_cllo;
    __nv_bfloat16 *p_iwhi, *p_iwlo, *p_wghi, *p_wglo, *p_owhi, *p_owlo;
    cudaGetSymbolAddress((void**)&p_gate,   g_gate);
    cudaGetSymbolAddress((void**)&p_pre,    g_pre);
    cudaGetSymbolAddress((void**)&p_hseq,   g_hseq);
    cudaGetSymbolAddress((void**)&p_hstate, g_hstate);
    cudaGetSymbolAddress((void**)&p_W,     g_W);
    cudaGetSymbolAddress((void**)&p_FCh,   g_FCh);
    cudaGetSymbolAddress((void**)&p_FCx,   g_FCx);
    cudaGetSymbolAddress((void**)&p_FChP,  g_FChP);
    cudaGetSymbolAddress((void**)&p_xhi,   g_xhi);
    cudaGetSymbolAddress((void**)&p_xlo,   g_xlo);
    cudaGetSymbolAddress((void**)&p_xphi,  g_xphi);
    cudaGetSymbolAddress((void**)&p_xplo,  g_xplo);
    cudaGetSymbolAddress((void**)&p_clhi,  g_clhi);
    cudaGetSymbolAddress((void**)&p_cllo,  g_cllo);
    cudaGetSymbolAddress((void**)&p_iwhi,  g_iwhi);
    cudaGetSymbolAddress((void**)&p_iwlo,  g_iwlo);
    cudaGetSymbolAddress((void**)&p_wghi,  g_wghi);
    cudaGetSymbolAddress((void**)&p_wglo,  g_wglo);
    cudaGetSymbolAddress((void**)&p_owhi,  g_owhi);
    cudaGetSymbolAddress((void**)&p_owlo,  g_owlo);

    cudaFuncSetAttribute(conv_pre_kernel, cudaFuncAttributeMaxDynamicSharedMemorySize, 65536);
    cudaFuncSetAttribute(spectra_kernel,  cudaFuncAttributeMaxDynamicSharedMemorySize, 49152);
    const int GSM = 2 * STAGE_BYTES + 1024;
    cudaFuncSetAttribute(gemm_mma<0>, cudaFuncAttributeMaxDynamicSharedMemorySize, GSM);
    cudaFuncSetAttribute(gemm_mma<1>, cudaFuncAttributeMaxDynamicSharedMemorySize, GSM);
    cudaFuncSetAttribute(gemm_mma<2>, cudaFuncAttributeMaxDynamicSharedMemorySize, GSM);

    // ---- cached streams/events (created once, before capture baseline) ----
    static cudaStream_t s2 = nullptr, s3 = nullptr;
    static cudaEvent_t ev0, evSplit, evG1m;
    static cudaEvent_t evC[4];
    static cudaEvent_t evG2[4];
    static cudaEvent_t evS[4];
    static cudaEvent_t evO;
    if (s2 == nullptr){
        cudaStreamCreateWithFlags(&s2, cudaStreamNonBlocking);
        cudaStreamCreateWithFlags(&s3, cudaStreamNonBlocking);
        cudaEventCreateWithFlags(&ev0,    cudaEventDisableTiming);
        cudaEventCreateWithFlags(&evSplit,cudaEventDisableTiming);
        cudaEventCreateWithFlags(&evG1m,  cudaEventDisableTiming);
        for (int i = 0; i < 4; ++i){
            cudaEventCreateWithFlags(&evC[i],  cudaEventDisableTiming);
            cudaEventCreateWithFlags(&evG2[i], cudaEventDisableTiming);
            cudaEventCreateWithFlags(&evS[i],  cudaEventDisableTiming);
        }
        cudaEventCreateWithFlags(&evO, cudaEventDisableTiming);
    }

    const dim3 gThr(256);

    // ---- main: setup ----
    twiddle_kernel<<<4, 512>>>(p_W);
    spectra_kernel<<<1, 256, 49152>>>(ch, cx, p_W, p_FCh, p_FCx);
    prep_fchp_kernel<<<1, 512>>>(ch, p_FChP);
    cudaEventRecord(ev0, 0);

    split_kernel<<<ROWS * DIMX / 4 / 256, gThr>>>(x,   p_xhi,  p_xlo,  ROWS * DIMX / 4);
    split_kernel<<<DI * DIMX   / 4 / 256, gThr>>>(inw, p_iwhi, p_iwlo, DI * DIMX / 4);
    cudaEventRecord(evSplit, 0);

    // s2: weight splits for GEMM2/GEMM3
    cudaStreamWaitEvent(s2, ev0, 0);
    split_kernel<<<DI * DI   / 4 / 256, gThr, 0, s2>>>(wg,   p_wghi, p_wglo, DI * DI / 4);
    split_kernel<<<DIMX * DI / 4 / 256, gThr, 0, s2>>>(outw, p_owhi, p_owlo, DIMX * DI / 4);

    // main: GEMM1 q0 + conv q0
    gemm_mma<2><<<dim3(DI / 128, 16), 256, GSM>>>(
        p_xhi, p_xlo, p_iwhi, p_iwlo, nullptr, nullptr, p_xphi, p_xplo, DIMX, DI, 0);
    cudaEventRecord(evG1m, 0);
    conv_pre_kernel<<<1024, 256, 65536>>>(p_xphi, p_xplo, bv, p_W, p_FCx, p_pre, 0);

    // s2: GEMM1 q1-3 + conv q1-3
    cudaStreamWaitEvent(s2, evSplit, 0);
    for (int q = 1; q < 4; ++q){
        gemm_mma<2><<<dim3(DI / 128, 16), 256, GSM, s2>>>(
            p_xhi, p_xlo, p_iwhi, p_iwlo, nullptr, nullptr, p_xphi, p_xplo, DIMX, DI, q * TQ);
        conv_pre_kernel<<<1024, 256, 65536, s2>>>(p_xphi, p_xplo, bv, p_W, p_FCx, p_pre, q * TQ);
        cudaEventRecord(evC[q], s2);
    }
    // s2: GEMM2 quarters
    cudaStreamWaitEvent(s2, evG1m, 0);
    for (int q = 0; q < 4; ++q){
        gemm_mma<1><<<dim3(DI / 128, 16), 256, GSM, s2>>>(
            p_xphi, p_xplo, p_wghi, p_wglo, bg, p_gate, nullptr, nullptr, DI, DI, q * TQ);
        cudaEventRecord(evG2[q], s2);
    }

    // main: scan quarters (512 threads per CTA)
    scan_part_kernel<<<4, 512>>>(p_pre, p_hseq, p_FChP, h0, p_hstate, nullptr, 0, TQ);
    cudaEventRecord(evS[0], 0);
    for (int q = 1; q < 4; ++q){
        cudaStreamWaitEvent(0, evC[q], 0);
        scan_part_kernel<<<4, 512>>>(p_pre, p_hseq, p_FChP, p_hstate, p_hstate,
                                     (q == 3) ? hfinal : nullptr, q * TQ, (q + 1) * TQ);
        if (q < 3) cudaEventRecord(evS[q], 0);
    }

    // s3: epilogue quarters 0..2 under the scan
    for (int q = 0; q < 3; ++q){
        cudaStreamWaitEvent(s3, evS[q], 0);
        cudaStreamWaitEvent(s3, evG2[q], 0);
        cell_split_kernel<<<4096, 256, 0, s3>>>(p_hseq, p_gate, p_clhi, p_cllo, q * TQ);
        gemm_mma<0><<<dim3(DIMX / 128, 16), 256, GSM, s3>>>(
            p_clhi, p_cllo, p_owhi, p_owlo, nullptr, out, nullptr, nullptr, DI, DIMX, q * TQ);
    }
    cudaEventRecord(evO, s3);

    // main: last quarter epilogue
    cudaStreamWaitEvent(0, evG2[3], 0);
    cell_split_kernel<<<4096, 256>>>(p_hseq, p_gate, p_clhi, p_cllo, 3 * TQ);
    gemm_mma<0><<<dim3(DIMX / 128, 16), 256, GSM>>>(
        p_clhi, p_cllo, p_owhi, p_owlo, nullptr, out, nullptr, nullptr, DI, DIMX, 3 * TQ);

    // join s3
    cudaStreamWaitEvent(0, evO, 0);
}

// round 11
// speedup vs baseline: 2.6492x; 1.2969x over previous
#include <cuda_runtime.h>
#include <cuda_bf16.h>
#include <math.h>
#include <stdint.h>

#ifndef M_PI
#define M_PI 3.14159265358979323846
#endif

// Problem constants
#define B_SZ   8
#define T_SZ   1024
#define DIMX   1024
#define DI     2048
#define NFFT   2048
#define ROWS   (B_SZ * T_SZ)   // 8192
#define TQ     256             // T quarter
#define NH     1024            // half length (packed complex)

// ----- device scratch -----
__device__ float  g_gate [(size_t)ROWS * DI];
__device__ float  g_pre  [(size_t)ROWS * DI];
__device__ float  g_hseq [(size_t)ROWS * DI];
__device__ float  g_hstate[(size_t)B_SZ * DI];
__device__ float2 g_W   [NFFT];
__device__ float2 g_FCh [NFFT];
__device__ float2 g_FCx [NFFT];

// bf16 split operands
__device__ __nv_bfloat16 g_xhi [(size_t)ROWS * DIMX];
__device__ __nv_bfloat16 g_xlo [(size_t)ROWS * DIMX];
__device__ __nv_bfloat16 g_xphi[(size_t)ROWS * DI];
__device__ __nv_bfloat16 g_xplo[(size_t)ROWS * DI];
__device__ __nv_bfloat16 g_clhi[(size_t)ROWS * DI];
__device__ __nv_bfloat16 g_cllo[(size_t)ROWS * DI];
__device__ __nv_bfloat16 g_iwhi[(size_t)DI * DIMX];
__device__ __nv_bfloat16 g_iwlo[(size_t)DI * DIMX];
__device__ __nv_bfloat16 g_wghi[(size_t)DI * DI];
__device__ __nv_bfloat16 g_wglo[(size_t)DI * DI];
__device__ __nv_bfloat16 g_owhi[(size_t)DIMX * DI];
__device__ __nv_bfloat16 g_owlo[(size_t)DIMX * DI];

__device__ __forceinline__ float2 cmulf(float2 a, float2 b){
    return make_float2(fmaf(a.x, b.x, -a.y * b.y), fmaf(a.x, b.y, a.y * b.x));
}
__device__ __forceinline__ float2 cadd(float2 a, float2 b){ return make_float2(a.x+b.x, a.y+b.y); }
__device__ __forceinline__ float2 csub(float2 a, float2 b){ return make_float2(a.x-b.x, a.y-b.y); }

__device__ __forceinline__ float tanh_fast(float x){
    float ax = fabsf(x);
    float e  = __expf(-2.0f * ax);
    float r  = __fdividef(1.0f - e, 1.0f + e);
    return copysignf(r, x);
}

__device__ __forceinline__ int sidx(int i){ return i ^ ((i >> 4) & 15); }
__device__ __forceinline__ int padk(int k){ return k + (k >> 5); }   // bank pad

// ============================================================================
// PTX helpers
// ============================================================================
__device__ __forceinline__ uint32_t smem_u32(const void* p){
    uint32_t a;
    asm("{ .reg .u64 t; cvta.to.shared.u64 t, %1; cvt.u32.u64 %0, t; }" : "=r"(a) : "l"(p));
    return a;
}
__device__ __forceinline__ void cpasync16(uint32_t dst, const void* src){
    asm volatile("cp.async.cg.shared.global [%0], [%1], 16;" :: "r"(dst), "l"(src));
}
#define CP_COMMIT()  asm volatile("cp.async.commit_group;" ::: "memory")
#define CP_WAIT(n)   asm volatile("cp.async.wait_group %0;" :: "n"(n) : "memory")

__device__ __forceinline__ void ldsm_x4(uint32_t* r, uint32_t addr){
    asm volatile("ldmatrix.sync.aligned.m8n8.x4.shared.b16 {%0,%1,%2,%3}, [%4];"
        : "=r"(r[0]), "=r"(r[1]), "=r"(r[2]), "=r"(r[3]) : "r"(addr));
}
__device__ __forceinline__ void mma16816(float* c, const uint32_t* a,
                                         uint32_t b0, uint32_t b1){
    asm volatile("mma.sync.aligned.m16n8k16.row.col.f32.bf16.bf16.f32 "
        "{%0,%1,%2,%3}, {%4,%5,%6,%7}, {%8,%9}, {%0,%1,%2,%3};"
        : "+f"(c[0]), "+f"(c[1]), "+f"(c[2]), "+f"(c[3])
        : "r"(a[0]), "r"(a[1]), "r"(a[2]), "r"(a[3]), "r"(b0), "r"(b1));
}

#define SWZ128(o) ((o) ^ (((o) >> 3) & 0x70))

// ============================================================================
// DFT cores. DIR=0 fwd (e^-i), DIR=1 inv (e^+i). No scaling.
// ============================================================================
template<int DIR>
__device__ __forceinline__ void dft4(const float2* a, float2* X)
{
    float2 s0 = cadd(a[0], a[2]), s1 = csub(a[0], a[2]);
    float2 s2 = cadd(a[1], a[3]), s3 = csub(a[1], a[3]);
    float2 is3 = DIR ? make_float2(-s3.y, s3.x) : make_float2(s3.y, -s3.x);
    X[0] = cadd(s0, s2); X[2] = csub(s0, s2);
    X[1] = cadd(s1, is3); X[3] = csub(s1, is3);
}

template<int DIR>
__device__ __forceinline__ void dft8(const float2* a, float2* X)
{
    const float RS = 0.70710678118654752f;
    float2 s0 = cadd(a[0], a[4]), s1 = csub(a[0], a[4]);
    float2 s2 = cadd(a[2], a[6]), s3 = csub(a[2], a[6]);
    float2 s3i = DIR ? make_float2(-s3.y, s3.x) : make_float2(s3.y, -s3.x);
    float2 E0 = cadd(s0, s2), E2 = csub(s0, s2);
    float2 E1 = cadd(s1, s3i), E3 = csub(s1, s3i);
    float2 u0 = cadd(a[1], a[5]), u1 = csub(a[1], a[5]);
    float2 u2 = cadd(a[3], a[7]), u3 = csub(a[3], a[7]);
    float2 u3i = DIR ? make_float2(-u3.y, u3.x) : make_float2(u3.y, -u3.x);
    float2 O0 = cadd(u0, u2), O2 = csub(u0, u2);
    float2 O1 = cadd(u1, u3i), O3 = csub(u1, u3i);
    float2 t1, t2, t3;
    if (DIR == 0){
        t1 = make_float2((O1.x + O1.y) * RS, (O1.y - O1.x) * RS);
        t2 = make_float2(O2.y, -O2.x);
        t3 = make_float2((O3.y - O3.x) * RS, -(O3.x + O3.y) * RS);
    } else {
        t1 = make_float2((O1.x - O1.y) * RS, (O1.x + O1.y) * RS);
        t2 = make_float2(-O2.y, O2.x);
        t3 = make_float2(-(O3.x + O3.y) * RS, (O3.x - O3.y) * RS);
    }
    X[0] = cadd(E0, O0);  X[4] = csub(E0, O0);
    X[1] = cadd(E1, t1);  X[5] = csub(E1, t1);
    X[2] = cadd(E2, t2);  X[6] = csub(E2, t2);
    X[3] = cadd(E3, t3);  X[7] = csub(E3, t3);
}

// ============================================================================
// 1024-pt DIF transform, 256 threads, 4 pts/thread.
// 1024 = 4 (reg, W1024) x 4 (W256) x 4 (W64) x 16 (lane FFT-16).
// Natural output index of spec[c] at thread tid:
//   k = (tid>>6) + 4*((tid>>4)&3) + 16*c + 64*bitrev4(tid&15)
// ============================================================================
struct TWR {
    float2 t1[3];   // W1024^{tid r}
    float2 t2[3];   // W256^{q s},  q = tid&63
    float2 t3[3];   // W64^{l16 c}
    float2 lt[3];   // lane stages h=8,4,2
    float2 wb[4];   // e^{-2pi i (tid+256c)/2048}
};

__device__ __forceinline__ int bitrev4(int l){
    return ((l & 1) << 3) | ((l & 2) << 1) | ((l & 4) >> 1) | ((l & 8) >> 3);
}

__device__ __forceinline__ void make_twr(TWR& tw, int tid){
    const int q = tid & 63, l16 = tid & 15;
    #pragma unroll
    for (int r = 1; r < 4; ++r){
        double a = -2.0 * M_PI * (double)((tid * r) & 1023) / 1024.0;
        double s, c; sincos(a, &s, &c);
        tw.t1[r-1] = make_float2((float)c, (float)s);
    }
    #pragma unroll
    for (int s2 = 1; s2 < 4; ++s2){
        double a = -2.0 * M_PI * (double)((q * s2) & 255) / 256.0;
        double s, c; sincos(a, &s, &c);
        tw.t2[s2-1] = make_float2((float)c, (float)s);
    }
    #pragma unroll
    for (int c2 = 1; c2 < 4; ++c2){
        double a = -2.0 * M_PI * (double)((l16 * c2) & 63) / 64.0;
        double s, c; sincos(a, &s, &c);
        tw.t3[c2-1] = make_float2((float)c, (float)s);
    }
    #pragma unroll
    for (int st = 0; st < 3; ++st){
        int h = 8 >> st;
        double a = -M_PI * (double)(l16 & (h - 1)) / (double)h;
        double s, c; sincos(a, &s, &c);
        tw.lt[st] = make_float2((float)c, (float)s);
    }
    #pragma unroll
    for (int c2 = 0; c2 < 4; ++c2){
        double a = -2.0 * M_PI * (double)(tid + 256 * c2) / 2048.0;
        double s, c; sincos(a, &s, &c);
        tw.wb[c2] = make_float2((float)c, (float)s);
    }
}

__device__ __forceinline__ float2 shfl_xor_c(float2 v, int m){
    float2 r;
    r.x = __shfl_xor_sync(0xffffffffu, v.x, m);
    r.y = __shfl_xor_sync(0xffffffffu, v.y, m);
    return r;
}

// forward: z[4] (z[p] = X[tid + 256p]) -> spec[4]. 2 barriers.
__device__ __forceinline__ void fwd1024(const float2* z, float2* spec,
                                        float2* exA, float2* exB,
                                        const TWR& tw, int tid)
{
    const int l16 = tid & 15;
    float2 y[4];
    dft4<0>(z, y);
    #pragma unroll
    for (int r = 1; r < 4; ++r) y[r] = cmulf(y[r], tw.t1[r-1]);
    #pragma unroll
    for (int r = 0; r < 4; ++r) exA[r*256 + tid] = y[r];
    __syncthreads();
    const int r_ = tid >> 6, q = tid & 63;
    float2 a[4];
    #pragma unroll
    for (int p = 0; p < 4; ++p) a[p] = exA[r_*256 + q + 64*p];
    float2 As[4];
    dft4<0>(a, As);
    #pragma unroll
    for (int s = 1; s < 4; ++s) As[s] = cmulf(As[s], tw.t2[s-1]);
    #pragma unroll
    for (int s = 0; s < 4; ++s) exB[((r_<<2) + s)*64 + q] = As[s];
    __syncthreads();
    const int rs = tid >> 4;
    float2 b[4];
    #pragma unroll
    for (int w0 = 0; w0 < 4; ++w0) b[w0] = exB[rs*64 + 16*w0 + l16];
    dft4<0>(b, spec);
    #pragma unroll
    for (int c = 1; c < 4; ++c) spec[c] = cmulf(spec[c], tw.t3[c-1]);
    #pragma unroll
    for (int c = 0; c < 4; ++c){
        float2 v = spec[c];
        #pragma unroll
        for (int st = 0; st < 3; ++st){
            const int h = 8 >> st;
            float2 p = shfl_xor_c(v, h);
            if (l16 & h) v = cmulf(csub(p, v), tw.lt[st]);
            else         v = cadd(v, p);
        }
        {   float2 p = shfl_xor_c(v, 1);
            v = (l16 & 1) ? csub(p, v) : cadd(v, p); }
        spec[c] = v;
    }
}

// inverse: spec[4] -> z[4] (exact mirror, conjugate twiddles). 2 barriers.
__device__ __forceinline__ void inv1024(float2* spec, float2* z,
                                        float2* exA, float2* exB,
                                        const TWR& tw, int tid)
{
    const int l16 = tid & 15;
    #pragma unroll
    for (int c = 0; c < 4; ++c){
        float2 v = spec[c];
        {   float2 p = shfl_xor_c(v, 1);
            v = (l16 & 1) ? csub(p, v) : cadd(v, p); }
        #pragma unroll
        for (int st = 2; st >= 0; --st){
            const int h = 8 >> st;
            float2 wc = tw.lt[st]; wc.y = -wc.y;
            if (l16 & h) v = cmulf(v, wc);
            float2 p = shfl_xor_c(v, h);
            v = (l16 & h) ? csub(p, v) : cadd(v, p);
        }
        spec[c] = v;
    }
    #pragma unroll
    for (int c = 1; c < 4; ++c){
        float2 wc = tw.t3[c-1]; wc.y = -wc.y;
        spec[c] = cmulf(spec[c], wc);
    }
    const int rs = tid >> 4;
    float2 b[4];
    dft4<1>(spec, b);
    #pragma unroll
    for (int w0 = 0; w0 < 4; ++w0) exA[rs*64 + 16*w0 + l16] = b[w0];
    __syncthreads();
    const int r_ = tid >> 6, q = tid & 63;
    float2 As[4];
    #pragma unroll
    for (int s = 0; s < 4; ++s) As[s] = exA[((r_<<2) + s)*64 + q];
    #pragma unroll
    for (int s = 1; s < 4; ++s){
        float2 wc = tw.t2[s-1]; wc.y = -wc.y;
        As[s] = cmulf(As[s], wc);
    }
    float2 a[4];
    dft4<1>(As, a);
    #pragma unroll
    for (int p = 0; p < 4; ++p) exB[r_*256 + q + 64*p] = a[p];
    __syncthreads();
    float2 y[4];
    #pragma unroll
    for (int r = 0; r < 4; ++r) y[r] = exB[r*256 + tid];
    #pragma unroll
    for (int r = 1; r < 4; ++r){
        float2 wc = tw.t1[r-1]; wc.y = -wc.y;
        y[r] = cmulf(y[r], wc);
    }
    dft4<1>(y, z);
}

// ============================================================================
// Scan part kernel: steps [t0,t1). 8 CTAs (one batch each), 256 threads.
// State packed z[n] = h[2n] + i h[2n+1]; 1024-pt FFT + natural-order untangle
// against FCh (natural 2048 spectrum, includes 1/2048).
// ============================================================================
__global__ void __launch_bounds__(256, 1) scan_part_kernel(
    const float* __restrict__ pre, float* __restrict__ hseq,
    const float2* __restrict__ FCn,
    const float* __restrict__ hin, float* __restrict__ hstate,
    float* __restrict__ hfinal, int t0, int t1)
{
    __shared__ float2 exA[1056];
    __shared__ float2 exB[1056];
    const int tid = threadIdx.x;
    const int b = blockIdx.x;
    TWR tw; make_twr(tw, tid);

    // permuted slot -> natural k map (unpadded)
    const int kbase = (tid >> 6) + 4 * ((tid >> 4) & 3) + 64 * bitrev4(tid & 15);

    // FC in natural order for untangle k' = tid + 256c
    float2 FC1[4], FC2[4];
    #pragma unroll
    for (int c = 0; c < 4; ++c){
        FC1[c] = FCn[tid + 256*c];
        FC2[c] = FCn[tid + 256*c + 1024];
    }

    float2 z[4];
    const float2* hin2 = (const float2*)(hin + (size_t)b * DI);
    #pragma unroll
    for (int p = 0; p < 4; ++p) z[p] = hin2[tid + 256*p];

    const float* preb = pre  + (size_t)b * T_SZ * DI;
    float*       hsb  = hseq + (size_t)b * T_SZ * DI;

    for (int ts = t0; ts < t1; ++ts){
        const size_t off = (size_t)ts * DI;
        const float2* prow = (const float2*)(preb + off);
        float2 prv[4];
        #pragma unroll
        for (int p = 0; p < 4; ++p) prv[p] = prow[tid + 256*p];

        float2 spec[4];
        fwd1024(z, spec, exA, exB, tw, tid);

        // ---- untangle + pointwise + repack (natural order via exA/exB) ----
        #pragma unroll
        for (int c = 0; c < 4; ++c) exA[padk(kbase + 16*c)] = spec[c];
        __syncthreads();
        #pragma unroll
        for (int c = 0; c < 4; ++c){
            const int ku = tid + 256*c;
            const int km = (NH - ku) & (NH - 1);
            float2 Zk = exA[padk(ku)];
            float2 Zm = exA[padk(km)];
            float2 S = make_float2(0.5f*(Zk.x + Zm.x), 0.5f*(Zk.y - Zm.y));
            float2 D = make_float2(0.5f*(Zk.x - Zm.x), 0.5f*(Zk.y + Zm.y));
            float2 iw = make_float2(-tw.wb[c].y, tw.wb[c].x);   // i * wbar
            float2 E  = cmulf(iw, D);
            float2 X1 = csub(S, E);
            float2 X2 = cadd(S, E);
            float2 Y1 = cmulf(X1, FC1[c]);
            float2 Y2 = cmulf(X2, FC2[c]);
            float2 Se = cadd(Y1, Y2);
            float2 Df = csub(Y1, Y2);
            float2 wp = make_float2(tw.wb[c].x, -tw.wb[c].y);   // conj(wbar)
            float2 Od = cmulf(wp, Df);
            exB[padk(ku)] = make_float2(Se.x - Od.y, Se.y + Od.x);  // Se + i*Od
        }
        __syncthreads();
        #pragma unroll
        for (int c = 0; c < 4; ++c) spec[c] = exB[padk(kbase + 16*c)];

        inv1024(spec, z, exA, exB, tw, tid);

        float2* hrow = (float2*)(hsb + off);
        #pragma unroll
        for (int p = 0; p < 4; ++p){
            float h0v = tanh_fast(z[p].x + prv[p].x);
            float h1v = tanh_fast(z[p].y + prv[p].y);
            hrow[tid + 256*p] = make_float2(h0v, h1v);
            z[p] = make_float2(h0v, h1v);
        }
    }
    float2* hst = (float2*)(hstate + (size_t)b * DI);
    #pragma unroll
    for (int p = 0; p < 4; ++p) hst[tid + 256*p] = z[p];
    if (hfinal){
        float2* hf = (float2*)(hfinal + (size_t)b * DI);
        #pragma unroll
        for (int p = 0; p < 4; ++p) hf[tid + 256*p] = z[p];
    }
}

// ============================================================================
// Smem Stockham FFT path for setup/conv (verified, 256 threads).
// ============================================================================
template<int DIR>
__device__ __forceinline__ void fft2048_r8(float2* bufA, float2* bufB,
                                           const float2* __restrict__ W, int tid)
{
    float2* X = bufA;
    float2* Y = bufB;
    #pragma unroll
    for (int st = 0; st < 3; ++st){
        const int s  = (st == 0) ? 1 : (st == 1) ? 8 : 64;
        const int ps = tid & ~(s - 1);
        const int q  = tid & (s - 1);
        float2 a[8], o[8];
        #pragma unroll
        for (int r = 0; r < 8; ++r) a[r] = X[sidx(tid + 256 * r)];
        dft8<DIR>(a, o);
        const int ob = q + 8 * ps;
        Y[sidx(ob)] = o[0];
        #pragma unroll
        for (int r = 1; r < 8; ++r){
            float2 w = W[r * ps];
            if (DIR) w.y = -w.y;
            Y[sidx(ob + s * r)] = cmulf(w, o[r]);
        }
        __syncthreads();
        float2* tmp = X; X = Y; Y = tmp;
    }
    #pragma unroll
    for (int h = 0; h < 2; ++h){
        const int j = tid + 256 * h;
        float2 a = X[sidx(j)];
        float2 b = X[sidx(j + 512)];
        float2 c = X[sidx(j + 1024)];
        float2 d = X[sidx(j + 1536)];
        float2 apc = cadd(a, c), amc = csub(a, c);
        float2 bpd = cadd(b, d), bmd = csub(b, d);
        float2 ib  = make_float2(-bmd.y, bmd.x);
        float2 x1, x3;
        if (DIR == 0){ x1 = csub(amc, ib); x3 = cadd(amc, ib); }
        else         { x1 = cadd(amc, ib); x3 = csub(amc, ib); }
        Y[sidx(j)]        = cadd(apc, bpd);
        Y[sidx(j + 512)]  = x1;
        Y[sidx(j + 1024)] = csub(apc, bpd);
        Y[sidx(j + 1536)] = x3;
    }
    __syncthreads();
}

__global__ void twiddle_kernel(float2* __restrict__ W)
{
    int k = blockIdx.x * blockDim.x + threadIdx.x;
    if (k < NFFT){
        double a = -2.0 * M_PI * (double)k / (double)NFFT;
        W[k] = make_float2((float)cos(a), (float)sin(a));
    }
}

__global__ void spectra_kernel(const float* __restrict__ ch, const float* __restrict__ cx,
                               const float2* __restrict__ Wg,
                               float2* __restrict__ FCh, float2* __restrict__ FCx)
{
    extern __shared__ float2 sm[];
    float2* bufA = sm;
    float2* bufB = sm + 2048;
    float2* Wc   = sm + 4096;
    const int tid = threadIdx.x;
    for (int k = tid; k < NFFT; k += 256){
        Wc[k] = Wg[k];
        bufA[sidx(k)] = make_float2(ch[k], cx[k]);
    }
    __syncthreads();
    fft2048_r8<0>(bufA, bufB, Wc, tid);
    const float inv = 1.0f / (float)NFFT;
    for (int k = tid; k < NFFT; k += 256){
        float2 A  = bufA[sidx(k)];
        float2 Zm = bufA[sidx((NFFT - k) & (NFFT - 1))];
        float2 Bc = make_float2(Zm.x, -Zm.y);
        float2 FH = make_float2(0.5f * (A.x + Bc.x), 0.5f * (A.y + Bc.y));
        float2 Dd = make_float2(A.x - Bc.x, A.y - Bc.y);
        float2 FX = make_float2(0.5f * Dd.y, -0.5f * Dd.x);
        FCh[k] = make_float2(FH.x * inv, FH.y * inv);
        FCx[k] = make_float2(FX.x * inv, FX.y * inv);
    }
}

// conv_pre chunked over T-quarters: 1024 CTAs cover 8 batches x 128 row-pairs
__global__ void conv_pre_kernel(const __nv_bfloat16* __restrict__ xph,
                                const __nv_bfloat16* __restrict__ xpl,
                                const float* __restrict__ bvec,
                                const float2* __restrict__ Wg, const float2* __restrict__ FCg,
                                float* __restrict__ pre, int toff)
{
    extern __shared__ float2 sm[];
    float2* bufA = sm;
    float2* bufB = sm + 2048;
    float2* Wc   = sm + 4096;
    float2* FC   = sm + 6144;
    const int tid = threadIdx.x;
    const int bid = blockIdx.x;
    const size_t r0 = (size_t)(bid >> 7) * T_SZ + (size_t)(bid & 127) * 2 + toff;
    const __nv_bfloat16* h0p = xph + r0 * DI;
    const __nv_bfloat16* l0p = xpl + r0 * DI;
    for (int k = tid; k < NFFT; k += 256){
        Wc[k] = Wg[k];
        FC[k] = FCg[k];
        float v0 = __bfloat162float(h0p[k]) + __bfloat162float(l0p[k]);
        float v1 = __bfloat162float(h0p[DI + k]) + __bfloat162float(l0p[DI + k]);
        bufA[sidx(k)] = make_float2(v0, v1);
    }
    __syncthreads();
    fft2048_r8<0>(bufA, bufB, Wc, tid);
    for (int k = tid; k < NFFT; k += 256){
        int si = sidx(k);
        bufA[si] = cmulf(bufA[si], FC[k]);
    }
    __syncthreads();
    fft2048_r8<1>(bufA, bufB, Wc, tid);
    float* p0 = pre + r0 * DI;
    float* p1 = p0 + DI;
    for (int k = tid; k < NFFT; k += 256){
        const float bb = bvec[k];
        float2 v = bufA[sidx(k)];
        p0[k] = v.x + bb;
        p1[k] = v.y + bb;
    }
}

// ============================================================================
// Elementwise split helpers
// ============================================================================
__global__ void split_kernel(const float* __restrict__ s,
                             __nv_bfloat16* __restrict__ hi, __nv_bfloat16* __restrict__ lo,
                             int n4)
{
    int i = blockIdx.x * blockDim.x + threadIdx.x;
    if (i >= n4) return;
    float4 v = ((const float4*)s)[i];
    __nv_bfloat16 h0 = __float2bfloat16(v.x), h1 = __float2bfloat16(v.y);
    __nv_bfloat16 h2 = __float2bfloat16(v.z), h3 = __float2bfloat16(v.w);
    __nv_bfloat16 l0 = __float2bfloat16(v.x - __bfloat162float(h0));
    __nv_bfloat16 l1 = __float2bfloat16(v.y - __bfloat162float(h1));
    __nv_bfloat16 l2 = __float2bfloat16(v.z - __bfloat162float(h2));
    __nv_bfloat16 l3 = __float2bfloat16(v.w - __bfloat162float(h3));
    ((__nv_bfloat162*)hi)[i * 2]     = __nv_bfloat162(h0, h1);
    ((__nv_bfloat162*)hi)[i * 2 + 1] = __nv_bfloat162(h2, h3);
    ((__nv_bfloat162*)lo)[i * 2]     = __nv_bfloat162(l0, l1);
    ((__nv_bfloat162*)lo)[i * 2 + 1] = __nv_bfloat162(l2, l3);
}

// cell = hseq * gate, split to bf16, T-quarter chunked. grid 4096 x 256.
__global__ void cell_split_kernel(const float* __restrict__ a, const float* __restrict__ g,
                                  __nv_bfloat16* __restrict__ hi, __nv_bfloat16* __restrict__ lo,
                                  int toff)
{
    const int gg = blockIdx.x * blockDim.x + threadIdx.x;
    const int rloc = gg >> 9;
    const int c    = gg & 511;
    const size_t row = (size_t)(rloc >> 8) * T_SZ + (size_t)(rloc & 255) + toff;
    const size_t i = row * (DI / 4) + c;
    float4 va = ((const float4*)a)[i];
    float4 vg = ((const float4*)g)[i];
    float4 v = make_float4(va.x * vg.x, va.y * vg.y, va.z * vg.z, va.w * vg.w);
    __nv_bfloat16 h0 = __float2bfloat16(v.x), h1 = __float2bfloat16(v.y);
    __nv_bfloat16 h2 = __float2bfloat16(v.z), h3 = __float2bfloat16(v.w);
    __nv_bfloat16 l0 = __float2bfloat16(v.x - __bfloat162float(h0));
    __nv_bfloat16 l1 = __float2bfloat16(v.y - __bfloat162float(h1));
    __nv_bfloat16 l2 = __float2bfloat16(v.z - __bfloat162float(h2));
    __nv_bfloat16 l3 = __float2bfloat16(v.w - __bfloat162float(h3));
    ((__nv_bfloat162*)hi)[i * 2]     = __nv_bfloat162(h0, h1);
    ((__nv_bfloat162*)hi)[i * 2 + 1] = __nv_bfloat162(h2, h3);
    ((__nv_bfloat162*)lo)[i * 2]     = __nv_bfloat162(l0, l1);
    ((__nv_bfloat162*)lo)[i * 2 + 1] = __nv_bfloat162(l2, l3);
}

// ============================================================================
// mma.sync bf16 split GEMM, T-quarter row mapping (unchanged from R10)
// ============================================================================
#define KCH 64
#define STAGE_BYTES 65536

template<int EPI>
__global__ void __launch_bounds__(256, 1) gemm_mma(
    const __nv_bfloat16* __restrict__ Ahi, const __nv_bfloat16* __restrict__ Alo,
    const __nv_bfloat16* __restrict__ Bhi, const __nv_bfloat16* __restrict__ Blo,
    const float* __restrict__ bias,
    float* __restrict__ Cf,
    __nv_bfloat16* __restrict__ Chi, __nv_bfloat16* __restrict__ Clo,
    int K, int N, int moff)
{
    extern __shared__ char dsm[];
    const int tid  = threadIdx.x;
    const int wid  = tid >> 5;
    const int lane = tid & 31;
    const int wm = wid & 1;
    const int wn = wid >> 1;
    const int by = blockIdx.y;
    const int bm = (by >> 1) * 1024 + (by & 1) * 128 + moff;
    const int bn = blockIdx.x * 128;

    const uint32_t sbase = (smem_u32(dsm) + 1023u) & ~1023u;

    float acc[4][4][4];
    #pragma unroll
    for (int i = 0; i < 4; ++i)
        #pragma unroll
        for (int j = 0; j < 4; ++j)
            #pragma unroll
            for (int e = 0; e < 4; ++e) acc[i][j][e] = 0.0f;

    const int lrow = tid >> 3;
    const int lc   = tid & 7;
    auto load_stage = [&](int s, int k0){
        const uint32_t tA_hi = sbase + s * STAGE_BYTES;
        const uint32_t tA_lo = tA_hi + 16384;
        const uint32_t tB_hi = tA_hi + 32768;
        const uint32_t tB_lo = tA_hi + 49152;
        #pragma unroll
        for (int p = 0; p < 4; ++p){
            const int row = lrow + p * 32;
            const uint32_t sw = SWZ128((uint32_t)(row * 128 + lc * 16));
            const size_t ga = (size_t)(bm + row) * K + k0 + lc * 8;
            const size_t gb = (size_t)(bn + row) * K + k0 + lc * 8;
            cpasync16(tA_hi + sw, Ahi + ga);
            cpasync16(tA_lo + sw, Alo + ga);
            cpasync16(tB_hi + sw, Bhi + gb);
            cpasync16(tB_lo + sw, Blo + gb);
        }
        CP_COMMIT();
    };

    const int NIT = K / KCH;
    load_stage(0, 0);

    const int lr8  = (lane & 7) + ((lane & 8) ? 8 : 0);
    const int lk16 = (lane & 16) ? 16 : 0;

    for (int it = 0; it < NIT; ++it){
        if (it + 1 < NIT){
            load_stage((it + 1) & 1, (it + 1) * KCH);
            CP_WAIT(1);
        } else {
            CP_WAIT(0);
        }
        __syncthreads();

        const uint32_t st   = sbase + (it & 1) * STAGE_BYTES;
        const uint32_t sAhi = st;
        const uint32_t sAlo = st + 16384;
        const uint32_t sBhi = st + 32768;
        const uint32_t sBlo = st + 49152;

        #pragma unroll
        for (int ks = 0; ks < 4; ++ks){
            uint32_t ah[4][4], al[4][4], bh[2][4], bl[2][4];
            #pragma unroll
            for (int i = 0; i < 4; ++i){
                const int r = wm * 64 + i * 16 + lr8;
                const uint32_t off = SWZ128((uint32_t)(r * 128 + ks * 32 + lk16));
                ldsm_x4(ah[i], sAhi + off);
                ldsm_x4(al[i], sAlo + off);
            }
            #pragma unroll
            for (int np = 0; np < 2; ++np){
                const int r = wn * 32 + np * 16 + lr8;
                const uint32_t off = SWZ128((uint32_t)(r * 128 + ks * 32 + lk16));
                ldsm_x4(bh[np], sBhi + off);
                ldsm_x4(bl[np], sBlo + off);
            }
            #pragma unroll
            for (int i = 0; i < 4; ++i){
                #pragma unroll
                for (int j = 0; j < 4; ++j){
                    const int np = j >> 1, sl = j & 1;
                    mma16816(acc[i][j], ah[i], bh[np][sl], bh[np][sl + 2]);
                    mma16816(acc[i][j], al[i], bh[np][sl], bh[np][sl + 2]);
                    mma16816(acc[i][j], ah[i], bl[np][sl], bl[np][sl + 2]);
                }
            }
        }
        __syncthreads();
    }

    const int qr = lane >> 2;
    const int qc = (lane & 3) * 2;
    #pragma unroll
    for (int i = 0; i < 4; ++i){
        #pragma unroll
        for (int j = 0; j < 4; ++j){
            const int col = bn + wn * 32 + j * 8 + qc;
            #pragma unroll
            for (int h = 0; h < 2; ++h){
                const int row = bm + wm * 64 + i * 16 + qr + h * 8;
                float v0 = acc[i][j][h * 2];
                float v1 = acc[i][j][h * 2 + 1];
                if (EPI == 1){
                    v0 += bias[col];
                    v1 += bias[col + 1];
                    v0 = v0 / (1.0f + expf(-v0));
                    v1 = v1 / (1.0f + expf(-v1));
                    *(float2*)(Cf + (size_t)row * N + col) = make_float2(v0, v1);
                } else if (EPI == 2){
                    __nv_bfloat16 h0 = __float2bfloat16(v0);
                    __nv_bfloat16 h1 = __float2bfloat16(v1);
                    __nv_bfloat16 l0 = __float2bfloat16(v0 - __bfloat162float(h0));
                    __nv_bfloat16 l1 = __float2bfloat16(v1 - __bfloat162float(h1));
                    *(__nv_bfloat162*)(Chi + (size_t)row * N + col) = __nv_bfloat162(h0, h1);
                    *(__nv_bfloat162*)(Clo + (size_t)row * N + col) = __nv_bfloat162(l0, l1);
                } else {
                    *(float2*)(Cf + (size_t)row * N + col) = make_float2(v0, v1);
                }
            }
        }
    }
}

// ============================================================================
// Launch — T-quarter pipeline across 3 streams (handles static-cached).
// ============================================================================
extern "C" void kernel_launch(void* const* d_in, const int* in_sizes, int n_in,
                              void* d_out, int out_size)
{
    (void)in_sizes; (void)n_in;
    const float* x    = (const float*)d_in[0];
    const float* h0   = (const float*)d_in[1];
    const float* inw  = (const float*)d_in[2];
    const float* outw = (const float*)d_in[3];
    const float* ch   = (const float*)d_in[4];
    const float* cx   = (const float*)d_in[5];
    const float* bv   = (const float*)d_in[6];
    const float* wg   = (const float*)d_in[7];
    const float* bg   = (const float*)d_in[8];

    float* out = (float*)d_out;
    float* hfinal = (out_size >= (int)(ROWS * DIMX + B_SZ * DI))
                        ? out + (size_t)ROWS * DIMX : nullptr;

    float *p_gate, *p_pre, *p_hseq, *p_hstate;
    float2 *p_W, *p_FCh, *p_FCx;
    __nv_bfloat16 *p_xhi, *p_xlo, *p_xphi, *p_xplo, *p_clhi, *p_cllo;
    __nv_bfloat16 *p_iwhi, *p_iwlo, *p_wghi, *p_wglo, *p_owhi, *p_owlo;
    cudaGetSymbolAddress((void**)&p_gate,   g_gate);
    cudaGetSymbolAddress((void**)&p_pre,    g_pre);
    cudaGetSymbolAddress((void**)&p_hseq,   g_hseq);
    cudaGetSymbolAddress((void**)&p_hstate, g_hstate);
    cudaGetSymbolAddress((void**)&p_W,     g_W);
    cudaGetSymbolAddress((void**)&p_FCh,   g_FCh);
    cudaGetSymbolAddress((void**)&p_FCx,   g_FCx);
    cudaGetSymbolAddress((void**)&p_xhi,   g_xhi);
    cudaGetSymbolAddress((void**)&p_xlo,   g_xlo);
    cudaGetSymbolAddress((void**)&p_xphi,  g_xphi);
    cudaGetSymbolAddress((void**)&p_xplo,  g_xplo);
    cudaGetSymbolAddress((void**)&p_clhi,  g_clhi);
    cudaGetSymbolAddress((void**)&p_cllo,  g_cllo);
    cudaGetSymbolAddress((void**)&p_iwhi,  g_iwhi);
    cudaGetSymbolAddress((void**)&p_iwlo,  g_iwlo);
    cudaGetSymbolAddress((void**)&p_wghi,  g_wghi);
    cudaGetSymbolAddress((void**)&p_wglo,  g_wglo);
    cudaGetSymbolAddress((void**)&p_owhi,  g_owhi);
    cudaGetSymbolAddress((void**)&p_owlo,  g_owlo);

    cudaFuncSetAttribute(conv_pre_kernel, cudaFuncAttributeMaxDynamicSharedMemorySize, 65536);
    cudaFuncSetAttribute(spectra_kernel,  cudaFuncAttributeMaxDynamicSharedMemorySize, 49152);
    const int GSM = 2 * STAGE_BYTES + 1024;
    cudaFuncSetAttribute(gemm_mma<0>, cudaFuncAttributeMaxDynamicSharedMemorySize, GSM);
    cudaFuncSetAttribute(gemm_mma<1>, cudaFuncAttributeMaxDynamicSharedMemorySize, GSM);
    cudaFuncSetAttribute(gemm_mma<2>, cudaFuncAttributeMaxDynamicSharedMemorySize, GSM);

    // ---- cached streams/events (created once, before capture baseline) ----
    static cudaStream_t s2 = nullptr, s3 = nullptr;
    static cudaEvent_t ev0, evSplit, evG1m;
    static cudaEvent_t evC[4];
    static cudaEvent_t evG2[4];
    static cudaEvent_t evS[4];
    static cudaEvent_t evO;
    if (s2 == nullptr){
        cudaStreamCreateWithFlags(&s2, cudaStreamNonBlocking);
        cudaStreamCreateWithFlags(&s3, cudaStreamNonBlocking);
        cudaEventCreateWithFlags(&ev0,    cudaEventDisableTiming);
        cudaEventCreateWithFlags(&evSplit,cudaEventDisableTiming);
        cudaEventCreateWithFlags(&evG1m,  cudaEventDisableTiming);
        for (int i = 0; i < 4; ++i){
            cudaEventCreateWithFlags(&evC[i],  cudaEventDisableTiming);
            cudaEventCreateWithFlags(&evG2[i], cudaEventDisableTiming);
            cudaEventCreateWithFlags(&evS[i],  cudaEventDisableTiming);
        }
        cudaEventCreateWithFlags(&evO, cudaEventDisableTiming);
    }

    const dim3 gThr(256);

    // ---- main: setup ----
    twiddle_kernel<<<4, 512>>>(p_W);
    spectra_kernel<<<1, 256, 49152>>>(ch, cx, p_W, p_FCh, p_FCx);
    cudaEventRecord(ev0, 0);

    split_kernel<<<ROWS * DIMX / 4 / 256, gThr>>>(x,   p_xhi,  p_xlo,  ROWS * DIMX / 4);
    split_kernel<<<DI * DIMX   / 4 / 256, gThr>>>(inw, p_iwhi, p_iwlo, DI * DIMX / 4);
    cudaEventRecord(evSplit, 0);

    // s2: weight splits for GEMM2/GEMM3
    cudaStreamWaitEvent(s2, ev0, 0);
    split_kernel<<<DI * DI   / 4 / 256, gThr, 0, s2>>>(wg,   p_wghi, p_wglo, DI * DI / 4);
    split_kernel<<<DIMX * DI / 4 / 256, gThr, 0, s2>>>(outw, p_owhi, p_owlo, DIMX * DI / 4);

    // main: GEMM1 q0 + conv q0
    gemm_mma<2><<<dim3(DI / 128, 16), 256, GSM>>>(
        p_xhi, p_xlo, p_iwhi, p_iwlo, nullptr, nullptr, p_xphi, p_xplo, DIMX, DI, 0);
    cudaEventRecord(evG1m, 0);
    conv_pre_kernel<<<1024, 256, 65536>>>(p_xphi, p_xplo, bv, p_W, p_FCx, p_pre, 0);

    // s2: GEMM1 q1-3 + conv q1-3
    cudaStreamWaitEvent(s2, evSplit, 0);
    for (int q = 1; q < 4; ++q){
        gemm_mma<2><<<dim3(DI / 128, 16), 256, GSM, s2>>>(
            p_xhi, p_xlo, p_iwhi, p_iwlo, nullptr, nullptr, p_xphi, p_xplo, DIMX, DI, q * TQ);
        conv_pre_kernel<<<1024, 256, 65536, s2>>>(p_xphi, p_xplo, bv, p_W, p_FCx, p_pre, q * TQ);
        cudaEventRecord(evC[q], s2);
    }
    // s2: GEMM2 quarters
    cudaStreamWaitEvent(s2, evG1m, 0);
    for (int q = 0; q < 4; ++q){
        gemm_mma<1><<<dim3(DI / 128, 16), 256, GSM, s2>>>(
            p_xphi, p_xplo, p_wghi, p_wglo, bg, p_gate, nullptr, nullptr, DI, DI, q * TQ);
        cudaEventRecord(evG2[q], s2);
    }

    // main: scan quarters (8 CTAs, one batch each, real-packed half FFT)
    scan_part_kernel<<<8, 256>>>(p_pre, p_hseq, p_FCh, h0, p_hstate, nullptr, 0, TQ);
    cudaEventRecord(evS[0], 0);
    for (int q = 1; q < 4; ++q){
        cudaStreamWaitEvent(0, evC[q], 0);
        scan_part_kernel<<<8, 256>>>(p_pre, p_hseq, p_FCh, p_hstate, p_hstate,
                                     (q == 3) ? hfinal : nullptr, q * TQ, (q + 1) * TQ);
        if (q < 3) cudaEventRecord(evS[q], 0);
    }

    // s3: epilogue quarters 0..2 under the scan
    for (int q = 0; q < 3; ++q){
        cudaStreamWaitEvent(s3, evS[q], 0);
        cudaStreamWaitEvent(s3, evG2[q], 0);
        cell_split_kernel<<<4096, 256, 0, s3>>>(p_hseq, p_gate, p_clhi, p_cllo, q * TQ);
        gemm_mma<0><<<dim3(DIMX / 128, 16), 256, GSM, s3>>>(
            p_clhi, p_cllo, p_owhi, p_owlo, nullptr, out, nullptr, nullptr, DI, DIMX, q * TQ);
    }
    cudaEventRecord(evO, s3);

    // main: last quarter epilogue
    cudaStreamWaitEvent(0, evG2[3], 0);
    cell_split_kernel<<<4096, 256>>>(p_hseq, p_gate, p_clhi, p_cllo, 3 * TQ);
    gemm_mma<0><<<dim3(DIMX / 128, 16), 256, GSM>>>(
        p_clhi, p_cllo, p_owhi, p_owlo, nullptr, out, nullptr, nullptr, DI, DIMX, 3 * TQ);

    // join s3
    cudaStreamWaitEvent(0, evO, 0);
}